// round 12
// baseline (speedup 1.0000x reference)
#include <cuda_runtime.h>
#include <cuda_bf16.h>
#include <cstdint>

#define B_   8
#define L_   1024
#define D_   512
#define H_   8
#define DK_  64
#define KW_  7
#define PAD_ 3
#define NCAT 448    /* KW*DK */
#define WKN  512    /* padded Wker N for qcat GEMM */

// ---------------- scratch (device globals; no runtime allocation) ----------
__device__ float g_bcat[H_*WKN];
// q/k/v_s bf16 split (written directly by the projections), layout [B*L, 512]
__device__ __align__(16) __nv_bfloat16 g_qs_hi[B_*L_*D_];
__device__ __align__(16) __nv_bfloat16 g_qs_lo[B_*L_*D_];
__device__ __align__(16) __nv_bfloat16 g_ks_hi[B_*L_*D_];
__device__ __align__(16) __nv_bfloat16 g_ks_lo[B_*L_*D_];
__device__ __align__(16) __nv_bfloat16 g_vs_hi[B_*L_*D_];
__device__ __align__(16) __nv_bfloat16 g_vs_lo[B_*L_*D_];
// Wker permuted+padded: [h][n=0..511][d=0..63]
__device__ __align__(16) __nv_bfloat16 g_wker_hi[H_*WKN*DK_];
__device__ __align__(16) __nv_bfloat16 g_wker_lo[H_*WKN*DK_];
// bf16 hi/lo operands for the logits GEMM (compact stride 448)
__device__ __align__(16) __nv_bfloat16 g_qcat_hi[(size_t)B_*H_*L_*NCAT];
__device__ __align__(16) __nv_bfloat16 g_qcat_lo[(size_t)B_*H_*L_*NCAT];
__device__ __align__(16) __nv_bfloat16 g_kcat_hi[(size_t)B_*H_*L_*NCAT];
__device__ __align__(16) __nv_bfloat16 g_kcat_lo[(size_t)B_*H_*L_*NCAT];
// projection inputs (bf16 split)
__device__ __align__(16) __nv_bfloat16 g_inq_hi[B_*L_*D_];
__device__ __align__(16) __nv_bfloat16 g_inq_lo[B_*L_*D_];
__device__ __align__(16) __nv_bfloat16 g_ink_hi[B_*L_*D_];
__device__ __align__(16) __nv_bfloat16 g_ink_lo[B_*L_*D_];
__device__ __align__(16) __nv_bfloat16 g_inv_hi[B_*L_*D_];
__device__ __align__(16) __nv_bfloat16 g_inv_lo[B_*L_*D_];
// weights (bf16 split): slots 0=Wq 1=Wk 2=Wv 3=Wproj
__device__ __align__(16) __nv_bfloat16 g_w_hi[4*D_*D_];
__device__ __align__(16) __nv_bfloat16 g_w_lo[4*D_*D_];
// v transposed per head: [z][n=0..63][k=0..1023]
__device__ __align__(16) __nv_bfloat16 g_vt_hi[(size_t)B_*H_*DK_*L_];
__device__ __align__(16) __nv_bfloat16 g_vt_lo[(size_t)B_*H_*DK_*L_];
// ctx in bf16 split, layout [B*L, 512]
__device__ __align__(16) __nv_bfloat16 g_ctx_hi[B_*L_*D_];
__device__ __align__(16) __nv_bfloat16 g_ctx_lo[B_*L_*D_];

// ====================== baseline-PTX tensor helpers ========================
static __device__ __forceinline__ uint32_t smem_u32(const void* p){
    uint32_t a;
    asm("{ .reg .u64 t; cvta.to.shared.u64 t, %1; cvt.u32.u64 %0, t; }"
        : "=r"(a) : "l"(p));
    return a;
}
#define CP_ASYNC16(dst, src) \
    asm volatile("cp.async.cg.shared.global [%0], [%1], 16;" \
                 :: "r"(dst), "l"(src) : "memory")
#define CP_COMMIT() asm volatile("cp.async.commit_group;" ::: "memory")
#define CP_WAIT(n)  asm volatile("cp.async.wait_group %0;" :: "n"(n) : "memory")
#define LDSM4(r0, r1, r2, r3, addr) \
    asm volatile("ldmatrix.sync.aligned.m8n8.x4.shared.b16 {%0,%1,%2,%3}, [%4];" \
                 : "=r"(r0), "=r"(r1), "=r"(r2), "=r"(r3) : "r"(addr))
#define MMA16816(d, a, b) \
    asm volatile("mma.sync.aligned.m16n8k16.row.col.f32.bf16.bf16.f32 " \
                 "{%0,%1,%2,%3},{%4,%5,%6,%7},{%8,%9},{%0,%1,%2,%3};" \
                 : "+f"((d)[0]), "+f"((d)[1]), "+f"((d)[2]), "+f"((d)[3]) \
                 : "r"((a)[0]), "r"((a)[1]), "r"((a)[2]), "r"((a)[3]), \
                   "r"((b)[0]), "r"((b)[1]))

static __device__ __forceinline__ unsigned pk2(float a, float b){
    __nv_bfloat162 t = __floats2bfloat162_rn(a, b);
    return *reinterpret_cast<unsigned*>(&t);
}
static __device__ __forceinline__ float bhi(float x){
    return __bfloat162float(__float2bfloat16_rn(x));
}

// ---------------------------------------------------------------------------
// conv_split3: fp32 -> bf16 hi/lo for q,k,v inputs in one launch (y = slot)
// ---------------------------------------------------------------------------
__global__ __launch_bounds__(256) void conv_split3_kernel(
    const float* __restrict__ s0, const float* __restrict__ s1,
    const float* __restrict__ s2, int n8)
{
    int i = blockIdx.x * 256 + threadIdx.x;
    if (i >= n8) return;
    const float* src; __nv_bfloat16 *dh, *dl;
    if (blockIdx.y == 0)      { src = s0; dh = g_inq_hi; dl = g_inq_lo; }
    else if (blockIdx.y == 1) { src = s1; dh = g_ink_hi; dl = g_ink_lo; }
    else                      { src = s2; dh = g_inv_hi; dl = g_inv_lo; }
    const float4* s = (const float4*)(src + (size_t)i * 8);
    float4 v0 = s[0], v1 = s[1];
    float f[8] = {v0.x, v0.y, v0.z, v0.w, v1.x, v1.y, v1.z, v1.w};
    float hh[8], ll[8];
#pragma unroll
    for (int e = 0; e < 8; e++) { hh[e] = bhi(f[e]); ll[e] = f[e] - hh[e]; }
    *(uint4*)(dh + (size_t)i * 8) = make_uint4(pk2(hh[0],hh[1]), pk2(hh[2],hh[3]),
                                               pk2(hh[4],hh[5]), pk2(hh[6],hh[7]));
    *(uint4*)(dl + (size_t)i * 8) = make_uint4(pk2(ll[0],ll[1]), pk2(ll[2],ll[3]),
                                               pk2(ll[4],ll[5]), pk2(ll[6],ll[7]));
}

// conv_split4: the 4 weight matrices into g_w slots (y = slot)
__global__ __launch_bounds__(256) void conv_split4_kernel(
    const float* __restrict__ s0, const float* __restrict__ s1,
    const float* __restrict__ s2, const float* __restrict__ s3, int n8)
{
    int i = blockIdx.x * 256 + threadIdx.x;
    if (i >= n8) return;
    const float* srcs[4] = {s0, s1, s2, s3};
    const float* src = srcs[blockIdx.y];
    size_t slot = (size_t)blockIdx.y * D_ * D_;
    const float4* s = (const float4*)(src + (size_t)i * 8);
    float4 v0 = s[0], v1 = s[1];
    float f[8] = {v0.x, v0.y, v0.z, v0.w, v1.x, v1.y, v1.z, v1.w};
    float hh[8], ll[8];
#pragma unroll
    for (int e = 0; e < 8; e++) { hh[e] = bhi(f[e]); ll[e] = f[e] - hh[e]; }
    *(uint4*)(g_w_hi + slot + (size_t)i * 8) =
        make_uint4(pk2(hh[0],hh[1]), pk2(hh[2],hh[3]),
                   pk2(hh[4],hh[5]), pk2(hh[6],hh[7]));
    *(uint4*)(g_w_lo + slot + (size_t)i * 8) =
        make_uint4(pk2(ll[0],ll[1]), pk2(ll[2],ll[3]),
                   pk2(ll[4],ll[5]), pk2(ll[6],ll[7]));
}

// ---------------------------------------------------------------------------
// wker_prep: g_wker[h][n][d] = Wker[h, n&63, n>>6, d] for n<448 else 0
// ---------------------------------------------------------------------------
__global__ __launch_bounds__(256) void wker_prep_kernel(const float* __restrict__ Wker)
{
    int idx = blockIdx.x * 256 + threadIdx.x;      // over 8*512*8
    if (idx >= H_ * WKN * 8) return;
    int d8 = (idx & 7) * 8;
    int n  = (idx >> 3) & (WKN - 1);
    int h  = idx >> 12;
    float f[8] = {0,0,0,0,0,0,0,0};
    if (n < NCAT) {
        int t = n >> 6, c = n & 63;
        const float* src = Wker + (((size_t)(h*DK_ + c)) * KW_ + t) * DK_ + d8;
        float4 v0 = *(const float4*)src, v1 = *(const float4*)(src + 4);
        f[0]=v0.x; f[1]=v0.y; f[2]=v0.z; f[3]=v0.w;
        f[4]=v1.x; f[5]=v1.y; f[6]=v1.z; f[7]=v1.w;
    }
    float hh[8], ll[8];
#pragma unroll
    for (int e = 0; e < 8; e++) { hh[e] = bhi(f[e]); ll[e] = f[e] - hh[e]; }
    size_t off = ((size_t)h * WKN + n) * DK_ + d8;
    *(uint4*)(g_wker_hi + off) = make_uint4(pk2(hh[0],hh[1]), pk2(hh[2],hh[3]),
                                            pk2(hh[4],hh[5]), pk2(hh[6],hh[7]));
    *(uint4*)(g_wker_lo + off) = make_uint4(pk2(ll[0],ll[1]), pk2(ll[2],ll[3]),
                                            pk2(ll[4],ll[5]), pk2(ll[6],ll[7]));
}

// ---------------------------------------------------------------------------
// bcat[h, n] = bker[h, n&63, n>>6] for n<448 else 0   (padded to 512)
// ---------------------------------------------------------------------------
__global__ void bcat_kernel(const float* __restrict__ bker)
{
    int n = blockIdx.x * blockDim.x + threadIdx.x;
    if (n >= H_ * WKN) return;
    int h = n >> 9, r = n & (WKN - 1), t = r >> 6, c = r & 63;
    g_bcat[n] = (r < NCAT) ? bker[(size_t)(h*DK_ + c) * KW_ + t] : 0.f;
}

// ---------------------------------------------------------------------------
// Shared 3-stage mma mainloop pieces (tile 128x128, 8 warps 2x4)
// ---------------------------------------------------------------------------
#define GM_STAGE 32768
#define GM_SMEM3 (3*GM_STAGE)

// ---------------------------------------------------------------------------
// out-projection GEMM: C[M,N] fp32 = A@B^T + bias[N].  3-stage.  2 CTAs/SM.
// ---------------------------------------------------------------------------
__global__ __launch_bounds__(256, 2) void gemm_mma_nt(
    const __nv_bfloat16* __restrict__ Ah, const __nv_bfloat16* __restrict__ Al,
    const __nv_bfloat16* __restrict__ Bh, const __nv_bfloat16* __restrict__ Bl,
    const float* __restrict__ bias, float* __restrict__ C, int K, int N)
{
    extern __shared__ char smem[];
    const uint32_t sbase = smem_u32(smem);
    const int kc = K >> 5;

    const int tid  = threadIdx.x;
    const int wid  = tid >> 5, lane = tid & 31;
    const int wm   = wid >> 2, wn = wid & 3;

    const int i0 = blockIdx.y * 128;
    const int j0 = blockIdx.x * 128;

    const __nv_bfloat16* ah = Ah + (size_t)i0 * K;
    const __nv_bfloat16* al = Al + (size_t)i0 * K;
    const __nv_bfloat16* bh_ = Bh + (size_t)j0 * K;
    const __nv_bfloat16* bl_ = Bl + (size_t)j0 * K;

    auto issue = [&](int s, int c) {
        const uint32_t sb = sbase + s * GM_STAGE;
#pragma unroll
        for (int q = 0; q < 4; q++) {
            int u  = q * 256 + tid;
            int r  = u >> 3, cj = u & 7;
            const __nv_bfloat16* src =
                (cj < 4 ? ah : al) + (size_t)r * K + c * 32 + (cj & 3) * 8;
            CP_ASYNC16(sb + r * 128 + 16 * (cj ^ (r & 7)), src);
        }
#pragma unroll
        for (int q = 0; q < 4; q++) {
            int u  = q * 256 + tid;
            int r  = u >> 3, cj = u & 7;
            const __nv_bfloat16* src =
                (cj < 4 ? bh_ : bl_) + (size_t)r * K + c * 32 + (cj & 3) * 8;
            CP_ASYNC16(sb + 16384 + r * 128 + 16 * (cj ^ (r & 7)), src);
        }
    };

    float acc[4][4][4];
#pragma unroll
    for (int i = 0; i < 4; i++)
#pragma unroll
        for (int j = 0; j < 4; j++)
#pragma unroll
            for (int e = 0; e < 4; e++) acc[i][j][e] = 0.f;

    issue(0, 0); CP_COMMIT();
    issue(1, 1); CP_COMMIT();

    const int lrow = (lane & 7) + 8 * ((lane >> 3) & 1);
    const int lchk = lane >> 4;

    int stage = 0;
    for (int c = 0; c < kc; c++) {
        if (c + 2 < kc) {
            int s2 = stage + 2; if (s2 >= 3) s2 -= 3;
            issue(s2, c + 2); CP_COMMIT(); CP_WAIT(2);
        } else if (c + 1 < kc) { CP_WAIT(1); }
        else                   { CP_WAIT(0); }
        __syncthreads();

        const uint32_t sA = sbase + stage * GM_STAGE;
        const uint32_t sB = sA + 16384;

#pragma unroll
        for (int ks = 0; ks < 2; ks++) {
            uint32_t bh[4][2], bl[4][2];
#pragma unroll
            for (int g = 0; g < 2; g++) {
                int r  = wn * 32 + g * 16 + lrow;
                int ch = ks * 2 + lchk;
                uint32_t r0, r1, r2, r3;
                LDSM4(r0, r1, r2, r3, sB + r * 128 + 16 * ((ch)     ^ (r & 7)));
                bh[2*g][0] = r0; bh[2*g][1] = r2;
                bh[2*g+1][0] = r1; bh[2*g+1][1] = r3;
                LDSM4(r0, r1, r2, r3, sB + r * 128 + 16 * ((ch + 4) ^ (r & 7)));
                bl[2*g][0] = r0; bl[2*g][1] = r2;
                bl[2*g+1][0] = r1; bl[2*g+1][1] = r3;
            }
#pragma unroll
            for (int mf = 0; mf < 4; mf++) {
                int r  = wm * 64 + mf * 16 + lrow;
                int ch = ks * 2 + lchk;
                uint32_t ah_[4], al_[4];
                LDSM4(ah_[0], ah_[1], ah_[2], ah_[3],
                      sA + r * 128 + 16 * ((ch)     ^ (r & 7)));
                LDSM4(al_[0], al_[1], al_[2], al_[3],
                      sA + r * 128 + 16 * ((ch + 4) ^ (r & 7)));
#pragma unroll
                for (int nf = 0; nf < 4; nf++) {
                    MMA16816(acc[mf][nf], ah_, bh[nf]);
                    MMA16816(acc[mf][nf], ah_, bl[nf]);
                    MMA16816(acc[mf][nf], al_, bh[nf]);
                }
            }
        }
        __syncthreads();
        stage++; if (stage == 3) stage = 0;
    }

    const int rbase = i0 + wm * 64 + (lane >> 2);
    const int cbase = j0 + wn * 32 + 2 * (lane & 3);
#pragma unroll
    for (int mf = 0; mf < 4; mf++) {
        int gi = rbase + mf * 16;
        float* row0 = C + (size_t)gi * N;
        float* row1 = row0 + 8 * N;
#pragma unroll
        for (int nf = 0; nf < 4; nf++) {
            int gj = cbase + nf * 8;
            float b0 = bias[gj], b1 = bias[gj + 1];
            *(float2*)(row0 + gj) = make_float2(acc[mf][nf][0] + b0,
                                                acc[mf][nf][1] + b1);
            *(float2*)(row1 + gj) = make_float2(acc[mf][nf][2] + b0,
                                                acc[mf][nf][3] + b1);
        }
    }
}

// ---------------------------------------------------------------------------
// projection GEMM writing bf16 hi/lo ONLY.  K = N = 512, 16 chunks, 3-stage.
// Used for q, k, v projections.
// ---------------------------------------------------------------------------
__global__ __launch_bounds__(256, 2) void gemm_mma_split(
    const __nv_bfloat16* __restrict__ Ah, const __nv_bfloat16* __restrict__ Al,
    const __nv_bfloat16* __restrict__ Bh, const __nv_bfloat16* __restrict__ Bl,
    const float* __restrict__ bias,
    __nv_bfloat16* __restrict__ Ch, __nv_bfloat16* __restrict__ Cl)
{
    extern __shared__ char smem[];
    const uint32_t sbase = smem_u32(smem);
    const int K = D_;

    const int tid  = threadIdx.x;
    const int wid  = tid >> 5, lane = tid & 31;
    const int wm   = wid >> 2, wn = wid & 3;

    const int i0 = blockIdx.y * 128;
    const int j0 = blockIdx.x * 128;

    const __nv_bfloat16* ah = Ah + (size_t)i0 * K;
    const __nv_bfloat16* al = Al + (size_t)i0 * K;
    const __nv_bfloat16* bh_ = Bh + (size_t)j0 * K;
    const __nv_bfloat16* bl_ = Bl + (size_t)j0 * K;

    auto issue = [&](int s, int c) {
        const uint32_t sb = sbase + s * GM_STAGE;
#pragma unroll
        for (int q = 0; q < 4; q++) {
            int u  = q * 256 + tid;
            int r  = u >> 3, cj = u & 7;
            const __nv_bfloat16* src =
                (cj < 4 ? ah : al) + (size_t)r * K + c * 32 + (cj & 3) * 8;
            CP_ASYNC16(sb + r * 128 + 16 * (cj ^ (r & 7)), src);
        }
#pragma unroll
        for (int q = 0; q < 4; q++) {
            int u  = q * 256 + tid;
            int r  = u >> 3, cj = u & 7;
            const __nv_bfloat16* src =
                (cj < 4 ? bh_ : bl_) + (size_t)r * K + c * 32 + (cj & 3) * 8;
            CP_ASYNC16(sb + 16384 + r * 128 + 16 * (cj ^ (r & 7)), src);
        }
    };

    float acc[4][4][4];
#pragma unroll
    for (int i = 0; i < 4; i++)
#pragma unroll
        for (int j = 0; j < 4; j++)
#pragma unroll
            for (int e = 0; e < 4; e++) acc[i][j][e] = 0.f;

    issue(0, 0); CP_COMMIT();
    issue(1, 1); CP_COMMIT();

    const int lrow = (lane & 7) + 8 * ((lane >> 3) & 1);
    const int lchk = lane >> 4;

    int stage = 0;
    for (int c = 0; c < 16; c++) {
        if (c + 2 < 16) {
            int s2 = stage + 2; if (s2 >= 3) s2 -= 3;
            issue(s2, c + 2); CP_COMMIT(); CP_WAIT(2);
        } else if (c + 1 < 16) { CP_WAIT(1); }
        else                   { CP_WAIT(0); }
        __syncthreads();

        const uint32_t sA = sbase + stage * GM_STAGE;
        const uint32_t sB = sA + 16384;

#pragma unroll
        for (int ks = 0; ks < 2; ks++) {
            uint32_t bh[4][2], bl[4][2];
#pragma unroll
            for (int g = 0; g < 2; g++) {
                int r  = wn * 32 + g * 16 + lrow;
                int ch = ks * 2 + lchk;
                uint32_t r0, r1, r2, r3;
                LDSM4(r0, r1, r2, r3, sB + r * 128 + 16 * ((ch)     ^ (r & 7)));
                bh[2*g][0] = r0; bh[2*g][1] = r2;
                bh[2*g+1][0] = r1; bh[2*g+1][1] = r3;
                LDSM4(r0, r1, r2, r3, sB + r * 128 + 16 * ((ch + 4) ^ (r & 7)));
                bl[2*g][0] = r0; bl[2*g][1] = r2;
                bl[2*g+1][0] = r1; bl[2*g+1][1] = r3;
            }
#pragma unroll
            for (int mf = 0; mf < 4; mf++) {
                int r  = wm * 64 + mf * 16 + lrow;
                int ch = ks * 2 + lchk;
                uint32_t ah_[4], al_[4];
                LDSM4(ah_[0], ah_[1], ah_[2], ah_[3],
                      sA + r * 128 + 16 * ((ch)     ^ (r & 7)));
                LDSM4(al_[0], al_[1], al_[2], al_[3],
                      sA + r * 128 + 16 * ((ch + 4) ^ (r & 7)));
#pragma unroll
                for (int nf = 0; nf < 4; nf++) {
                    MMA16816(acc[mf][nf], ah_, bh[nf]);
                    MMA16816(acc[mf][nf], ah_, bl[nf]);
                    MMA16816(acc[mf][nf], al_, bh[nf]);
                }
            }
        }
        __syncthreads();
        stage++; if (stage == 3) stage = 0;
    }

    const int rbase = i0 + wm * 64 + (lane >> 2);
    const int cbase = j0 + wn * 32 + 2 * (lane & 3);
#pragma unroll
    for (int mf = 0; mf < 4; mf++) {
        int gi = rbase + mf * 16;
        size_t ro0 = (size_t)gi * D_, ro1 = ro0 + 8 * D_;
#pragma unroll
        for (int nf = 0; nf < 4; nf++) {
            int gj = cbase + nf * 8;
            float b0 = bias[gj], b1 = bias[gj + 1];
            float v0 = acc[mf][nf][0] + b0, v1 = acc[mf][nf][1] + b1;
            float v2 = acc[mf][nf][2] + b0, v3 = acc[mf][nf][3] + b1;
            float h0 = bhi(v0), h1 = bhi(v1), h2 = bhi(v2), h3 = bhi(v3);
            *(unsigned*)(Ch + ro0 + gj) = pk2(h0, h1);
            *(unsigned*)(Cl + ro0 + gj) = pk2(v0 - h0, v1 - h1);
            *(unsigned*)(Ch + ro1 + gj) = pk2(h2, h3);
            *(unsigned*)(Cl + ro1 + gj) = pk2(v2 - h2, v3 - h3);
        }
    }
}

// ---------------------------------------------------------------------------
// qcat via mma: per z: Qcat[1024, n<448] = q_s_head[1024,64] @ wker[512,64]^T
//   + bcat. K=64 -> 2 chunks.  grid (4, 8, 64).  compact stride 448.
// ---------------------------------------------------------------------------
__global__ __launch_bounds__(256, 2) void qcat_mma_kernel()
{
    __shared__ char smem[2 * GM_STAGE];
    const uint32_t sbase = smem_u32(smem);

    const int tid  = threadIdx.x;
    const int wid  = tid >> 5, lane = tid & 31;
    const int wm   = wid >> 2, wn = wid & 3;

    const int z  = blockIdx.z;
    const int b = z >> 3, h = z & 7;
    const int i0 = blockIdx.y * 128;
    const int n0 = blockIdx.x * 128;

    const __nv_bfloat16* ah = g_qs_hi + ((size_t)(b*L_ + i0)) * D_ + h*DK_;
    const __nv_bfloat16* al = g_qs_lo + ((size_t)(b*L_ + i0)) * D_ + h*DK_;
    const __nv_bfloat16* bh_ = g_wker_hi + ((size_t)h * WKN + n0) * DK_;
    const __nv_bfloat16* bl_ = g_wker_lo + ((size_t)h * WKN + n0) * DK_;

    auto issue = [&](int s, int c) {
        const uint32_t sb = sbase + s * GM_STAGE;
#pragma unroll
        for (int q = 0; q < 4; q++) {
            int u  = q * 256 + tid;
            int r  = u >> 3, cj = u & 7;
            const __nv_bfloat16* src =
                (cj < 4 ? ah : al) + (size_t)r * D_ + c * 32 + (cj & 3) * 8;
            CP_ASYNC16(sb + r * 128 + 16 * (cj ^ (r & 7)), src);
        }
#pragma unroll
        for (int q = 0; q < 4; q++) {
            int u  = q * 256 + tid;
            int r  = u >> 3, cj = u & 7;
            const __nv_bfloat16* src =
                (cj < 4 ? bh_ : bl_) + (size_t)r * DK_ + c * 32 + (cj & 3) * 8;
            CP_ASYNC16(sb + 16384 + r * 128 + 16 * (cj ^ (r & 7)), src);
        }
    };

    float acc[4][4][4];
#pragma unroll
    for (int i = 0; i < 4; i++)
#pragma unroll
        for (int j = 0; j < 4; j++)
#pragma unroll
            for (int e = 0; e < 4; e++) acc[i][j][e] = 0.f;

    issue(0, 0);
    CP_COMMIT();

    const int lrow = (lane & 7) + 8 * ((lane >> 3) & 1);
    const int lchk = lane >> 4;

    for (int c = 0; c < 2; c++) {
        const int s = c & 1;
        if (c == 0) { issue(1, 1); CP_COMMIT(); CP_WAIT(1); }
        else        { CP_WAIT(0); }
        __syncthreads();

        const uint32_t sA = sbase + s * GM_STAGE;
        const uint32_t sB = sA + 16384;

#pragma unroll
        for (int ks = 0; ks < 2; ks++) {
            uint32_t bh[4][2], bl[4][2];
#pragma unroll
            for (int g = 0; g < 2; g++) {
                int r  = wn * 32 + g * 16 + lrow;
                int ch = ks * 2 + lchk;
                uint32_t r0, r1, r2, r3;
                LDSM4(r0, r1, r2, r3, sB + r * 128 + 16 * ((ch)     ^ (r & 7)));
                bh[2*g][0] = r0; bh[2*g][1] = r2;
                bh[2*g+1][0] = r1; bh[2*g+1][1] = r3;
                LDSM4(r0, r1, r2, r3, sB + r * 128 + 16 * ((ch + 4) ^ (r & 7)));
                bl[2*g][0] = r0; bl[2*g][1] = r2;
                bl[2*g+1][0] = r1; bl[2*g+1][1] = r3;
            }
#pragma unroll
            for (int mf = 0; mf < 4; mf++) {
                int r  = wm * 64 + mf * 16 + lrow;
                int ch = ks * 2 + lchk;
                uint32_t ah_[4], al_[4];
                LDSM4(ah_[0], ah_[1], ah_[2], ah_[3],
                      sA + r * 128 + 16 * ((ch)     ^ (r & 7)));
                LDSM4(al_[0], al_[1], al_[2], al_[3],
                      sA + r * 128 + 16 * ((ch + 4) ^ (r & 7)));
#pragma unroll
                for (int nf = 0; nf < 4; nf++) {
                    MMA16816(acc[mf][nf], ah_, bh[nf]);
                    MMA16816(acc[mf][nf], ah_, bl[nf]);
                    MMA16816(acc[mf][nf], al_, bh[nf]);
                }
            }
        }
        __syncthreads();
    }

    __nv_bfloat16* Ch = g_qcat_hi + (size_t)z * L_ * NCAT;
    __nv_bfloat16* Cl = g_qcat_lo + (size_t)z * L_ * NCAT;
    const int rbase = i0 + wm * 64 + (lane >> 2);
    const int cbase = n0 + wn * 32 + 2 * (lane & 3);
#pragma unroll
    for (int mf = 0; mf < 4; mf++) {
        int gi = rbase + mf * 16;
        size_t ro0 = (size_t)gi * NCAT, ro1 = ro0 + 8 * NCAT;
#pragma unroll
        for (int nf = 0; nf < 4; nf++) {
            int gj = cbase + nf * 8;
            if (gj >= NCAT) continue;
            float b0 = g_bcat[h*WKN + gj], b1 = g_bcat[h*WKN + gj + 1];
            float v0 = acc[mf][nf][0] + b0, v1 = acc[mf][nf][1] + b1;
            float v2 = acc[mf][nf][2] + b0, v3 = acc[mf][nf][3] + b1;
            float h0 = bhi(v0), h1 = bhi(v1), h2 = bhi(v2), h3 = bhi(v3);
            *(unsigned*)(Ch + ro0 + gj) = pk2(h0, h1);
            *(unsigned*)(Cl + ro0 + gj) = pk2(v0 - h0, v1 - h1);
            *(unsigned*)(Ch + ro1 + gj) = pk2(h2, h3);
            *(unsigned*)(Cl + ro1 + gj) = pk2(v2 - h2, v3 - h3);
        }
    }
}

// ---------------------------------------------------------------------------
// Kcat prep: pure shifted copy of pre-split k_s.
//   Kcat[z][j][t*64+c] = ks_{hi,lo}[b*L + j+t-3][h*64+c]   (0 outside range)
// ---------------------------------------------------------------------------
__global__ __launch_bounds__(256) void kcat_prep_kernel()
{
    int idx = blockIdx.x * 256 + threadIdx.x;
    if (idx >= B_*H_*L_*(NCAT/8)) return;
    int c8 = idx % (NCAT/8);
    int rest = idx / (NCAT/8);
    int j = rest & (L_-1);
    int z = rest >> 10;
    int b = z >> 3, h = z & 7;
    int cpos = c8 * 8;
    int t = cpos >> 6, cc = cpos & 63;
    int src = j + t - PAD_;
    uint4 vh = make_uint4(0,0,0,0), vl = make_uint4(0,0,0,0);
    if (src >= 0 && src < L_) {
        size_t so = ((size_t)(b*L_ + src)) * D_ + h*DK_ + cc;
        vh = *(const uint4*)(g_ks_hi + so);
        vl = *(const uint4*)(g_ks_lo + so);
    }
    size_t off = (size_t)z * L_ * NCAT + (size_t)j * NCAT + cpos;
    *(uint4*)(g_kcat_hi + off) = vh;
    *(uint4*)(g_kcat_lo + off) = vl;
}

// ---------------------------------------------------------------------------
// vt transpose (bf16): vt[z][n][k] = v_s[b][k][h*64+n], hi/lo packed in smem.
// ---------------------------------------------------------------------------
__global__ __launch_bounds__(256) void vt_kernel()
{
    __shared__ uint32_t t[128][65];   // hi | lo<<16 per element
    const int z = blockIdx.y;
    const int b = z >> 3, h = z & 7;
    const int k0 = blockIdx.x * 128;
    const int tid = threadIdx.x;

#pragma unroll
    for (int q = 0; q < 4; q++) {          // 1024 units of 8 elems
        int u = q * 256 + tid;
        int r = u >> 3, c8 = (u & 7) * 8;
        size_t so = ((size_t)(b*L_ + k0 + r)) * D_ + h*DK_ + c8;
        uint4 vh = *(const uint4*)(g_vs_hi + so);
        uint4 vl = *(const uint4*)(g_vs_lo + so);
        uint32_t hw[4] = {vh.x, vh.y, vh.z, vh.w};
        uint32_t lw[4] = {vl.x, vl.y, vl.z, vl.w};
#pragma unroll
        for (int e = 0; e < 4; e++) {
            t[r][c8 + 2*e]     = (hw[e] & 0xffffu) | (lw[e] << 16);
            t[r][c8 + 2*e + 1] = (hw[e] >> 16)     | (lw[e] & 0xffff0000u);
        }
    }
    __syncthreads();

#pragma unroll
    for (int q = 0; q < 4; q++) {          // 64 n x 16 k-groups of 8
        int u = q * 256 + tid;
        int n = u >> 4, k8 = (u & 15) * 8;
        uint32_t hi4[4], lo4[4];
#pragma unroll
        for (int e = 0; e < 4; e++) {
            uint32_t a = t[k8 + 2*e][n];
            uint32_t c = t[k8 + 2*e + 1][n];
            hi4[e] = (a & 0xffffu) | ((c & 0xffffu) << 16);
            lo4[e] = (a >> 16)     | (c & 0xffff0000u);
        }
        size_t off = (size_t)z * DK_ * L_ + (size_t)n * L_ + k0 + k8;
        *(uint4*)(g_vt_hi + off) = make_uint4(hi4[0], hi4[1], hi4[2], hi4[3]);
        *(uint4*)(g_vt_lo + off) = make_uint4(lo4[0], lo4[1], lo4[2], lo4[3]);
    }
}

// ---------------------------------------------------------------------------
// Logits: 128x128 tile, K=448 in 14 chunks, A=Qcat B=Kcat, 3-stage pipeline.
// No rowbias (cancels in softmax).  grid (8, 8, 64).  2 CTAs/SM.
// ---------------------------------------------------------------------------
#define LOG_STAGE 32768
#define LOG_SMEM  (3*LOG_STAGE)

__global__ __launch_bounds__(256, 2) void logits_mma_kernel(float* __restrict__ attn)
{
    extern __shared__ char smem[];
    const uint32_t sbase = smem_u32(smem);

    const int tid  = threadIdx.x;
    const int wid  = tid >> 5, lane = tid & 31;
    const int wm   = wid >> 2, wn = wid & 3;

    const int z  = blockIdx.z;
    const int i0 = blockIdx.y * 128;
    const int j0 = blockIdx.x * 128;

    const __nv_bfloat16* qh = g_qcat_hi + (size_t)z * L_ * NCAT + (size_t)i0 * NCAT;
    const __nv_bfloat16* ql = g_qcat_lo + (size_t)z * L_ * NCAT + (size_t)i0 * NCAT;
    const __nv_bfloat16* kh = g_kcat_hi + (size_t)z * L_ * NCAT + (size_t)j0 * NCAT;
    const __nv_bfloat16* kl = g_kcat_lo + (size_t)z * L_ * NCAT + (size_t)j0 * NCAT;

    auto issue = [&](int s, int c) {
        const uint32_t sb = sbase + s * LOG_STAGE;
#pragma unroll
        for (int q = 0; q < 4; q++) {
            int u  = q * 256 + tid;
            int r  = u >> 3, cj = u & 7;
            const __nv_bfloat16* src =
                (cj < 4 ? qh : ql) + (size_t)r * NCAT + c * 32 + (cj & 3) * 8;
            CP_ASYNC16(sb + r * 128 + 16 * (cj ^ (r & 7)), src);
        }
#pragma unroll
        for (int q = 0; q < 4; q++) {
            int u  = q * 256 + tid;
            int r  = u >> 3, cj = u & 7;
            const __nv_bfloat16* src =
                (cj < 4 ? kh : kl) + (size_t)r * NCAT + c * 32 + (cj & 3) * 8;
            CP_ASYNC16(sb + 16384 + r * 128 + 16 * (cj ^ (r & 7)), src);
        }
    };

    float acc[4][4][4];
#pragma unroll
    for (int i = 0; i < 4; i++)
#pragma unroll
        for (int j = 0; j < 4; j++)
#pragma unroll
            for (int e = 0; e < 4; e++) acc[i][j][e] = 0.f;

    issue(0, 0); CP_COMMIT();
    issue(1, 1); CP_COMMIT();

    const int lrow = (lane & 7) + 8 * ((lane >> 3) & 1);
    const int lchk = lane >> 4;

    int stage = 0;
    for (int c = 0; c < 14; c++) {
        if (c + 2 < 14) {
            int s2 = stage + 2; if (s2 >= 3) s2 -= 3;
            issue(s2, c + 2); CP_COMMIT(); CP_WAIT(2);
        } else if (c + 1 < 14) { CP_WAIT(1); }
        else                   { CP_WAIT(0); }
        __syncthreads();

        const uint32_t sA = sbase + stage * LOG_STAGE;
        const uint32_t sB = sA + 16384;

#pragma unroll
        for (int ks = 0; ks < 2; ks++) {
            uint32_t bh[4][2], bl[4][2];
#pragma unroll
            for (int g = 0; g < 2; g++) {
                int r  = wn * 32 + g * 16 + lrow;
                int ch = ks * 2 + lchk;
                uint32_t r0, r1, r2, r3;
                LDSM4(r0, r1, r2, r3, sB + r * 128 + 16 * ((ch)     ^ (r & 7)));
                bh[2*g][0] = r0; bh[2*g][1] = r2;
                bh[2*g+1][0] = r1; bh[2*g+1][1] = r3;
                LDSM4(r0, r1, r2, r3, sB + r * 128 + 16 * ((ch + 4) ^ (r & 7)));
                bl[2*g][0] = r0; bl[2*g][1] = r2;
                bl[2*g+1][0] = r1; bl[2*g+1][1] = r3;
            }
#pragma unroll
            for (int mf = 0; mf < 4; mf++) {
                int r  = wm * 64 + mf * 16 + lrow;
                int ch = ks * 2 + lchk;
                uint32_t ah[4], al[4];
                LDSM4(ah[0], ah[1], ah[2], ah[3],
                      sA + r * 128 + 16 * ((ch)     ^ (r & 7)));
                LDSM4(al[0], al[1], al[2], al[3],
                      sA + r * 128 + 16 * ((ch + 4) ^ (r & 7)));
#pragma unroll
                for (int nf = 0; nf < 4; nf++) {
                    MMA16816(acc[mf][nf], ah, bh[nf]);
                    MMA16816(acc[mf][nf], ah, bl[nf]);
                    MMA16816(acc[mf][nf], al, bh[nf]);
                }
            }
        }
        __syncthreads();
        stage++; if (stage == 3) stage = 0;
    }

    const int rbase = i0 + wm * 64 + (lane >> 2);
    const int cbase = j0 + wn * 32 + 2 * (lane & 3);
#pragma unroll
    for (int mf = 0; mf < 4; mf++) {
        int gi0 = rbase + mf * 16;
        float* row0 = attn + ((size_t)z * L_ + gi0) * L_;
        float* row1 = row0 + 8 * L_;
#pragma unroll
        for (int nf = 0; nf < 4; nf++) {
            int gj = cbase + nf * 8;
            *(float2*)(row0 + gj) = make_float2(acc[mf][nf][0]*0.125f,
                                                acc[mf][nf][1]*0.125f);
            *(float2*)(row1 + gj) = make_float2(acc[mf][nf][2]*0.125f,
                                                acc[mf][nf][3]*0.125f);
        }
    }
}

// ---------------------------------------------------------------------------
// Row softmax in-place on attn; mask; head-0 duplicate.
// ---------------------------------------------------------------------------
__global__ __launch_bounds__(256) void softmax_kernel(
    float* __restrict__ attn, const unsigned char* __restrict__ mask,
    float* __restrict__ one_head)
{
    const int r = blockIdx.x;
    const int i = r & (L_-1);
    const int bh = r >> 10;
    const int h = bh & (H_-1), b = bh >> 3;
    float* row = attn + (size_t)r * L_;
    const unsigned char* mrow = mask + ((size_t)(b*L_ + i)) * L_;
    const int t4 = threadIdx.x * 4;

    float4 v = *(const float4*)(row + t4);
    uchar4 m = *(const uchar4*)(mrow + t4);
    float x0 = m.x ? -INFINITY : v.x;
    float x1 = m.y ? -INFINITY : v.y;
    float x2 = m.z ? -INFINITY : v.z;
    float x3 = m.w ? -INFINITY : v.w;

    __shared__ float sm[8], ss[8];
    float mx = fmaxf(fmaxf(x0, x1), fmaxf(x2, x3));
#pragma unroll
    for (int o = 16; o; o >>= 1) mx = fmaxf(mx, __shfl_xor_sync(0xffffffffu, mx, o));
    if ((threadIdx.x & 31) == 0) sm[threadIdx.x >> 5] = mx;
    __syncthreads();
    if (threadIdx.x < 32) {
        float t = (threadIdx.x < 8) ? sm[threadIdx.x] : -INFINITY;
#pragma unroll
        for (int o = 4; o; o >>= 1) t = fmaxf(t, __shfl_xor_sync(0xffffffffu, t, o));
        if (threadIdx.x == 0) sm[0] = t;
    }
    __syncthreads();
    mx = sm[0];

    float e0 = __expf(x0 - mx), e1 = __expf(x1 - mx);
    float e2 = __expf(x2 - mx), e3 = __expf(x3 - mx);
    float s = (e0 + e1) + (e2 + e3);
#pragma unroll
    for (int o = 16; o; o >>= 1) s += __shfl_xor_sync(0xffffffffu, s, o);
    if ((threadIdx.x & 31) == 0) ss[threadIdx.x >> 5] = s;
    __syncthreads();
    if (threadIdx.x < 32) {
        float t = (threadIdx.x < 8) ? ss[threadIdx.x] : 0.f;
#pragma unroll
        for (int o = 4; o; o >>= 1) t += __shfl_xor_sync(0xffffffffu, t, o);
        if (threadIdx.x == 0) ss[0] = t;
    }
    __syncthreads();
    float inv = 1.0f / ss[0];

    float4 o = make_float4(e0*inv, e1*inv, e2*inv, e3*inv);
    *(float4*)(row + t4) = o;
    if (h == 0)
        *(float4*)(one_head + ((size_t)(b*L_ + i)) * L_ + t4) = o;
}

// ---------------------------------------------------------------------------
// ctx via mma: per (b,h): C[1024,64] = attn @ v_head.
// ---------------------------------------------------------------------------
#define CTX_STAGE 24576

__global__ __launch_bounds__(256, 2) void ctx_mma_kernel(const float* __restrict__ attn)
{
    __shared__ char smem[2 * CTX_STAGE];
    const uint32_t sbase = smem_u32(smem);

    const int tid  = threadIdx.x;
    const int wid  = tid >> 5, lane = tid & 31;
    const int wm   = wid >> 2, wn = wid & 3;

    const int z  = blockIdx.y;
    const int b = z >> 3, h = z & 7;
    const int i0 = blockIdx.x * 128;

    const float* A = attn + ((size_t)z * L_ + i0) * L_;
    const __nv_bfloat16* vh = g_vt_hi + (size_t)z * DK_ * L_;
    const __nv_bfloat16* vl = g_vt_lo + (size_t)z * DK_ * L_;

    auto issueB = [&](int s, int c) {
        const uint32_t sb = sbase + s * CTX_STAGE + 16384;
#pragma unroll
        for (int q = 0; q < 2; q++) {
            int u  = q * 256 + tid;
            int r  = u >> 3, cj = u & 7;
            const __nv_bfloat16* src =
                (cj < 4 ? vh : vl) + (size_t)r * L_ + c * 32 + (cj & 3) * 8;
            CP_ASYNC16(sb + r * 128 + 16 * (cj ^ (r & 7)), src);
        }
    };
    float fa[2][8];
    auto ldgA = [&](int c) {
#pragma unroll
        for (int q = 0; q < 2; q++) {
            int u = q * 256 + tid;
            int r = u >> 2, seg = u & 3;
            const float4* p = (const float4*)(A + (size_t)r * L_ + c * 32 + seg * 8);
            float4 v0 = p[0], v1 = p[1];
            fa[q][0]=v0.x; fa[q][1]=v0.y; fa[q][2]=v0.z; fa[q][3]=v0.w;
            fa[q][4]=v1.x; fa[q][5]=v1.y; fa[q][6]=v1.z; fa[q][7]=v1.w;
        }
    };
    auto stsA = [&](int s) {
#pragma unroll
        for (int q = 0; q < 2; q++) {
            int u = q * 256 + tid;
            int r = u >> 2, seg = u & 3;
            float hh[8], ll[8];
#pragma unroll
            for (int e = 0; e < 8; e++) { hh[e] = bhi(fa[q][e]); ll[e] = fa[q][e] - hh[e]; }
            *(uint4*)(smem + s * CTX_STAGE + r * 128 + 16 * ((seg)     ^ (r & 7))) =
                make_uint4(pk2(hh[0],hh[1]), pk2(hh[2],hh[3]),
                           pk2(hh[4],hh[5]), pk2(hh[6],hh[7]));
            *(uint4*)(smem + s * CTX_STAGE + r * 128 + 16 * ((seg + 4) ^ (r & 7))) =
                make_uint4(pk2(ll[0],ll[1]), pk2(ll[2],ll[3]),
                           pk2(ll[4],ll[5]), pk2(ll[6],ll[7]));
        }
    };

    float acc[4][2][4];
#pragma unroll
    for (int i = 0; i < 4; i++)
#pragma unroll
        for (int j = 0; j < 2; j++)
#pragma unroll
            for (int e = 0; e < 4; e++) acc[i][j][e] = 0.f;

    ldgA(0);
    issueB(0, 0); CP_COMMIT();

    const int lrow = (lane & 7) + 8 * ((lane >> 3) & 1);
    const int lchk = lane >> 4;

    for (int c = 0; c < 32; c++) {
        const int s = c & 1;
        stsA(s);
        if (c + 1 < 32) {
            ldgA(c + 1);
            issueB(s ^ 1, c + 1); CP_COMMIT(); CP_WAIT(1);
        } else {
            CP_WAIT(0);
        }
        __syncthreads();

        const uint32_t sA = sbase + s * CTX_STAGE;
        const uint32_t sB = sA + 16384;

#pragma unroll
        for (int ks = 0; ks < 2; ks++) {
            uint32_t bh[2][2], bl[2][2];
            {
                int r  = wn * 16 + lrow;
                int ch = ks * 2 + lchk;
                uint32_t r0, r1, r2, r3;
                LDSM4(r0, r1, r2, r3, sB + r * 128 + 16 * ((ch)     ^ (r & 7)));
                bh[0][0] = r0; bh[0][1] = r2; bh[1][0] = r1; bh[1][1] = r3;
                LDSM4(r0, r1, r2, r3, sB + r * 128 + 16 * ((ch + 4) ^ (r & 7)));
                bl[0][0] = r0; bl[0][1] = r2; bl[1][0] = r1; bl[1][1] = r3;
            }
#pragma unroll
            for (int mf = 0; mf < 4; mf++) {
                int r  = wm * 64 + mf * 16 + lrow;
                int ch = ks * 2 + lchk;
                uint32_t ah[4], al[4];
                LDSM4(ah[0], ah[1], ah[2], ah[3],
                      sA + r * 128 + 16 * ((ch)     ^ (r & 7)));
                LDSM4(al[0], al[1], al[2], al[3],
                      sA + r * 128 + 16 * ((ch + 4) ^ (r & 7)));
#pragma unroll
                for (int nf = 0; nf < 2; nf++) {
                    MMA16816(acc[mf][nf], ah, bh[nf]);
                    MMA16816(acc[mf][nf], ah, bl[nf]);
                    MMA16816(acc[mf][nf], al, bh[nf]);
                }
            }
        }
        __syncthreads();
    }

    const int rbase = i0 + wm * 64 + (lane >> 2);
    const int cb = h * DK_ + wn * 16 + 2 * (lane & 3);
#pragma unroll
    for (int mf = 0; mf < 4; mf++) {
        int gi = rbase + mf * 16;
        size_t ro0 = ((size_t)(b * L_) + gi) * D_;
        size_t ro1 = ro0 + 8 * D_;
#pragma unroll
        for (int nf = 0; nf < 2; nf++) {
            int gj = cb + nf * 8;
            float v0 = acc[mf][nf][0], v1 = acc[mf][nf][1];
            float v2 = acc[mf][nf][2], v3 = acc[mf][nf][3];
            float h0 = bhi(v0), h1 = bhi(v1), h2 = bhi(v2), h3 = bhi(v3);
            *(unsigned*)(g_ctx_hi + ro0 + gj) = pk2(h0, h1);
            *(unsigned*)(g_ctx_lo + ro0 + gj) = pk2(v0 - h0, v1 - h1);
            *(unsigned*)(g_ctx_hi + ro1 + gj) = pk2(h2, h3);
            *(unsigned*)(g_ctx_lo + ro1 + gj) = pk2(v2 - h2, v3 - h3);
        }
    }
}

// ---------------------------------------------------------------------------
extern "C" void kernel_launch(void* const* d_in, const int* in_sizes, int n_in,
                              void* d_out, int out_size)
{
    const float* q      = (const float*)d_in[0];
    const float* k      = (const float*)d_in[1];
    const float* v      = (const float*)d_in[2];
    const unsigned char* mask = (const unsigned char*)d_in[3];
    const float* Wq     = (const float*)d_in[4];
    const float* bq     = (const float*)d_in[5];
    const float* Wk     = (const float*)d_in[6];
    const float* bk     = (const float*)d_in[7];
    const float* Wv     = (const float*)d_in[8];
    const float* bv     = (const float*)d_in[9];
    const float* Wker   = (const float*)d_in[10];
    const float* bker   = (const float*)d_in[11];
    const float* Wproj  = (const float*)d_in[15];
    const float* bproj  = (const float*)d_in[16];

    float* out      = (float*)d_out;
    float* attn     = out + (size_t)B_ * L_ * D_;
    float* one_head = attn + (size_t)B_ * H_ * L_ * L_;

    void* p;
    __nv_bfloat16 *iqh, *iql, *ikh, *ikl, *ivh, *ivl, *wh, *wl, *ch, *cl;
    __nv_bfloat16 *qsh, *qsl, *ksh, *ksl, *vsh, *vsl;
    cudaGetSymbolAddress(&p, g_inq_hi); iqh = (__nv_bfloat16*)p;
    cudaGetSymbolAddress(&p, g_inq_lo); iql = (__nv_bfloat16*)p;
    cudaGetSymbolAddress(&p, g_ink_hi); ikh = (__nv_bfloat16*)p;
    cudaGetSymbolAddress(&p, g_ink_lo); ikl = (__nv_bfloat16*)p;
    cudaGetSymbolAddress(&p, g_inv_hi); ivh = (__nv_bfloat16*)p;
    cudaGetSymbolAddress(&p, g_inv_lo); ivl = (__nv_bfloat16*)p;
    cudaGetSymbolAddress(&p, g_w_hi);   wh  = (__nv_bfloat16*)p;
    cudaGetSymbolAddress(&p, g_w_lo);   wl  = (__nv_bfloat16*)p;
    cudaGetSymbolAddress(&p, g_ctx_hi); ch  = (__nv_bfloat16*)p;
    cudaGetSymbolAddress(&p, g_ctx_lo); cl  = (__nv_bfloat16*)p;
    cudaGetSymbolAddress(&p, g_qs_hi);  qsh = (__nv_bfloat16*)p;
    cudaGetSymbolAddress(&p, g_qs_lo);  qsl = (__nv_bfloat16*)p;
    cudaGetSymbolAddress(&p, g_ks_hi);  ksh = (__nv_bfloat16*)p;
    cudaGetSymbolAddress(&p, g_ks_lo);  ksl = (__nv_bfloat16*)p;
    cudaGetSymbolAddress(&p, g_vs_hi);  vsh = (__nv_bfloat16*)p;
    cudaGetSymbolAddress(&p, g_vs_lo);  vsl = (__nv_bfloat16*)p;

    static bool attr_done = false;
    if (!attr_done) {
        cudaFuncSetAttribute(logits_mma_kernel,
            cudaFuncAttributeMaxDynamicSharedMemorySize, LOG_SMEM);
        cudaFuncSetAttribute(gemm_mma_nt,
            cudaFuncAttributeMaxDynamicSharedMemorySize, GM_SMEM3);
        cudaFuncSetAttribute(gemm_mma_split,
            cudaFuncAttributeMaxDynamicSharedMemorySize, GM_SMEM3);
        attr_done = true;
    }

    const int M = B_ * L_;        // 8192
    const int NE = M * D_;
    const int NW = D_ * D_;
    dim3 blk(256);

    // 0) splits + weight prep (fused launches)
    conv_split3_kernel<<<dim3((NE/8 + 255)/256, 3), 256>>>(q, k, v, NE/8);
    conv_split4_kernel<<<dim3((NW/8 + 255)/256, 4), 256>>>(Wq, Wk, Wv, Wproj, NW/8);
    wker_prep_kernel<<<(H_*WKN*8 + 255)/256, 256>>>(Wker);
    bcat_kernel<<<(H_*WKN + 255)/256, 256>>>(bker);

    // 1) projections (tensor cores) -> bf16 hi/lo directly
    gemm_mma_split<<<dim3(D_/128, M/128), blk, GM_SMEM3>>>(iqh, iql, wh,        wl,        bq, qsh, qsl);
    gemm_mma_split<<<dim3(D_/128, M/128), blk, GM_SMEM3>>>(ikh, ikl, wh + NW,   wl + NW,   bk, ksh, ksl);
    gemm_mma_split<<<dim3(D_/128, M/128), blk, GM_SMEM3>>>(ivh, ivl, wh + 2*NW, wl + 2*NW, bv, vsh, vsl);

    // 2) operand prep
    qcat_mma_kernel<<<dim3(WKN/128, L_/128, B_*H_), blk>>>();
    kcat_prep_kernel<<<(B_*H_*L_*(NCAT/8) + 255)/256, 256>>>();
    vt_kernel<<<dim3(L_/128, B_*H_), blk>>>();

    // 3) tensor-core logits -> attn region (raw, scaled; no rowbias)
    logits_mma_kernel<<<dim3(L_/128, L_/128, B_*H_), 256, LOG_SMEM>>>(attn);

    // 4) softmax in place (+ one_head copy)
    softmax_kernel<<<B_*H_*L_, 256>>>(attn, mask, one_head);

    // 5) ctx = attn @ v_s -> g_ctx hi/lo
    ctx_mma_kernel<<<dim3(L_/128, B_*H_), blk>>>(attn);

    // 6) out = ctx @ Wproj^T + bproj
    gemm_mma_nt<<<dim3(D_/128, M/128), blk, GM_SMEM3>>>(ch, cl, wh + 3*NW, wl + 3*NW, bproj, out, D_, D_);
}

// round 13
// speedup vs baseline: 1.0078x; 1.0078x over previous
#include <cuda_runtime.h>
#include <cuda_bf16.h>
#include <cstdint>

#define B_   8
#define L_   1024
#define D_   512
#define H_   8
#define DK_  64
#define KW_  7
#define PAD_ 3
#define NCAT 448    /* KW*DK */
#define WKN  512    /* padded Wker N for qcat GEMM */

// ---------------- scratch (device globals; no runtime allocation) ----------
__device__ float g_bcat[H_*WKN];
// q/k/v_s bf16 split (written directly by the projections), layout [B*L, 512]
__device__ __align__(16) __nv_bfloat16 g_qs_hi[B_*L_*D_];
__device__ __align__(16) __nv_bfloat16 g_qs_lo[B_*L_*D_];
__device__ __align__(16) __nv_bfloat16 g_ks_hi[B_*L_*D_];
__device__ __align__(16) __nv_bfloat16 g_ks_lo[B_*L_*D_];
__device__ __align__(16) __nv_bfloat16 g_vs_hi[B_*L_*D_];
__device__ __align__(16) __nv_bfloat16 g_vs_lo[B_*L_*D_];
// Wker permuted+padded: [h][n=0..511][d=0..63]
__device__ __align__(16) __nv_bfloat16 g_wker_hi[H_*WKN*DK_];
__device__ __align__(16) __nv_bfloat16 g_wker_lo[H_*WKN*DK_];
// bf16 hi/lo operands for the logits GEMM (compact stride 448)
__device__ __align__(16) __nv_bfloat16 g_qcat_hi[(size_t)B_*H_*L_*NCAT];
__device__ __align__(16) __nv_bfloat16 g_qcat_lo[(size_t)B_*H_*L_*NCAT];
__device__ __align__(16) __nv_bfloat16 g_kcat_hi[(size_t)B_*H_*L_*NCAT];
__device__ __align__(16) __nv_bfloat16 g_kcat_lo[(size_t)B_*H_*L_*NCAT];
// projection inputs (bf16 split)
__device__ __align__(16) __nv_bfloat16 g_inq_hi[B_*L_*D_];
__device__ __align__(16) __nv_bfloat16 g_inq_lo[B_*L_*D_];
__device__ __align__(16) __nv_bfloat16 g_ink_hi[B_*L_*D_];
__device__ __align__(16) __nv_bfloat16 g_ink_lo[B_*L_*D_];
__device__ __align__(16) __nv_bfloat16 g_inv_hi[B_*L_*D_];
__device__ __align__(16) __nv_bfloat16 g_inv_lo[B_*L_*D_];
// weights (bf16 split): slots 0=Wq 1=Wk 2=Wv 3=Wproj
__device__ __align__(16) __nv_bfloat16 g_w_hi[4*D_*D_];
__device__ __align__(16) __nv_bfloat16 g_w_lo[4*D_*D_];
// v transposed per head: [z][n=0..63][k=0..1023]
__device__ __align__(16) __nv_bfloat16 g_vt_hi[(size_t)B_*H_*DK_*L_];
__device__ __align__(16) __nv_bfloat16 g_vt_lo[(size_t)B_*H_*DK_*L_];
// ctx in bf16 split, layout [B*L, 512]
__device__ __align__(16) __nv_bfloat16 g_ctx_hi[B_*L_*D_];
__device__ __align__(16) __nv_bfloat16 g_ctx_lo[B_*L_*D_];

// ====================== baseline-PTX tensor helpers ========================
static __device__ __forceinline__ uint32_t smem_u32(const void* p){
    uint32_t a;
    asm("{ .reg .u64 t; cvta.to.shared.u64 t, %1; cvt.u32.u64 %0, t; }"
        : "=r"(a) : "l"(p));
    return a;
}
#define CP_ASYNC16(dst, src) \
    asm volatile("cp.async.cg.shared.global [%0], [%1], 16;" \
                 :: "r"(dst), "l"(src) : "memory")
#define CP_COMMIT() asm volatile("cp.async.commit_group;" ::: "memory")
#define CP_WAIT(n)  asm volatile("cp.async.wait_group %0;" :: "n"(n) : "memory")
#define LDSM4(r0, r1, r2, r3, addr) \
    asm volatile("ldmatrix.sync.aligned.m8n8.x4.shared.b16 {%0,%1,%2,%3}, [%4];" \
                 : "=r"(r0), "=r"(r1), "=r"(r2), "=r"(r3) : "r"(addr))
#define MMA16816(d, a, b) \
    asm volatile("mma.sync.aligned.m16n8k16.row.col.f32.bf16.bf16.f32 " \
                 "{%0,%1,%2,%3},{%4,%5,%6,%7},{%8,%9},{%0,%1,%2,%3};" \
                 : "+f"((d)[0]), "+f"((d)[1]), "+f"((d)[2]), "+f"((d)[3]) \
                 : "r"((a)[0]), "r"((a)[1]), "r"((a)[2]), "r"((a)[3]), \
                   "r"((b)[0]), "r"((b)[1]))

static __device__ __forceinline__ unsigned pk2(float a, float b){
    __nv_bfloat162 t = __floats2bfloat162_rn(a, b);
    return *reinterpret_cast<unsigned*>(&t);
}
static __device__ __forceinline__ float bhi(float x){
    return __bfloat162float(__float2bfloat16_rn(x));
}

// ---------------------------------------------------------------------------
// conv_split3: fp32 -> bf16 hi/lo for q,k,v inputs in one launch (y = slot)
// ---------------------------------------------------------------------------
__global__ __launch_bounds__(256) void conv_split3_kernel(
    const float* __restrict__ s0, const float* __restrict__ s1,
    const float* __restrict__ s2, int n8)
{
    int i = blockIdx.x * 256 + threadIdx.x;
    if (i >= n8) return;
    const float* src; __nv_bfloat16 *dh, *dl;
    if (blockIdx.y == 0)      { src = s0; dh = g_inq_hi; dl = g_inq_lo; }
    else if (blockIdx.y == 1) { src = s1; dh = g_ink_hi; dl = g_ink_lo; }
    else                      { src = s2; dh = g_inv_hi; dl = g_inv_lo; }
    const float4* s = (const float4*)(src + (size_t)i * 8);
    float4 v0 = s[0], v1 = s[1];
    float f[8] = {v0.x, v0.y, v0.z, v0.w, v1.x, v1.y, v1.z, v1.w};
    float hh[8], ll[8];
#pragma unroll
    for (int e = 0; e < 8; e++) { hh[e] = bhi(f[e]); ll[e] = f[e] - hh[e]; }
    *(uint4*)(dh + (size_t)i * 8) = make_uint4(pk2(hh[0],hh[1]), pk2(hh[2],hh[3]),
                                               pk2(hh[4],hh[5]), pk2(hh[6],hh[7]));
    *(uint4*)(dl + (size_t)i * 8) = make_uint4(pk2(ll[0],ll[1]), pk2(ll[2],ll[3]),
                                               pk2(ll[4],ll[5]), pk2(ll[6],ll[7]));
}

// conv_split4: the 4 weight matrices into g_w slots (y = slot)
__global__ __launch_bounds__(256) void conv_split4_kernel(
    const float* __restrict__ s0, const float* __restrict__ s1,
    const float* __restrict__ s2, const float* __restrict__ s3, int n8)
{
    int i = blockIdx.x * 256 + threadIdx.x;
    if (i >= n8) return;
    const float* srcs[4] = {s0, s1, s2, s3};
    const float* src = srcs[blockIdx.y];
    size_t slot = (size_t)blockIdx.y * D_ * D_;
    const float4* s = (const float4*)(src + (size_t)i * 8);
    float4 v0 = s[0], v1 = s[1];
    float f[8] = {v0.x, v0.y, v0.z, v0.w, v1.x, v1.y, v1.z, v1.w};
    float hh[8], ll[8];
#pragma unroll
    for (int e = 0; e < 8; e++) { hh[e] = bhi(f[e]); ll[e] = f[e] - hh[e]; }
    *(uint4*)(g_w_hi + slot + (size_t)i * 8) =
        make_uint4(pk2(hh[0],hh[1]), pk2(hh[2],hh[3]),
                   pk2(hh[4],hh[5]), pk2(hh[6],hh[7]));
    *(uint4*)(g_w_lo + slot + (size_t)i * 8) =
        make_uint4(pk2(ll[0],ll[1]), pk2(ll[2],ll[3]),
                   pk2(ll[4],ll[5]), pk2(ll[6],ll[7]));
}

// ---------------------------------------------------------------------------
// wker_prep: g_wker[h][n][d] = Wker[h, n&63, n>>6, d] for n<448 else 0
// ---------------------------------------------------------------------------
__global__ __launch_bounds__(256) void wker_prep_kernel(const float* __restrict__ Wker)
{
    int idx = blockIdx.x * 256 + threadIdx.x;      // over 8*512*8
    if (idx >= H_ * WKN * 8) return;
    int d8 = (idx & 7) * 8;
    int n  = (idx >> 3) & (WKN - 1);
    int h  = idx >> 12;
    float f[8] = {0,0,0,0,0,0,0,0};
    if (n < NCAT) {
        int t = n >> 6, c = n & 63;
        const float* src = Wker + (((size_t)(h*DK_ + c)) * KW_ + t) * DK_ + d8;
        float4 v0 = *(const float4*)src, v1 = *(const float4*)(src + 4);
        f[0]=v0.x; f[1]=v0.y; f[2]=v0.z; f[3]=v0.w;
        f[4]=v1.x; f[5]=v1.y; f[6]=v1.z; f[7]=v1.w;
    }
    float hh[8], ll[8];
#pragma unroll
    for (int e = 0; e < 8; e++) { hh[e] = bhi(f[e]); ll[e] = f[e] - hh[e]; }
    size_t off = ((size_t)h * WKN + n) * DK_ + d8;
    *(uint4*)(g_wker_hi + off) = make_uint4(pk2(hh[0],hh[1]), pk2(hh[2],hh[3]),
                                            pk2(hh[4],hh[5]), pk2(hh[6],hh[7]));
    *(uint4*)(g_wker_lo + off) = make_uint4(pk2(ll[0],ll[1]), pk2(ll[2],ll[3]),
                                            pk2(ll[4],ll[5]), pk2(ll[6],ll[7]));
}

// ---------------------------------------------------------------------------
// bcat[h, n] = bker[h, n&63, n>>6] for n<448 else 0   (padded to 512)
// ---------------------------------------------------------------------------
__global__ void bcat_kernel(const float* __restrict__ bker)
{
    int n = blockIdx.x * blockDim.x + threadIdx.x;
    if (n >= H_ * WKN) return;
    int h = n >> 9, r = n & (WKN - 1), t = r >> 6, c = r & 63;
    g_bcat[n] = (r < NCAT) ? bker[(size_t)(h*DK_ + c) * KW_ + t] : 0.f;
}

// ---------------------------------------------------------------------------
// 2-stage mma GEMM pieces (tile 128x128, 8 warps 2x4) -- R11-proven config
// ---------------------------------------------------------------------------
#define GM_STAGE 32768
#define GM_SMEM  (2*GM_STAGE)

// ---------------------------------------------------------------------------
// out-projection GEMM: C[M,N] fp32 = A@B^T + bias[N].  2-stage.  2 CTAs/SM.
// ---------------------------------------------------------------------------
__global__ __launch_bounds__(256, 2) void gemm_mma_nt(
    const __nv_bfloat16* __restrict__ Ah, const __nv_bfloat16* __restrict__ Al,
    const __nv_bfloat16* __restrict__ Bh, const __nv_bfloat16* __restrict__ Bl,
    const float* __restrict__ bias, float* __restrict__ C, int K, int N)
{
    extern __shared__ char smem[];
    const uint32_t sbase = smem_u32(smem);
    const int kc = K >> 5;

    const int tid  = threadIdx.x;
    const int wid  = tid >> 5, lane = tid & 31;
    const int wm   = wid >> 2, wn = wid & 3;

    const int i0 = blockIdx.y * 128;
    const int j0 = blockIdx.x * 128;

    const __nv_bfloat16* ah = Ah + (size_t)i0 * K;
    const __nv_bfloat16* al = Al + (size_t)i0 * K;
    const __nv_bfloat16* bh_ = Bh + (size_t)j0 * K;
    const __nv_bfloat16* bl_ = Bl + (size_t)j0 * K;

    auto issue = [&](int s, int c) {
        const uint32_t sb = sbase + s * GM_STAGE;
#pragma unroll
        for (int q = 0; q < 4; q++) {
            int u  = q * 256 + tid;
            int r  = u >> 3, cj = u & 7;
            const __nv_bfloat16* src =
                (cj < 4 ? ah : al) + (size_t)r * K + c * 32 + (cj & 3) * 8;
            CP_ASYNC16(sb + r * 128 + 16 * (cj ^ (r & 7)), src);
        }
#pragma unroll
        for (int q = 0; q < 4; q++) {
            int u  = q * 256 + tid;
            int r  = u >> 3, cj = u & 7;
            const __nv_bfloat16* src =
                (cj < 4 ? bh_ : bl_) + (size_t)r * K + c * 32 + (cj & 3) * 8;
            CP_ASYNC16(sb + 16384 + r * 128 + 16 * (cj ^ (r & 7)), src);
        }
    };

    float acc[4][4][4];
#pragma unroll
    for (int i = 0; i < 4; i++)
#pragma unroll
        for (int j = 0; j < 4; j++)
#pragma unroll
            for (int e = 0; e < 4; e++) acc[i][j][e] = 0.f;

    issue(0, 0);
    CP_COMMIT();

    const int lrow = (lane & 7) + 8 * ((lane >> 3) & 1);
    const int lchk = lane >> 4;

    for (int c = 0; c < kc; c++) {
        const int s = c & 1;
        if (c + 1 < kc) { issue(s ^ 1, c + 1); CP_COMMIT(); CP_WAIT(1); }
        else            { CP_WAIT(0); }
        __syncthreads();

        const uint32_t sA = sbase + s * GM_STAGE;
        const uint32_t sB = sA + 16384;

#pragma unroll
        for (int ks = 0; ks < 2; ks++) {
            uint32_t bh[4][2], bl[4][2];
#pragma unroll
            for (int g = 0; g < 2; g++) {
                int r  = wn * 32 + g * 16 + lrow;
                int ch = ks * 2 + lchk;
                uint32_t r0, r1, r2, r3;
                LDSM4(r0, r1, r2, r3, sB + r * 128 + 16 * ((ch)     ^ (r & 7)));
                bh[2*g][0] = r0; bh[2*g][1] = r2;
                bh[2*g+1][0] = r1; bh[2*g+1][1] = r3;
                LDSM4(r0, r1, r2, r3, sB + r * 128 + 16 * ((ch + 4) ^ (r & 7)));
                bl[2*g][0] = r0; bl[2*g][1] = r2;
                bl[2*g+1][0] = r1; bl[2*g+1][1] = r3;
            }
#pragma unroll
            for (int mf = 0; mf < 4; mf++) {
                int r  = wm * 64 + mf * 16 + lrow;
                int ch = ks * 2 + lchk;
                uint32_t ah_[4], al_[4];
                LDSM4(ah_[0], ah_[1], ah_[2], ah_[3],
                      sA + r * 128 + 16 * ((ch)     ^ (r & 7)));
                LDSM4(al_[0], al_[1], al_[2], al_[3],
                      sA + r * 128 + 16 * ((ch + 4) ^ (r & 7)));
#pragma unroll
                for (int nf = 0; nf < 4; nf++) {
                    MMA16816(acc[mf][nf], ah_, bh[nf]);
                    MMA16816(acc[mf][nf], ah_, bl[nf]);
                    MMA16816(acc[mf][nf], al_, bh[nf]);
                }
            }
        }
        __syncthreads();
    }

    const int rbase = i0 + wm * 64 + (lane >> 2);
    const int cbase = j0 + wn * 32 + 2 * (lane & 3);
#pragma unroll
    for (int mf = 0; mf < 4; mf++) {
        int gi = rbase + mf * 16;
        float* row0 = C + (size_t)gi * N;
        float* row1 = row0 + 8 * N;
#pragma unroll
        for (int nf = 0; nf < 4; nf++) {
            int gj = cbase + nf * 8;
            float b0 = bias[gj], b1 = bias[gj + 1];
            *(float2*)(row0 + gj) = make_float2(acc[mf][nf][0] + b0,
                                                acc[mf][nf][1] + b1);
            *(float2*)(row1 + gj) = make_float2(acc[mf][nf][2] + b0,
                                                acc[mf][nf][3] + b1);
        }
    }
}

// ---------------------------------------------------------------------------
// projection GEMM writing bf16 hi/lo ONLY.  K = N = 512, 16 chunks, 2-stage.
// Used for q, k, v projections.
// ---------------------------------------------------------------------------
__global__ __launch_bounds__(256, 2) void gemm_mma_split(
    const __nv_bfloat16* __restrict__ Ah, const __nv_bfloat16* __restrict__ Al,
    const __nv_bfloat16* __restrict__ Bh, const __nv_bfloat16* __restrict__ Bl,
    const float* __restrict__ bias,
    __nv_bfloat16* __restrict__ Ch, __nv_bfloat16* __restrict__ Cl)
{
    extern __shared__ char smem[];
    const uint32_t sbase = smem_u32(smem);
    const int K = D_;

    const int tid  = threadIdx.x;
    const int wid  = tid >> 5, lane = tid & 31;
    const int wm   = wid >> 2, wn = wid & 3;

    const int i0 = blockIdx.y * 128;
    const int j0 = blockIdx.x * 128;

    const __nv_bfloat16* ah = Ah + (size_t)i0 * K;
    const __nv_bfloat16* al = Al + (size_t)i0 * K;
    const __nv_bfloat16* bh_ = Bh + (size_t)j0 * K;
    const __nv_bfloat16* bl_ = Bl + (size_t)j0 * K;

    auto issue = [&](int s, int c) {
        const uint32_t sb = sbase + s * GM_STAGE;
#pragma unroll
        for (int q = 0; q < 4; q++) {
            int u  = q * 256 + tid;
            int r  = u >> 3, cj = u & 7;
            const __nv_bfloat16* src =
                (cj < 4 ? ah : al) + (size_t)r * K + c * 32 + (cj & 3) * 8;
            CP_ASYNC16(sb + r * 128 + 16 * (cj ^ (r & 7)), src);
        }
#pragma unroll
        for (int q = 0; q < 4; q++) {
            int u  = q * 256 + tid;
            int r  = u >> 3, cj = u & 7;
            const __nv_bfloat16* src =
                (cj < 4 ? bh_ : bl_) + (size_t)r * K + c * 32 + (cj & 3) * 8;
            CP_ASYNC16(sb + 16384 + r * 128 + 16 * (cj ^ (r & 7)), src);
        }
    };

    float acc[4][4][4];
#pragma unroll
    for (int i = 0; i < 4; i++)
#pragma unroll
        for (int j = 0; j < 4; j++)
#pragma unroll
            for (int e = 0; e < 4; e++) acc[i][j][e] = 0.f;

    issue(0, 0);
    CP_COMMIT();

    const int lrow = (lane & 7) + 8 * ((lane >> 3) & 1);
    const int lchk = lane >> 4;

    for (int c = 0; c < 16; c++) {
        const int s = c & 1;
        if (c + 1 < 16) { issue(s ^ 1, c + 1); CP_COMMIT(); CP_WAIT(1); }
        else            { CP_WAIT(0); }
        __syncthreads();

        const uint32_t sA = sbase + s * GM_STAGE;
        const uint32_t sB = sA + 16384;

#pragma unroll
        for (int ks = 0; ks < 2; ks++) {
            uint32_t bh[4][2], bl[4][2];
#pragma unroll
            for (int g = 0; g < 2; g++) {
                int r  = wn * 32 + g * 16 + lrow;
                int ch = ks * 2 + lchk;
                uint32_t r0, r1, r2, r3;
                LDSM4(r0, r1, r2, r3, sB + r * 128 + 16 * ((ch)     ^ (r & 7)));
                bh[2*g][0] = r0; bh[2*g][1] = r2;
                bh[2*g+1][0] = r1; bh[2*g+1][1] = r3;
                LDSM4(r0, r1, r2, r3, sB + r * 128 + 16 * ((ch + 4) ^ (r & 7)));
                bl[2*g][0] = r0; bl[2*g][1] = r2;
                bl[2*g+1][0] = r1; bl[2*g+1][1] = r3;
            }
#pragma unroll
            for (int mf = 0; mf < 4; mf++) {
                int r  = wm * 64 + mf * 16 + lrow;
                int ch = ks * 2 + lchk;
                uint32_t ah_[4], al_[4];
                LDSM4(ah_[0], ah_[1], ah_[2], ah_[3],
                      sA + r * 128 + 16 * ((ch)     ^ (r & 7)));
                LDSM4(al_[0], al_[1], al_[2], al_[3],
                      sA + r * 128 + 16 * ((ch + 4) ^ (r & 7)));
#pragma unroll
                for (int nf = 0; nf < 4; nf++) {
                    MMA16816(acc[mf][nf], ah_, bh[nf]);
                    MMA16816(acc[mf][nf], ah_, bl[nf]);
                    MMA16816(acc[mf][nf], al_, bh[nf]);
                }
            }
        }
        __syncthreads();
    }

    const int rbase = i0 + wm * 64 + (lane >> 2);
    const int cbase = j0 + wn * 32 + 2 * (lane & 3);
#pragma unroll
    for (int mf = 0; mf < 4; mf++) {
        int gi = rbase + mf * 16;
        size_t ro0 = (size_t)gi * D_, ro1 = ro0 + 8 * D_;
#pragma unroll
        for (int nf = 0; nf < 4; nf++) {
            int gj = cbase + nf * 8;
            float b0 = bias[gj], b1 = bias[gj + 1];
            float v0 = acc[mf][nf][0] + b0, v1 = acc[mf][nf][1] + b1;
            float v2 = acc[mf][nf][2] + b0, v3 = acc[mf][nf][3] + b1;
            float h0 = bhi(v0), h1 = bhi(v1), h2 = bhi(v2), h3 = bhi(v3);
            *(unsigned*)(Ch + ro0 + gj) = pk2(h0, h1);
            *(unsigned*)(Cl + ro0 + gj) = pk2(v0 - h0, v1 - h1);
            *(unsigned*)(Ch + ro1 + gj) = pk2(h2, h3);
            *(unsigned*)(Cl + ro1 + gj) = pk2(v2 - h2, v3 - h3);
        }
    }
}

// ---------------------------------------------------------------------------
// qcat via mma: per z: Qcat[1024, n<448] = q_s_head[1024,64] @ wker[512,64]^T
//   + bcat. K=64 -> 2 chunks.  grid (4, 8, 64).  compact stride 448.
// ---------------------------------------------------------------------------
__global__ __launch_bounds__(256, 2) void qcat_mma_kernel()
{
    __shared__ char smem[2 * GM_STAGE];
    const uint32_t sbase = smem_u32(smem);

    const int tid  = threadIdx.x;
    const int wid  = tid >> 5, lane = tid & 31;
    const int wm   = wid >> 2, wn = wid & 3;

    const int z  = blockIdx.z;
    const int b = z >> 3, h = z & 7;
    const int i0 = blockIdx.y * 128;
    const int n0 = blockIdx.x * 128;

    const __nv_bfloat16* ah = g_qs_hi + ((size_t)(b*L_ + i0)) * D_ + h*DK_;
    const __nv_bfloat16* al = g_qs_lo + ((size_t)(b*L_ + i0)) * D_ + h*DK_;
    const __nv_bfloat16* bh_ = g_wker_hi + ((size_t)h * WKN + n0) * DK_;
    const __nv_bfloat16* bl_ = g_wker_lo + ((size_t)h * WKN + n0) * DK_;

    auto issue = [&](int s, int c) {
        const uint32_t sb = sbase + s * GM_STAGE;
#pragma unroll
        for (int q = 0; q < 4; q++) {
            int u  = q * 256 + tid;
            int r  = u >> 3, cj = u & 7;
            const __nv_bfloat16* src =
                (cj < 4 ? ah : al) + (size_t)r * D_ + c * 32 + (cj & 3) * 8;
            CP_ASYNC16(sb + r * 128 + 16 * (cj ^ (r & 7)), src);
        }
#pragma unroll
        for (int q = 0; q < 4; q++) {
            int u  = q * 256 + tid;
            int r  = u >> 3, cj = u & 7;
            const __nv_bfloat16* src =
                (cj < 4 ? bh_ : bl_) + (size_t)r * DK_ + c * 32 + (cj & 3) * 8;
            CP_ASYNC16(sb + 16384 + r * 128 + 16 * (cj ^ (r & 7)), src);
        }
    };

    float acc[4][4][4];
#pragma unroll
    for (int i = 0; i < 4; i++)
#pragma unroll
        for (int j = 0; j < 4; j++)
#pragma unroll
            for (int e = 0; e < 4; e++) acc[i][j][e] = 0.f;

    issue(0, 0);
    CP_COMMIT();

    const int lrow = (lane & 7) + 8 * ((lane >> 3) & 1);
    const int lchk = lane >> 4;

    for (int c = 0; c < 2; c++) {
        const int s = c & 1;
        if (c == 0) { issue(1, 1); CP_COMMIT(); CP_WAIT(1); }
        else        { CP_WAIT(0); }
        __syncthreads();

        const uint32_t sA = sbase + s * GM_STAGE;
        const uint32_t sB = sA + 16384;

#pragma unroll
        for (int ks = 0; ks < 2; ks++) {
            uint32_t bh[4][2], bl[4][2];
#pragma unroll
            for (int g = 0; g < 2; g++) {
                int r  = wn * 32 + g * 16 + lrow;
                int ch = ks * 2 + lchk;
                uint32_t r0, r1, r2, r3;
                LDSM4(r0, r1, r2, r3, sB + r * 128 + 16 * ((ch)     ^ (r & 7)));
                bh[2*g][0] = r0; bh[2*g][1] = r2;
                bh[2*g+1][0] = r1; bh[2*g+1][1] = r3;
                LDSM4(r0, r1, r2, r3, sB + r * 128 + 16 * ((ch + 4) ^ (r & 7)));
                bl[2*g][0] = r0; bl[2*g][1] = r2;
                bl[2*g+1][0] = r1; bl[2*g+1][1] = r3;
            }
#pragma unroll
            for (int mf = 0; mf < 4; mf++) {
                int r  = wm * 64 + mf * 16 + lrow;
                int ch = ks * 2 + lchk;
                uint32_t ah_[4], al_[4];
                LDSM4(ah_[0], ah_[1], ah_[2], ah_[3],
                      sA + r * 128 + 16 * ((ch)     ^ (r & 7)));
                LDSM4(al_[0], al_[1], al_[2], al_[3],
                      sA + r * 128 + 16 * ((ch + 4) ^ (r & 7)));
#pragma unroll
                for (int nf = 0; nf < 4; nf++) {
                    MMA16816(acc[mf][nf], ah_, bh[nf]);
                    MMA16816(acc[mf][nf], ah_, bl[nf]);
                    MMA16816(acc[mf][nf], al_, bh[nf]);
                }
            }
        }
        __syncthreads();
    }

    __nv_bfloat16* Ch = g_qcat_hi + (size_t)z * L_ * NCAT;
    __nv_bfloat16* Cl = g_qcat_lo + (size_t)z * L_ * NCAT;
    const int rbase = i0 + wm * 64 + (lane >> 2);
    const int cbase = n0 + wn * 32 + 2 * (lane & 3);
#pragma unroll
    for (int mf = 0; mf < 4; mf++) {
        int gi = rbase + mf * 16;
        size_t ro0 = (size_t)gi * NCAT, ro1 = ro0 + 8 * NCAT;
#pragma unroll
        for (int nf = 0; nf < 4; nf++) {
            int gj = cbase + nf * 8;
            if (gj >= NCAT) continue;
            float b0 = g_bcat[h*WKN + gj], b1 = g_bcat[h*WKN + gj + 1];
            float v0 = acc[mf][nf][0] + b0, v1 = acc[mf][nf][1] + b1;
            float v2 = acc[mf][nf][2] + b0, v3 = acc[mf][nf][3] + b1;
            float h0 = bhi(v0), h1 = bhi(v1), h2 = bhi(v2), h3 = bhi(v3);
            *(unsigned*)(Ch + ro0 + gj) = pk2(h0, h1);
            *(unsigned*)(Cl + ro0 + gj) = pk2(v0 - h0, v1 - h1);
            *(unsigned*)(Ch + ro1 + gj) = pk2(h2, h3);
            *(unsigned*)(Cl + ro1 + gj) = pk2(v2 - h2, v3 - h3);
        }
    }
}

// ---------------------------------------------------------------------------
// Kcat prep: pure shifted copy of pre-split k_s.
//   Kcat[z][j][t*64+c] = ks_{hi,lo}[b*L + j+t-3][h*64+c]   (0 outside range)
// ---------------------------------------------------------------------------
__global__ __launch_bounds__(256) void kcat_prep_kernel()
{
    int idx = blockIdx.x * 256 + threadIdx.x;
    if (idx >= B_*H_*L_*(NCAT/8)) return;
    int c8 = idx % (NCAT/8);
    int rest = idx / (NCAT/8);
    int j = rest & (L_-1);
    int z = rest >> 10;
    int b = z >> 3, h = z & 7;
    int cpos = c8 * 8;
    int t = cpos >> 6, cc = cpos & 63;
    int src = j + t - PAD_;
    uint4 vh = make_uint4(0,0,0,0), vl = make_uint4(0,0,0,0);
    if (src >= 0 && src < L_) {
        size_t so = ((size_t)(b*L_ + src)) * D_ + h*DK_ + cc;
        vh = *(const uint4*)(g_ks_hi + so);
        vl = *(const uint4*)(g_ks_lo + so);
    }
    size_t off = (size_t)z * L_ * NCAT + (size_t)j * NCAT + cpos;
    *(uint4*)(g_kcat_hi + off) = vh;
    *(uint4*)(g_kcat_lo + off) = vl;
}

// ---------------------------------------------------------------------------
// vt transpose (bf16): vt[z][n][k] = v_s[b][k][h*64+n], hi/lo packed in smem.
// ---------------------------------------------------------------------------
__global__ __launch_bounds__(256) void vt_kernel()
{
    __shared__ uint32_t t[128][65];   // hi | lo<<16 per element
    const int z = blockIdx.y;
    const int b = z >> 3, h = z & 7;
    const int k0 = blockIdx.x * 128;
    const int tid = threadIdx.x;

#pragma unroll
    for (int q = 0; q < 4; q++) {          // 1024 units of 8 elems
        int u = q * 256 + tid;
        int r = u >> 3, c8 = (u & 7) * 8;
        size_t so = ((size_t)(b*L_ + k0 + r)) * D_ + h*DK_ + c8;
        uint4 vh = *(const uint4*)(g_vs_hi + so);
        uint4 vl = *(const uint4*)(g_vs_lo + so);
        uint32_t hw[4] = {vh.x, vh.y, vh.z, vh.w};
        uint32_t lw[4] = {vl.x, vl.y, vl.z, vl.w};
#pragma unroll
        for (int e = 0; e < 4; e++) {
            t[r][c8 + 2*e]     = (hw[e] & 0xffffu) | (lw[e] << 16);
            t[r][c8 + 2*e + 1] = (hw[e] >> 16)     | (lw[e] & 0xffff0000u);
        }
    }
    __syncthreads();

#pragma unroll
    for (int q = 0; q < 4; q++) {          // 64 n x 16 k-groups of 8
        int u = q * 256 + tid;
        int n = u >> 4, k8 = (u & 15) * 8;
        uint32_t hi4[4], lo4[4];
#pragma unroll
        for (int e = 0; e < 4; e++) {
            uint32_t a = t[k8 + 2*e][n];
            uint32_t c = t[k8 + 2*e + 1][n];
            hi4[e] = (a & 0xffffu) | ((c & 0xffffu) << 16);
            lo4[e] = (a >> 16)     | (c & 0xffff0000u);
        }
        size_t off = (size_t)z * DK_ * L_ + (size_t)n * L_ + k0 + k8;
        *(uint4*)(g_vt_hi + off) = make_uint4(hi4[0], hi4[1], hi4[2], hi4[3]);
        *(uint4*)(g_vt_lo + off) = make_uint4(lo4[0], lo4[1], lo4[2], lo4[3]);
    }
}

// ---------------------------------------------------------------------------
// Logits: 128x128 tile, K=448 in 14 chunks, A=Qcat B=Kcat, 3-stage pipeline.
// No rowbias (cancels in softmax).  grid (8, 8, 64).  2 CTAs/SM.
// ---------------------------------------------------------------------------
#define LOG_STAGE 32768
#define LOG_SMEM  (3*LOG_STAGE)

__global__ __launch_bounds__(256, 2) void logits_mma_kernel(float* __restrict__ attn)
{
    extern __shared__ char smem[];
    const uint32_t sbase = smem_u32(smem);

    const int tid  = threadIdx.x;
    const int wid  = tid >> 5, lane = tid & 31;
    const int wm   = wid >> 2, wn = wid & 3;

    const int z  = blockIdx.z;
    const int i0 = blockIdx.y * 128;
    const int j0 = blockIdx.x * 128;

    const __nv_bfloat16* qh = g_qcat_hi + (size_t)z * L_ * NCAT + (size_t)i0 * NCAT;
    const __nv_bfloat16* ql = g_qcat_lo + (size_t)z * L_ * NCAT + (size_t)i0 * NCAT;
    const __nv_bfloat16* kh = g_kcat_hi + (size_t)z * L_ * NCAT + (size_t)j0 * NCAT;
    const __nv_bfloat16* kl = g_kcat_lo + (size_t)z * L_ * NCAT + (size_t)j0 * NCAT;

    auto issue = [&](int s, int c) {
        const uint32_t sb = sbase + s * LOG_STAGE;
#pragma unroll
        for (int q = 0; q < 4; q++) {
            int u  = q * 256 + tid;
            int r  = u >> 3, cj = u & 7;
            const __nv_bfloat16* src =
                (cj < 4 ? qh : ql) + (size_t)r * NCAT + c * 32 + (cj & 3) * 8;
            CP_ASYNC16(sb + r * 128 + 16 * (cj ^ (r & 7)), src);
        }
#pragma unroll
        for (int q = 0; q < 4; q++) {
            int u  = q * 256 + tid;
            int r  = u >> 3, cj = u & 7;
            const __nv_bfloat16* src =
                (cj < 4 ? kh : kl) + (size_t)r * NCAT + c * 32 + (cj & 3) * 8;
            CP_ASYNC16(sb + 16384 + r * 128 + 16 * (cj ^ (r & 7)), src);
        }
    };

    float acc[4][4][4];
#pragma unroll
    for (int i = 0; i < 4; i++)
#pragma unroll
        for (int j = 0; j < 4; j++)
#pragma unroll
            for (int e = 0; e < 4; e++) acc[i][j][e] = 0.f;

    issue(0, 0); CP_COMMIT();
    issue(1, 1); CP_COMMIT();

    const int lrow = (lane & 7) + 8 * ((lane >> 3) & 1);
    const int lchk = lane >> 4;

    int stage = 0;
    for (int c = 0; c < 14; c++) {
        if (c + 2 < 14) {
            int s2 = stage + 2; if (s2 >= 3) s2 -= 3;
            issue(s2, c + 2); CP_COMMIT(); CP_WAIT(2);
        } else if (c + 1 < 14) { CP_WAIT(1); }
        else                   { CP_WAIT(0); }
        __syncthreads();

        const uint32_t sA = sbase + stage * LOG_STAGE;
        const uint32_t sB = sA + 16384;

#pragma unroll
        for (int ks = 0; ks < 2; ks++) {
            uint32_t bh[4][2], bl[4][2];
#pragma unroll
            for (int g = 0; g < 2; g++) {
                int r  = wn * 32 + g * 16 + lrow;
                int ch = ks * 2 + lchk;
                uint32_t r0, r1, r2, r3;
                LDSM4(r0, r1, r2, r3, sB + r * 128 + 16 * ((ch)     ^ (r & 7)));
                bh[2*g][0] = r0; bh[2*g][1] = r2;
                bh[2*g+1][0] = r1; bh[2*g+1][1] = r3;
                LDSM4(r0, r1, r2, r3, sB + r * 128 + 16 * ((ch + 4) ^ (r & 7)));
                bl[2*g][0] = r0; bl[2*g][1] = r2;
                bl[2*g+1][0] = r1; bl[2*g+1][1] = r3;
            }
#pragma unroll
            for (int mf = 0; mf < 4; mf++) {
                int r  = wm * 64 + mf * 16 + lrow;
                int ch = ks * 2 + lchk;
                uint32_t ah[4], al[4];
                LDSM4(ah[0], ah[1], ah[2], ah[3],
                      sA + r * 128 + 16 * ((ch)     ^ (r & 7)));
                LDSM4(al[0], al[1], al[2], al[3],
                      sA + r * 128 + 16 * ((ch + 4) ^ (r & 7)));
#pragma unroll
                for (int nf = 0; nf < 4; nf++) {
                    MMA16816(acc[mf][nf], ah, bh[nf]);
                    MMA16816(acc[mf][nf], ah, bl[nf]);
                    MMA16816(acc[mf][nf], al, bh[nf]);
                }
            }
        }
        __syncthreads();
        stage++; if (stage == 3) stage = 0;
    }

    const int rbase = i0 + wm * 64 + (lane >> 2);
    const int cbase = j0 + wn * 32 + 2 * (lane & 3);
#pragma unroll
    for (int mf = 0; mf < 4; mf++) {
        int gi0 = rbase + mf * 16;
        float* row0 = attn + ((size_t)z * L_ + gi0) * L_;
        float* row1 = row0 + 8 * L_;
#pragma unroll
        for (int nf = 0; nf < 4; nf++) {
            int gj = cbase + nf * 8;
            *(float2*)(row0 + gj) = make_float2(acc[mf][nf][0]*0.125f,
                                                acc[mf][nf][1]*0.125f);
            *(float2*)(row1 + gj) = make_float2(acc[mf][nf][2]*0.125f,
                                                acc[mf][nf][3]*0.125f);
        }
    }
}

// ---------------------------------------------------------------------------
// Row softmax in-place on attn; mask; head-0 duplicate.
// ---------------------------------------------------------------------------
__global__ __launch_bounds__(256) void softmax_kernel(
    float* __restrict__ attn, const unsigned char* __restrict__ mask,
    float* __restrict__ one_head)
{
    const int r = blockIdx.x;
    const int i = r & (L_-1);
    const int bh = r >> 10;
    const int h = bh & (H_-1), b = bh >> 3;
    float* row = attn + (size_t)r * L_;
    const unsigned char* mrow = mask + ((size_t)(b*L_ + i)) * L_;
    const int t4 = threadIdx.x * 4;

    float4 v = *(const float4*)(row + t4);
    uchar4 m = *(const uchar4*)(mrow + t4);
    float x0 = m.x ? -INFINITY : v.x;
    float x1 = m.y ? -INFINITY : v.y;
    float x2 = m.z ? -INFINITY : v.z;
    float x3 = m.w ? -INFINITY : v.w;

    __shared__ float sm[8], ss[8];
    float mx = fmaxf(fmaxf(x0, x1), fmaxf(x2, x3));
#pragma unroll
    for (int o = 16; o; o >>= 1) mx = fmaxf(mx, __shfl_xor_sync(0xffffffffu, mx, o));
    if ((threadIdx.x & 31) == 0) sm[threadIdx.x >> 5] = mx;
    __syncthreads();
    if (threadIdx.x < 32) {
        float t = (threadIdx.x < 8) ? sm[threadIdx.x] : -INFINITY;
#pragma unroll
        for (int o = 4; o; o >>= 1) t = fmaxf(t, __shfl_xor_sync(0xffffffffu, t, o));
        if (threadIdx.x == 0) sm[0] = t;
    }
    __syncthreads();
    mx = sm[0];

    float e0 = __expf(x0 - mx), e1 = __expf(x1 - mx);
    float e2 = __expf(x2 - mx), e3 = __expf(x3 - mx);
    float s = (e0 + e1) + (e2 + e3);
#pragma unroll
    for (int o = 16; o; o >>= 1) s += __shfl_xor_sync(0xffffffffu, s, o);
    if ((threadIdx.x & 31) == 0) ss[threadIdx.x >> 5] = s;
    __syncthreads();
    if (threadIdx.x < 32) {
        float t = (threadIdx.x < 8) ? ss[threadIdx.x] : 0.f;
#pragma unroll
        for (int o = 4; o; o >>= 1) t += __shfl_xor_sync(0xffffffffu, t, o);
        if (threadIdx.x == 0) ss[0] = t;
    }
    __syncthreads();
    float inv = 1.0f / ss[0];

    float4 o = make_float4(e0*inv, e1*inv, e2*inv, e3*inv);
    *(float4*)(row + t4) = o;
    if (h == 0)
        *(float4*)(one_head + ((size_t)(b*L_ + i)) * L_ + t4) = o;
}

// ---------------------------------------------------------------------------
// ctx via mma: per (b,h): C[1024,64] = attn @ v_head.
// ---------------------------------------------------------------------------
#define CTX_STAGE 24576

__global__ __launch_bounds__(256, 2) void ctx_mma_kernel(const float* __restrict__ attn)
{
    __shared__ char smem[2 * CTX_STAGE];
    const uint32_t sbase = smem_u32(smem);

    const int tid  = threadIdx.x;
    const int wid  = tid >> 5, lane = tid & 31;
    const int wm   = wid >> 2, wn = wid & 3;

    const int z  = blockIdx.y;
    const int b = z >> 3, h = z & 7;
    const int i0 = blockIdx.x * 128;

    const float* A = attn + ((size_t)z * L_ + i0) * L_;
    const __nv_bfloat16* vh = g_vt_hi + (size_t)z * DK_ * L_;
    const __nv_bfloat16* vl = g_vt_lo + (size_t)z * DK_ * L_;

    auto issueB = [&](int s, int c) {
        const uint32_t sb = sbase + s * CTX_STAGE + 16384;
#pragma unroll
        for (int q = 0; q < 2; q++) {
            int u  = q * 256 + tid;
            int r  = u >> 3, cj = u & 7;
            const __nv_bfloat16* src =
                (cj < 4 ? vh : vl) + (size_t)r * L_ + c * 32 + (cj & 3) * 8;
            CP_ASYNC16(sb + r * 128 + 16 * (cj ^ (r & 7)), src);
        }
    };
    float fa[2][8];
    auto ldgA = [&](int c) {
#pragma unroll
        for (int q = 0; q < 2; q++) {
            int u = q * 256 + tid;
            int r = u >> 2, seg = u & 3;
            const float4* p = (const float4*)(A + (size_t)r * L_ + c * 32 + seg * 8);
            float4 v0 = p[0], v1 = p[1];
            fa[q][0]=v0.x; fa[q][1]=v0.y; fa[q][2]=v0.z; fa[q][3]=v0.w;
            fa[q][4]=v1.x; fa[q][5]=v1.y; fa[q][6]=v1.z; fa[q][7]=v1.w;
        }
    };
    auto stsA = [&](int s) {
#pragma unroll
        for (int q = 0; q < 2; q++) {
            int u = q * 256 + tid;
            int r = u >> 2, seg = u & 3;
            float hh[8], ll[8];
#pragma unroll
            for (int e = 0; e < 8; e++) { hh[e] = bhi(fa[q][e]); ll[e] = fa[q][e] - hh[e]; }
            *(uint4*)(smem + s * CTX_STAGE + r * 128 + 16 * ((seg)     ^ (r & 7))) =
                make_uint4(pk2(hh[0],hh[1]), pk2(hh[2],hh[3]),
                           pk2(hh[4],hh[5]), pk2(hh[6],hh[7]));
            *(uint4*)(smem + s * CTX_STAGE + r * 128 + 16 * ((seg + 4) ^ (r & 7))) =
                make_uint4(pk2(ll[0],ll[1]), pk2(ll[2],ll[3]),
                           pk2(ll[4],ll[5]), pk2(ll[6],ll[7]));
        }
    };

    float acc[4][2][4];
#pragma unroll
    for (int i = 0; i < 4; i++)
#pragma unroll
        for (int j = 0; j < 2; j++)
#pragma unroll
            for (int e = 0; e < 4; e++) acc[i][j][e] = 0.f;

    ldgA(0);
    issueB(0, 0); CP_COMMIT();

    const int lrow = (lane & 7) + 8 * ((lane >> 3) & 1);
    const int lchk = lane >> 4;

    for (int c = 0; c < 32; c++) {
        const int s = c & 1;
        stsA(s);
        if (c + 1 < 32) {
            ldgA(c + 1);
            issueB(s ^ 1, c + 1); CP_COMMIT(); CP_WAIT(1);
        } else {
            CP_WAIT(0);
        }
        __syncthreads();

        const uint32_t sA = sbase + s * CTX_STAGE;
        const uint32_t sB = sA + 16384;

#pragma unroll
        for (int ks = 0; ks < 2; ks++) {
            uint32_t bh[2][2], bl[2][2];
            {
                int r  = wn * 16 + lrow;
                int ch = ks * 2 + lchk;
                uint32_t r0, r1, r2, r3;
                LDSM4(r0, r1, r2, r3, sB + r * 128 + 16 * ((ch)     ^ (r & 7)));
                bh[0][0] = r0; bh[0][1] = r2; bh[1][0] = r1; bh[1][1] = r3;
                LDSM4(r0, r1, r2, r3, sB + r * 128 + 16 * ((ch + 4) ^ (r & 7)));
                bl[0][0] = r0; bl[0][1] = r2; bl[1][0] = r1; bl[1][1] = r3;
            }
#pragma unroll
            for (int mf = 0; mf < 4; mf++) {
                int r  = wm * 64 + mf * 16 + lrow;
                int ch = ks * 2 + lchk;
                uint32_t ah[4], al[4];
                LDSM4(ah[0], ah[1], ah[2], ah[3],
                      sA + r * 128 + 16 * ((ch)     ^ (r & 7)));
                LDSM4(al[0], al[1], al[2], al[3],
                      sA + r * 128 + 16 * ((ch + 4) ^ (r & 7)));
#pragma unroll
                for (int nf = 0; nf < 2; nf++) {
                    MMA16816(acc[mf][nf], ah, bh[nf]);
                    MMA16816(acc[mf][nf], ah, bl[nf]);
                    MMA16816(acc[mf][nf], al, bh[nf]);
                }
            }
        }
        __syncthreads();
    }

    const int rbase = i0 + wm * 64 + (lane >> 2);
    const int cb = h * DK_ + wn * 16 + 2 * (lane & 3);
#pragma unroll
    for (int mf = 0; mf < 4; mf++) {
        int gi = rbase + mf * 16;
        size_t ro0 = ((size_t)(b * L_) + gi) * D_;
        size_t ro1 = ro0 + 8 * D_;
#pragma unroll
        for (int nf = 0; nf < 2; nf++) {
            int gj = cb + nf * 8;
            float v0 = acc[mf][nf][0], v1 = acc[mf][nf][1];
            float v2 = acc[mf][nf][2], v3 = acc[mf][nf][3];
            float h0 = bhi(v0), h1 = bhi(v1), h2 = bhi(v2), h3 = bhi(v3);
            *(unsigned*)(g_ctx_hi + ro0 + gj) = pk2(h0, h1);
            *(unsigned*)(g_ctx_lo + ro0 + gj) = pk2(v0 - h0, v1 - h1);
            *(unsigned*)(g_ctx_hi + ro1 + gj) = pk2(h2, h3);
            *(unsigned*)(g_ctx_lo + ro1 + gj) = pk2(v2 - h2, v3 - h3);
        }
    }
}

// ---------------------------------------------------------------------------
extern "C" void kernel_launch(void* const* d_in, const int* in_sizes, int n_in,
                              void* d_out, int out_size)
{
    const float* q      = (const float*)d_in[0];
    const float* k      = (const float*)d_in[1];
    const float* v      = (const float*)d_in[2];
    const unsigned char* mask = (const unsigned char*)d_in[3];
    const float* Wq     = (const float*)d_in[4];
    const float* bq     = (const float*)d_in[5];
    const float* Wk     = (const float*)d_in[6];
    const float* bk     = (const float*)d_in[7];
    const float* Wv     = (const float*)d_in[8];
    const float* bv     = (const float*)d_in[9];
    const float* Wker   = (const float*)d_in[10];
    const float* bker   = (const float*)d_in[11];
    const float* Wproj  = (const float*)d_in[15];
    const float* bproj  = (const float*)d_in[16];

    float* out      = (float*)d_out;
    float* attn     = out + (size_t)B_ * L_ * D_;
    float* one_head = attn + (size_t)B_ * H_ * L_ * L_;

    void* p;
    __nv_bfloat16 *iqh, *iql, *ikh, *ikl, *ivh, *ivl, *wh, *wl, *ch, *cl;
    __nv_bfloat16 *qsh, *qsl, *ksh, *ksl, *vsh, *vsl;
    cudaGetSymbolAddress(&p, g_inq_hi); iqh = (__nv_bfloat16*)p;
    cudaGetSymbolAddress(&p, g_inq_lo); iql = (__nv_bfloat16*)p;
    cudaGetSymbolAddress(&p, g_ink_hi); ikh = (__nv_bfloat16*)p;
    cudaGetSymbolAddress(&p, g_ink_lo); ikl = (__nv_bfloat16*)p;
    cudaGetSymbolAddress(&p, g_inv_hi); ivh = (__nv_bfloat16*)p;
    cudaGetSymbolAddress(&p, g_inv_lo); ivl = (__nv_bfloat16*)p;
    cudaGetSymbolAddress(&p, g_w_hi);   wh  = (__nv_bfloat16*)p;
    cudaGetSymbolAddress(&p, g_w_lo);   wl  = (__nv_bfloat16*)p;
    cudaGetSymbolAddress(&p, g_ctx_hi); ch  = (__nv_bfloat16*)p;
    cudaGetSymbolAddress(&p, g_ctx_lo); cl  = (__nv_bfloat16*)p;
    cudaGetSymbolAddress(&p, g_qs_hi);  qsh = (__nv_bfloat16*)p;
    cudaGetSymbolAddress(&p, g_qs_lo);  qsl = (__nv_bfloat16*)p;
    cudaGetSymbolAddress(&p, g_ks_hi);  ksh = (__nv_bfloat16*)p;
    cudaGetSymbolAddress(&p, g_ks_lo);  ksl = (__nv_bfloat16*)p;
    cudaGetSymbolAddress(&p, g_vs_hi);  vsh = (__nv_bfloat16*)p;
    cudaGetSymbolAddress(&p, g_vs_lo);  vsl = (__nv_bfloat16*)p;

    static bool attr_done = false;
    if (!attr_done) {
        cudaFuncSetAttribute(logits_mma_kernel,
            cudaFuncAttributeMaxDynamicSharedMemorySize, LOG_SMEM);
        cudaFuncSetAttribute(gemm_mma_nt,
            cudaFuncAttributeMaxDynamicSharedMemorySize, GM_SMEM);
        cudaFuncSetAttribute(gemm_mma_split,
            cudaFuncAttributeMaxDynamicSharedMemorySize, GM_SMEM);
        attr_done = true;
    }

    const int M = B_ * L_;        // 8192
    const int NE = M * D_;
    const int NW = D_ * D_;
    dim3 blk(256);

    // 0) splits + weight prep (fused launches)
    conv_split3_kernel<<<dim3((NE/8 + 255)/256, 3), 256>>>(q, k, v, NE/8);
    conv_split4_kernel<<<dim3((NW/8 + 255)/256, 4), 256>>>(Wq, Wk, Wv, Wproj, NW/8);
    wker_prep_kernel<<<(H_*WKN*8 + 255)/256, 256>>>(Wker);
    bcat_kernel<<<(H_*WKN + 255)/256, 256>>>(bker);

    // 1) projections (tensor cores) -> bf16 hi/lo directly (2-stage, proven)
    gemm_mma_split<<<dim3(D_/128, M/128), blk, GM_SMEM>>>(iqh, iql, wh,        wl,        bq, qsh, qsl);
    gemm_mma_split<<<dim3(D_/128, M/128), blk, GM_SMEM>>>(ikh, ikl, wh + NW,   wl + NW,   bk, ksh, ksl);
    gemm_mma_split<<<dim3(D_/128, M/128), blk, GM_SMEM>>>(ivh, ivl, wh + 2*NW, wl + 2*NW, bv, vsh, vsl);

    // 2) operand prep
    qcat_mma_kernel<<<dim3(WKN/128, L_/128, B_*H_), blk>>>();
    kcat_prep_kernel<<<(B_*H_*L_*(NCAT/8) + 255)/256, 256>>>();
    vt_kernel<<<dim3(L_/128, B_*H_), blk>>>();

    // 3) tensor-core logits -> attn region (raw, scaled; no rowbias)
    logits_mma_kernel<<<dim3(L_/128, L_/128, B_*H_), 256, LOG_SMEM>>>(attn);

    // 4) softmax in place (+ one_head copy)
    softmax_kernel<<<B_*H_*L_, 256>>>(attn, mask, one_head);

    // 5) ctx = attn @ v_s -> g_ctx hi/lo
    ctx_mma_kernel<<<dim3(L_/128, B_*H_), blk>>>(attn);

    // 6) out = ctx @ Wproj^T + bproj (2-stage, proven)
    gemm_mma_nt<<<dim3(D_/128, M/128), blk, GM_SMEM>>>(ch, cl, wh + 3*NW, wl + 3*NW, bproj, out, D_, D_);
}

// round 14
// speedup vs baseline: 1.0686x; 1.0603x over previous
#include <cuda_runtime.h>
#include <cuda_bf16.h>
#include <cstdint>

#define B_   8
#define L_   1024
#define D_   512
#define H_   8
#define DK_  64
#define KW_  7
#define PAD_ 3
#define NCAT 448    /* KW*DK */
#define WKN  512    /* padded Wker N for qcat GEMM */

// ---------------- scratch (device globals; no runtime allocation) ----------
__device__ float g_bcat[H_*WKN];
// q/k/v_s bf16 split (written directly by the projections), layout [B*L, 512]
__device__ __align__(16) __nv_bfloat16 g_qs_hi[B_*L_*D_];
__device__ __align__(16) __nv_bfloat16 g_qs_lo[B_*L_*D_];
__device__ __align__(16) __nv_bfloat16 g_ks_hi[B_*L_*D_];
__device__ __align__(16) __nv_bfloat16 g_ks_lo[B_*L_*D_];
__device__ __align__(16) __nv_bfloat16 g_vs_hi[B_*L_*D_];
__device__ __align__(16) __nv_bfloat16 g_vs_lo[B_*L_*D_];
// Wker permuted+padded: [h][n=0..511][d=0..63]
__device__ __align__(16) __nv_bfloat16 g_wker_hi[H_*WKN*DK_];
__device__ __align__(16) __nv_bfloat16 g_wker_lo[H_*WKN*DK_];
// Qcat bf16 hi/lo (compact stride 448)
__device__ __align__(16) __nv_bfloat16 g_qcat_hi[(size_t)B_*H_*L_*NCAT];
__device__ __align__(16) __nv_bfloat16 g_qcat_lo[(size_t)B_*H_*L_*NCAT];
// projection inputs (bf16 split)
__device__ __align__(16) __nv_bfloat16 g_inq_hi[B_*L_*D_];
__device__ __align__(16) __nv_bfloat16 g_inq_lo[B_*L_*D_];
__device__ __align__(16) __nv_bfloat16 g_ink_hi[B_*L_*D_];
__device__ __align__(16) __nv_bfloat16 g_ink_lo[B_*L_*D_];
__device__ __align__(16) __nv_bfloat16 g_inv_hi[B_*L_*D_];
__device__ __align__(16) __nv_bfloat16 g_inv_lo[B_*L_*D_];
// weights (bf16 split): slots 0=Wq 1=Wk 2=Wv 3=Wproj
__device__ __align__(16) __nv_bfloat16 g_w_hi[4*D_*D_];
__device__ __align__(16) __nv_bfloat16 g_w_lo[4*D_*D_];
// v transposed per head: [z][n=0..63][k=0..1023]
__device__ __align__(16) __nv_bfloat16 g_vt_hi[(size_t)B_*H_*DK_*L_];
__device__ __align__(16) __nv_bfloat16 g_vt_lo[(size_t)B_*H_*DK_*L_];
// ctx in bf16 split, layout [B*L, 512]
__device__ __align__(16) __nv_bfloat16 g_ctx_hi[B_*L_*D_];
__device__ __align__(16) __nv_bfloat16 g_ctx_lo[B_*L_*D_];

// ====================== baseline-PTX tensor helpers ========================
static __device__ __forceinline__ uint32_t smem_u32(const void* p){
    uint32_t a;
    asm("{ .reg .u64 t; cvta.to.shared.u64 t, %1; cvt.u32.u64 %0, t; }"
        : "=r"(a) : "l"(p));
    return a;
}
#define CP_ASYNC16(dst, src) \
    asm volatile("cp.async.cg.shared.global [%0], [%1], 16;" \
                 :: "r"(dst), "l"(src) : "memory")
#define CP_COMMIT() asm volatile("cp.async.commit_group;" ::: "memory")
#define CP_WAIT(n)  asm volatile("cp.async.wait_group %0;" :: "n"(n) : "memory")
#define LDSM4(r0, r1, r2, r3, addr) \
    asm volatile("ldmatrix.sync.aligned.m8n8.x4.shared.b16 {%0,%1,%2,%3}, [%4];" \
                 : "=r"(r0), "=r"(r1), "=r"(r2), "=r"(r3) : "r"(addr))
#define MMA16816(d, a, b) \
    asm volatile("mma.sync.aligned.m16n8k16.row.col.f32.bf16.bf16.f32 " \
                 "{%0,%1,%2,%3},{%4,%5,%6,%7},{%8,%9},{%0,%1,%2,%3};" \
                 : "+f"((d)[0]), "+f"((d)[1]), "+f"((d)[2]), "+f"((d)[3]) \
                 : "r"((a)[0]), "r"((a)[1]), "r"((a)[2]), "r"((a)[3]), \
                   "r"((b)[0]), "r"((b)[1]))

static __device__ __forceinline__ unsigned pk2(float a, float b){
    __nv_bfloat162 t = __floats2bfloat162_rn(a, b);
    return *reinterpret_cast<unsigned*>(&t);
}
static __device__ __forceinline__ float bhi(float x){
    return __bfloat162float(__float2bfloat16_rn(x));
}

// ---------------------------------------------------------------------------
// conv_split3: fp32 -> bf16 hi/lo for q,k,v inputs in one launch (y = slot)
// ---------------------------------------------------------------------------
__global__ __launch_bounds__(256) void conv_split3_kernel(
    const float* __restrict__ s0, const float* __restrict__ s1,
    const float* __restrict__ s2, int n8)
{
    int i = blockIdx.x * 256 + threadIdx.x;
    if (i >= n8) return;
    const float* src; __nv_bfloat16 *dh, *dl;
    if (blockIdx.y == 0)      { src = s0; dh = g_inq_hi; dl = g_inq_lo; }
    else if (blockIdx.y == 1) { src = s1; dh = g_ink_hi; dl = g_ink_lo; }
    else                      { src = s2; dh = g_inv_hi; dl = g_inv_lo; }
    const float4* s = (const float4*)(src + (size_t)i * 8);
    float4 v0 = s[0], v1 = s[1];
    float f[8] = {v0.x, v0.y, v0.z, v0.w, v1.x, v1.y, v1.z, v1.w};
    float hh[8], ll[8];
#pragma unroll
    for (int e = 0; e < 8; e++) { hh[e] = bhi(f[e]); ll[e] = f[e] - hh[e]; }
    *(uint4*)(dh + (size_t)i * 8) = make_uint4(pk2(hh[0],hh[1]), pk2(hh[2],hh[3]),
                                               pk2(hh[4],hh[5]), pk2(hh[6],hh[7]));
    *(uint4*)(dl + (size_t)i * 8) = make_uint4(pk2(ll[0],ll[1]), pk2(ll[2],ll[3]),
                                               pk2(ll[4],ll[5]), pk2(ll[6],ll[7]));
}

// conv_split4: the 4 weight matrices into g_w slots (y = slot)
__global__ __launch_bounds__(256) void conv_split4_kernel(
    const float* __restrict__ s0, const float* __restrict__ s1,
    const float* __restrict__ s2, const float* __restrict__ s3, int n8)
{
    int i = blockIdx.x * 256 + threadIdx.x;
    if (i >= n8) return;
    const float* srcs[4] = {s0, s1, s2, s3};
    const float* src = srcs[blockIdx.y];
    size_t slot = (size_t)blockIdx.y * D_ * D_;
    const float4* s = (const float4*)(src + (size_t)i * 8);
    float4 v0 = s[0], v1 = s[1];
    float f[8] = {v0.x, v0.y, v0.z, v0.w, v1.x, v1.y, v1.z, v1.w};
    float hh[8], ll[8];
#pragma unroll
    for (int e = 0; e < 8; e++) { hh[e] = bhi(f[e]); ll[e] = f[e] - hh[e]; }
    *(uint4*)(g_w_hi + slot + (size_t)i * 8) =
        make_uint4(pk2(hh[0],hh[1]), pk2(hh[2],hh[3]),
                   pk2(hh[4],hh[5]), pk2(hh[6],hh[7]));
    *(uint4*)(g_w_lo + slot + (size_t)i * 8) =
        make_uint4(pk2(ll[0],ll[1]), pk2(ll[2],ll[3]),
                   pk2(ll[4],ll[5]), pk2(ll[6],ll[7]));
}

// ---------------------------------------------------------------------------
// wker_prep: g_wker[h][n][d] = Wker[h, n&63, n>>6, d] for n<448 else 0
// ---------------------------------------------------------------------------
__global__ __launch_bounds__(256) void wker_prep_kernel(const float* __restrict__ Wker)
{
    int idx = blockIdx.x * 256 + threadIdx.x;      // over 8*512*8
    if (idx >= H_ * WKN * 8) return;
    int d8 = (idx & 7) * 8;
    int n  = (idx >> 3) & (WKN - 1);
    int h  = idx >> 12;
    float f[8] = {0,0,0,0,0,0,0,0};
    if (n < NCAT) {
        int t = n >> 6, c = n & 63;
        const float* src = Wker + (((size_t)(h*DK_ + c)) * KW_ + t) * DK_ + d8;
        float4 v0 = *(const float4*)src, v1 = *(const float4*)(src + 4);
        f[0]=v0.x; f[1]=v0.y; f[2]=v0.z; f[3]=v0.w;
        f[4]=v1.x; f[5]=v1.y; f[6]=v1.z; f[7]=v1.w;
    }
    float hh[8], ll[8];
#pragma unroll
    for (int e = 0; e < 8; e++) { hh[e] = bhi(f[e]); ll[e] = f[e] - hh[e]; }
    size_t off = ((size_t)h * WKN + n) * DK_ + d8;
    *(uint4*)(g_wker_hi + off) = make_uint4(pk2(hh[0],hh[1]), pk2(hh[2],hh[3]),
                                            pk2(hh[4],hh[5]), pk2(hh[6],hh[7]));
    *(uint4*)(g_wker_lo + off) = make_uint4(pk2(ll[0],ll[1]), pk2(ll[2],ll[3]),
                                            pk2(ll[4],ll[5]), pk2(ll[6],ll[7]));
}

// ---------------------------------------------------------------------------
// bcat[h, n] = bker[h, n&63, n>>6] for n<448 else 0   (padded to 512)
// ---------------------------------------------------------------------------
__global__ void bcat_kernel(const float* __restrict__ bker)
{
    int n = blockIdx.x * blockDim.x + threadIdx.x;
    if (n >= H_ * WKN) return;
    int h = n >> 9, r = n & (WKN - 1), t = r >> 6, c = r & 63;
    g_bcat[n] = (r < NCAT) ? bker[(size_t)(h*DK_ + c) * KW_ + t] : 0.f;
}

// ---------------------------------------------------------------------------
// 2-stage mma GEMM pieces (tile 128x128, 8 warps 2x4) -- R11-proven config
// ---------------------------------------------------------------------------
#define GM_STAGE 32768
#define GM_SMEM  (2*GM_STAGE)

// ---------------------------------------------------------------------------
// out-projection GEMM: C[M,N] fp32 = A@B^T + bias[N].  2-stage.  2 CTAs/SM.
// ---------------------------------------------------------------------------
__global__ __launch_bounds__(256, 2) void gemm_mma_nt(
    const __nv_bfloat16* __restrict__ Ah, const __nv_bfloat16* __restrict__ Al,
    const __nv_bfloat16* __restrict__ Bh, const __nv_bfloat16* __restrict__ Bl,
    const float* __restrict__ bias, float* __restrict__ C, int K, int N)
{
    extern __shared__ char smem[];
    const uint32_t sbase = smem_u32(smem);
    const int kc = K >> 5;

    const int tid  = threadIdx.x;
    const int wid  = tid >> 5, lane = tid & 31;
    const int wm   = wid >> 2, wn = wid & 3;

    const int i0 = blockIdx.y * 128;
    const int j0 = blockIdx.x * 128;

    const __nv_bfloat16* ah = Ah + (size_t)i0 * K;
    const __nv_bfloat16* al = Al + (size_t)i0 * K;
    const __nv_bfloat16* bh_ = Bh + (size_t)j0 * K;
    const __nv_bfloat16* bl_ = Bl + (size_t)j0 * K;

    auto issue = [&](int s, int c) {
        const uint32_t sb = sbase + s * GM_STAGE;
#pragma unroll
        for (int q = 0; q < 4; q++) {
            int u  = q * 256 + tid;
            int r  = u >> 3, cj = u & 7;
            const __nv_bfloat16* src =
                (cj < 4 ? ah : al) + (size_t)r * K + c * 32 + (cj & 3) * 8;
            CP_ASYNC16(sb + r * 128 + 16 * (cj ^ (r & 7)), src);
        }
#pragma unroll
        for (int q = 0; q < 4; q++) {
            int u  = q * 256 + tid;
            int r  = u >> 3, cj = u & 7;
            const __nv_bfloat16* src =
                (cj < 4 ? bh_ : bl_) + (size_t)r * K + c * 32 + (cj & 3) * 8;
            CP_ASYNC16(sb + 16384 + r * 128 + 16 * (cj ^ (r & 7)), src);
        }
    };

    float acc[4][4][4];
#pragma unroll
    for (int i = 0; i < 4; i++)
#pragma unroll
        for (int j = 0; j < 4; j++)
#pragma unroll
            for (int e = 0; e < 4; e++) acc[i][j][e] = 0.f;

    issue(0, 0);
    CP_COMMIT();

    const int lrow = (lane & 7) + 8 * ((lane >> 3) & 1);
    const int lchk = lane >> 4;

    for (int c = 0; c < kc; c++) {
        const int s = c & 1;
        if (c + 1 < kc) { issue(s ^ 1, c + 1); CP_COMMIT(); CP_WAIT(1); }
        else            { CP_WAIT(0); }
        __syncthreads();

        const uint32_t sA = sbase + s * GM_STAGE;
        const uint32_t sB = sA + 16384;

#pragma unroll
        for (int ks = 0; ks < 2; ks++) {
            uint32_t bh[4][2], bl[4][2];
#pragma unroll
            for (int g = 0; g < 2; g++) {
                int r  = wn * 32 + g * 16 + lrow;
                int ch = ks * 2 + lchk;
                uint32_t r0, r1, r2, r3;
                LDSM4(r0, r1, r2, r3, sB + r * 128 + 16 * ((ch)     ^ (r & 7)));
                bh[2*g][0] = r0; bh[2*g][1] = r2;
                bh[2*g+1][0] = r1; bh[2*g+1][1] = r3;
                LDSM4(r0, r1, r2, r3, sB + r * 128 + 16 * ((ch + 4) ^ (r & 7)));
                bl[2*g][0] = r0; bl[2*g][1] = r2;
                bl[2*g+1][0] = r1; bl[2*g+1][1] = r3;
            }
#pragma unroll
            for (int mf = 0; mf < 4; mf++) {
                int r  = wm * 64 + mf * 16 + lrow;
                int ch = ks * 2 + lchk;
                uint32_t ah_[4], al_[4];
                LDSM4(ah_[0], ah_[1], ah_[2], ah_[3],
                      sA + r * 128 + 16 * ((ch)     ^ (r & 7)));
                LDSM4(al_[0], al_[1], al_[2], al_[3],
                      sA + r * 128 + 16 * ((ch + 4) ^ (r & 7)));
#pragma unroll
                for (int nf = 0; nf < 4; nf++) {
                    MMA16816(acc[mf][nf], ah_, bh[nf]);
                    MMA16816(acc[mf][nf], ah_, bl[nf]);
                    MMA16816(acc[mf][nf], al_, bh[nf]);
                }
            }
        }
        __syncthreads();
    }

    const int rbase = i0 + wm * 64 + (lane >> 2);
    const int cbase = j0 + wn * 32 + 2 * (lane & 3);
#pragma unroll
    for (int mf = 0; mf < 4; mf++) {
        int gi = rbase + mf * 16;
        float* row0 = C + (size_t)gi * N;
        float* row1 = row0 + 8 * N;
#pragma unroll
        for (int nf = 0; nf < 4; nf++) {
            int gj = cbase + nf * 8;
            float b0 = bias[gj], b1 = bias[gj + 1];
            *(float2*)(row0 + gj) = make_float2(acc[mf][nf][0] + b0,
                                                acc[mf][nf][1] + b1);
            *(float2*)(row1 + gj) = make_float2(acc[mf][nf][2] + b0,
                                                acc[mf][nf][3] + b1);
        }
    }
}

// ---------------------------------------------------------------------------
// projection GEMM writing bf16 hi/lo ONLY.  K = N = 512, 16 chunks, 2-stage.
// ---------------------------------------------------------------------------
__global__ __launch_bounds__(256, 2) void gemm_mma_split(
    const __nv_bfloat16* __restrict__ Ah, const __nv_bfloat16* __restrict__ Al,
    const __nv_bfloat16* __restrict__ Bh, const __nv_bfloat16* __restrict__ Bl,
    const float* __restrict__ bias,
    __nv_bfloat16* __restrict__ Ch, __nv_bfloat16* __restrict__ Cl)
{
    extern __shared__ char smem[];
    const uint32_t sbase = smem_u32(smem);
    const int K = D_;

    const int tid  = threadIdx.x;
    const int wid  = tid >> 5, lane = tid & 31;
    const int wm   = wid >> 2, wn = wid & 3;

    const int i0 = blockIdx.y * 128;
    const int j0 = blockIdx.x * 128;

    const __nv_bfloat16* ah = Ah + (size_t)i0 * K;
    const __nv_bfloat16* al = Al + (size_t)i0 * K;
    const __nv_bfloat16* bh_ = Bh + (size_t)j0 * K;
    const __nv_bfloat16* bl_ = Bl + (size_t)j0 * K;

    auto issue = [&](int s, int c) {
        const uint32_t sb = sbase + s * GM_STAGE;
#pragma unroll
        for (int q = 0; q < 4; q++) {
            int u  = q * 256 + tid;
            int r  = u >> 3, cj = u & 7;
            const __nv_bfloat16* src =
                (cj < 4 ? ah : al) + (size_t)r * K + c * 32 + (cj & 3) * 8;
            CP_ASYNC16(sb + r * 128 + 16 * (cj ^ (r & 7)), src);
        }
#pragma unroll
        for (int q = 0; q < 4; q++) {
            int u  = q * 256 + tid;
            int r  = u >> 3, cj = u & 7;
            const __nv_bfloat16* src =
                (cj < 4 ? bh_ : bl_) + (size_t)r * K + c * 32 + (cj & 3) * 8;
            CP_ASYNC16(sb + 16384 + r * 128 + 16 * (cj ^ (r & 7)), src);
        }
    };

    float acc[4][4][4];
#pragma unroll
    for (int i = 0; i < 4; i++)
#pragma unroll
        for (int j = 0; j < 4; j++)
#pragma unroll
            for (int e = 0; e < 4; e++) acc[i][j][e] = 0.f;

    issue(0, 0);
    CP_COMMIT();

    const int lrow = (lane & 7) + 8 * ((lane >> 3) & 1);
    const int lchk = lane >> 4;

    for (int c = 0; c < 16; c++) {
        const int s = c & 1;
        if (c + 1 < 16) { issue(s ^ 1, c + 1); CP_COMMIT(); CP_WAIT(1); }
        else            { CP_WAIT(0); }
        __syncthreads();

        const uint32_t sA = sbase + s * GM_STAGE;
        const uint32_t sB = sA + 16384;

#pragma unroll
        for (int ks = 0; ks < 2; ks++) {
            uint32_t bh[4][2], bl[4][2];
#pragma unroll
            for (int g = 0; g < 2; g++) {
                int r  = wn * 32 + g * 16 + lrow;
                int ch = ks * 2 + lchk;
                uint32_t r0, r1, r2, r3;
                LDSM4(r0, r1, r2, r3, sB + r * 128 + 16 * ((ch)     ^ (r & 7)));
                bh[2*g][0] = r0; bh[2*g][1] = r2;
                bh[2*g+1][0] = r1; bh[2*g+1][1] = r3;
                LDSM4(r0, r1, r2, r3, sB + r * 128 + 16 * ((ch + 4) ^ (r & 7)));
                bl[2*g][0] = r0; bl[2*g][1] = r2;
                bl[2*g+1][0] = r1; bl[2*g+1][1] = r3;
            }
#pragma unroll
            for (int mf = 0; mf < 4; mf++) {
                int r  = wm * 64 + mf * 16 + lrow;
                int ch = ks * 2 + lchk;
                uint32_t ah_[4], al_[4];
                LDSM4(ah_[0], ah_[1], ah_[2], ah_[3],
                      sA + r * 128 + 16 * ((ch)     ^ (r & 7)));
                LDSM4(al_[0], al_[1], al_[2], al_[3],
                      sA + r * 128 + 16 * ((ch + 4) ^ (r & 7)));
#pragma unroll
                for (int nf = 0; nf < 4; nf++) {
                    MMA16816(acc[mf][nf], ah_, bh[nf]);
                    MMA16816(acc[mf][nf], ah_, bl[nf]);
                    MMA16816(acc[mf][nf], al_, bh[nf]);
                }
            }
        }
        __syncthreads();
    }

    const int rbase = i0 + wm * 64 + (lane >> 2);
    const int cbase = j0 + wn * 32 + 2 * (lane & 3);
#pragma unroll
    for (int mf = 0; mf < 4; mf++) {
        int gi = rbase + mf * 16;
        size_t ro0 = (size_t)gi * D_, ro1 = ro0 + 8 * D_;
#pragma unroll
        for (int nf = 0; nf < 4; nf++) {
            int gj = cbase + nf * 8;
            float b0 = bias[gj], b1 = bias[gj + 1];
            float v0 = acc[mf][nf][0] + b0, v1 = acc[mf][nf][1] + b1;
            float v2 = acc[mf][nf][2] + b0, v3 = acc[mf][nf][3] + b1;
            float h0 = bhi(v0), h1 = bhi(v1), h2 = bhi(v2), h3 = bhi(v3);
            *(unsigned*)(Ch + ro0 + gj) = pk2(h0, h1);
            *(unsigned*)(Cl + ro0 + gj) = pk2(v0 - h0, v1 - h1);
            *(unsigned*)(Ch + ro1 + gj) = pk2(h2, h3);
            *(unsigned*)(Cl + ro1 + gj) = pk2(v2 - h2, v3 - h3);
        }
    }
}

// ---------------------------------------------------------------------------
// qcat via mma: per z: Qcat[1024, n<448] = q_s_head[1024,64] @ wker[512,64]^T
//   + bcat. K=64 -> 2 chunks.  grid (4, 8, 64).  compact stride 448.
// ---------------------------------------------------------------------------
__global__ __launch_bounds__(256, 2) void qcat_mma_kernel()
{
    __shared__ char smem[2 * GM_STAGE];
    const uint32_t sbase = smem_u32(smem);

    const int tid  = threadIdx.x;
    const int wid  = tid >> 5, lane = tid & 31;
    const int wm   = wid >> 2, wn = wid & 3;

    const int z  = blockIdx.z;
    const int b = z >> 3, h = z & 7;
    const int i0 = blockIdx.y * 128;
    const int n0 = blockIdx.x * 128;

    const __nv_bfloat16* ah = g_qs_hi + ((size_t)(b*L_ + i0)) * D_ + h*DK_;
    const __nv_bfloat16* al = g_qs_lo + ((size_t)(b*L_ + i0)) * D_ + h*DK_;
    const __nv_bfloat16* bh_ = g_wker_hi + ((size_t)h * WKN + n0) * DK_;
    const __nv_bfloat16* bl_ = g_wker_lo + ((size_t)h * WKN + n0) * DK_;

    auto issue = [&](int s, int c) {
        const uint32_t sb = sbase + s * GM_STAGE;
#pragma unroll
        for (int q = 0; q < 4; q++) {
            int u  = q * 256 + tid;
            int r  = u >> 3, cj = u & 7;
            const __nv_bfloat16* src =
                (cj < 4 ? ah : al) + (size_t)r * D_ + c * 32 + (cj & 3) * 8;
            CP_ASYNC16(sb + r * 128 + 16 * (cj ^ (r & 7)), src);
        }
#pragma unroll
        for (int q = 0; q < 4; q++) {
            int u  = q * 256 + tid;
            int r  = u >> 3, cj = u & 7;
            const __nv_bfloat16* src =
                (cj < 4 ? bh_ : bl_) + (size_t)r * DK_ + c * 32 + (cj & 3) * 8;
            CP_ASYNC16(sb + 16384 + r * 128 + 16 * (cj ^ (r & 7)), src);
        }
    };

    float acc[4][4][4];
#pragma unroll
    for (int i = 0; i < 4; i++)
#pragma unroll
        for (int j = 0; j < 4; j++)
#pragma unroll
            for (int e = 0; e < 4; e++) acc[i][j][e] = 0.f;

    issue(0, 0);
    CP_COMMIT();

    const int lrow = (lane & 7) + 8 * ((lane >> 3) & 1);
    const int lchk = lane >> 4;

    for (int c = 0; c < 2; c++) {
        const int s = c & 1;
        if (c == 0) { issue(1, 1); CP_COMMIT(); CP_WAIT(1); }
        else        { CP_WAIT(0); }
        __syncthreads();

        const uint32_t sA = sbase + s * GM_STAGE;
        const uint32_t sB = sA + 16384;

#pragma unroll
        for (int ks = 0; ks < 2; ks++) {
            uint32_t bh[4][2], bl[4][2];
#pragma unroll
            for (int g = 0; g < 2; g++) {
                int r  = wn * 32 + g * 16 + lrow;
                int ch = ks * 2 + lchk;
                uint32_t r0, r1, r2, r3;
                LDSM4(r0, r1, r2, r3, sB + r * 128 + 16 * ((ch)     ^ (r & 7)));
                bh[2*g][0] = r0; bh[2*g][1] = r2;
                bh[2*g+1][0] = r1; bh[2*g+1][1] = r3;
                LDSM4(r0, r1, r2, r3, sB + r * 128 + 16 * ((ch + 4) ^ (r & 7)));
                bl[2*g][0] = r0; bl[2*g][1] = r2;
                bl[2*g+1][0] = r1; bl[2*g+1][1] = r3;
            }
#pragma unroll
            for (int mf = 0; mf < 4; mf++) {
                int r  = wm * 64 + mf * 16 + lrow;
                int ch = ks * 2 + lchk;
                uint32_t ah_[4], al_[4];
                LDSM4(ah_[0], ah_[1], ah_[2], ah_[3],
                      sA + r * 128 + 16 * ((ch)     ^ (r & 7)));
                LDSM4(al_[0], al_[1], al_[2], al_[3],
                      sA + r * 128 + 16 * ((ch + 4) ^ (r & 7)));
#pragma unroll
                for (int nf = 0; nf < 4; nf++) {
                    MMA16816(acc[mf][nf], ah_, bh[nf]);
                    MMA16816(acc[mf][nf], ah_, bl[nf]);
                    MMA16816(acc[mf][nf], al_, bh[nf]);
                }
            }
        }
        __syncthreads();
    }

    __nv_bfloat16* Ch = g_qcat_hi + (size_t)z * L_ * NCAT;
    __nv_bfloat16* Cl = g_qcat_lo + (size_t)z * L_ * NCAT;
    const int rbase = i0 + wm * 64 + (lane >> 2);
    const int cbase = n0 + wn * 32 + 2 * (lane & 3);
#pragma unroll
    for (int mf = 0; mf < 4; mf++) {
        int gi = rbase + mf * 16;
        size_t ro0 = (size_t)gi * NCAT, ro1 = ro0 + 8 * NCAT;
#pragma unroll
        for (int nf = 0; nf < 4; nf++) {
            int gj = cbase + nf * 8;
            if (gj >= NCAT) continue;
            float b0 = g_bcat[h*WKN + gj], b1 = g_bcat[h*WKN + gj + 1];
            float v0 = acc[mf][nf][0] + b0, v1 = acc[mf][nf][1] + b1;
            float v2 = acc[mf][nf][2] + b0, v3 = acc[mf][nf][3] + b1;
            float h0 = bhi(v0), h1 = bhi(v1), h2 = bhi(v2), h3 = bhi(v3);
            *(unsigned*)(Ch + ro0 + gj) = pk2(h0, h1);
            *(unsigned*)(Cl + ro0 + gj) = pk2(v0 - h0, v1 - h1);
            *(unsigned*)(Ch + ro1 + gj) = pk2(h2, h3);
            *(unsigned*)(Cl + ro1 + gj) = pk2(v2 - h2, v3 - h3);
        }
    }
}

// ---------------------------------------------------------------------------
// vt transpose (bf16): vt[z][n][k] = v_s[b][k][h*64+n], hi/lo packed in smem.
// ---------------------------------------------------------------------------
__global__ __launch_bounds__(256) void vt_kernel()
{
    __shared__ uint32_t t[128][65];   // hi | lo<<16 per element
    const int z = blockIdx.y;
    const int b = z >> 3, h = z & 7;
    const int k0 = blockIdx.x * 128;
    const int tid = threadIdx.x;

#pragma unroll
    for (int q = 0; q < 4; q++) {          // 1024 units of 8 elems
        int u = q * 256 + tid;
        int r = u >> 3, c8 = (u & 7) * 8;
        size_t so = ((size_t)(b*L_ + k0 + r)) * D_ + h*DK_ + c8;
        uint4 vh = *(const uint4*)(g_vs_hi + so);
        uint4 vl = *(const uint4*)(g_vs_lo + so);
        uint32_t hw[4] = {vh.x, vh.y, vh.z, vh.w};
        uint32_t lw[4] = {vl.x, vl.y, vl.z, vl.w};
#pragma unroll
        for (int e = 0; e < 4; e++) {
            t[r][c8 + 2*e]     = (hw[e] & 0xffffu) | (lw[e] << 16);
            t[r][c8 + 2*e + 1] = (hw[e] >> 16)     | (lw[e] & 0xffff0000u);
        }
    }
    __syncthreads();

#pragma unroll
    for (int q = 0; q < 4; q++) {          // 64 n x 16 k-groups of 8
        int u = q * 256 + tid;
        int n = u >> 4, k8 = (u & 15) * 8;
        uint32_t hi4[4], lo4[4];
#pragma unroll
        for (int e = 0; e < 4; e++) {
            uint32_t a = t[k8 + 2*e][n];
            uint32_t c = t[k8 + 2*e + 1][n];
            hi4[e] = (a & 0xffffu) | ((c & 0xffffu) << 16);
            lo4[e] = (a >> 16)     | (c & 0xffff0000u);
        }
        size_t off = (size_t)z * DK_ * L_ + (size_t)n * L_ + k0 + k8;
        *(uint4*)(g_vt_hi + off) = make_uint4(hi4[0], hi4[1], hi4[2], hi4[3]);
        *(uint4*)(g_vt_lo + off) = make_uint4(lo4[0], lo4[1], lo4[2], lo4[3]);
    }
}

// ---------------------------------------------------------------------------
// Logits v3: 128x128 tile, K=448 in 14 chunks, A=Qcat (3-stage streamed),
// B = k_s panel loaded ONCE into smem (134 rows x 64 cols, hi+lo), with the
// conv t-shift applied as a +t smem ROW offset at ldmatrix time:
//   Kcat[j][t*64+cc] = ks[j+t-3][cc] = panel[(j-j0)+t]
// No Kcat materialization.  No rowbias.  grid (8, 8, 64).  2 CTAs/SM.
// smem: 3*16KB A stages + 2*17152B panel = 83456 B.
// ---------------------------------------------------------------------------
#define LOG_ASTAGE   16384
#define LOG_PANEL    17152              /* 134 rows * 128 B */
#define LOG_PANEL_HI (3*LOG_ASTAGE)
#define LOG_PANEL_LO (LOG_PANEL_HI + LOG_PANEL)
#define LOG_SMEM     (LOG_PANEL_LO + LOG_PANEL)

__global__ __launch_bounds__(256, 2) void logits_mma_kernel(float* __restrict__ attn)
{
    extern __shared__ char smem[];
    const uint32_t sbase = smem_u32(smem);
    const uint32_t pHI = sbase + LOG_PANEL_HI;
    const uint32_t pLO = sbase + LOG_PANEL_LO;

    const int tid  = threadIdx.x;
    const int wid  = tid >> 5, lane = tid & 31;
    const int wm   = wid >> 2, wn = wid & 3;

    const int z  = blockIdx.z;
    const int b = z >> 3, h = z & 7;
    const int i0 = blockIdx.y * 128;
    const int j0 = blockIdx.x * 128;

    const __nv_bfloat16* qh = g_qcat_hi + (size_t)z * L_ * NCAT + (size_t)i0 * NCAT;
    const __nv_bfloat16* ql = g_qcat_lo + (size_t)z * L_ * NCAT + (size_t)i0 * NCAT;
    const __nv_bfloat16* ksh = g_ks_hi + ((size_t)(b*L_)) * D_ + h*DK_;
    const __nv_bfloat16* ksl = g_ks_lo + ((size_t)(b*L_)) * D_ + h*DK_;

    auto issueA = [&](int s, int c) {
        const uint32_t sb = sbase + s * LOG_ASTAGE;
#pragma unroll
        for (int q = 0; q < 4; q++) {
            int u  = q * 256 + tid;
            int r  = u >> 3, cj = u & 7;
            const __nv_bfloat16* src =
                (cj < 4 ? qh : ql) + (size_t)r * NCAT + c * 32 + (cj & 3) * 8;
            CP_ASYNC16(sb + r * 128 + 16 * (cj ^ (r & 7)), src);
        }
    };

    // ---- panel load: rows j0-3 .. j0+130, 8 groups of 8 cols each ----
    for (int u = tid; u < 134 * 8; u += 256) {
        int r  = u >> 3, g8 = u & 7;
        int j  = j0 + r - PAD_;
        uint32_t dh = pHI + r * 128 + 16 * (g8 ^ (r & 7));
        uint32_t dl = pLO + r * 128 + 16 * (g8 ^ (r & 7));
        if (j >= 0 && j < L_) {
            CP_ASYNC16(dh, ksh + (size_t)j * D_ + g8 * 8);
            CP_ASYNC16(dl, ksl + (size_t)j * D_ + g8 * 8);
        } else {
            *(uint4*)(smem + (dh - sbase)) = make_uint4(0,0,0,0);
            *(uint4*)(smem + (dl - sbase)) = make_uint4(0,0,0,0);
        }
    }
    issueA(0, 0); CP_COMMIT();   // group: panel + A0
    issueA(1, 1); CP_COMMIT();   // group: A1

    float acc[4][4][4];
#pragma unroll
    for (int i = 0; i < 4; i++)
#pragma unroll
        for (int j = 0; j < 4; j++)
#pragma unroll
            for (int e = 0; e < 4; e++) acc[i][j][e] = 0.f;

    const int lrow = (lane & 7) + 8 * ((lane >> 3) & 1);
    const int lchk = lane >> 4;

    int stage = 0;
    for (int c = 0; c < 14; c++) {
        if (c + 2 < 14) {
            int s2 = stage + 2; if (s2 >= 3) s2 -= 3;
            issueA(s2, c + 2); CP_COMMIT(); CP_WAIT(2);
        } else if (c + 1 < 14) { CP_WAIT(1); }
        else                   { CP_WAIT(0); }
        __syncthreads();

        const uint32_t sA = sbase + stage * LOG_ASTAGE;
        const int t    = c >> 1;
        const int half = c & 1;

#pragma unroll
        for (int ks = 0; ks < 2; ks++) {
            uint32_t bh[4][2], bl[4][2];
#pragma unroll
            for (int g = 0; g < 2; g++) {
                int rr = wn * 32 + g * 16 + lrow + t;        // shifted panel row
                int g8 = half * 4 + ks * 2 + lchk;
                uint32_t r0, r1, r2, r3;
                LDSM4(r0, r1, r2, r3, pHI + rr * 128 + 16 * (g8 ^ (rr & 7)));
                bh[2*g][0] = r0; bh[2*g][1] = r2;
                bh[2*g+1][0] = r1; bh[2*g+1][1] = r3;
                LDSM4(r0, r1, r2, r3, pLO + rr * 128 + 16 * (g8 ^ (rr & 7)));
                bl[2*g][0] = r0; bl[2*g][1] = r2;
                bl[2*g+1][0] = r1; bl[2*g+1][1] = r3;
            }
#pragma unroll
            for (int mf = 0; mf < 4; mf++) {
                int r  = wm * 64 + mf * 16 + lrow;
                int ch = ks * 2 + lchk;
                uint32_t ah[4], al[4];
                LDSM4(ah[0], ah[1], ah[2], ah[3],
                      sA + r * 128 + 16 * ((ch)     ^ (r & 7)));
                LDSM4(al[0], al[1], al[2], al[3],
                      sA + r * 128 + 16 * ((ch + 4) ^ (r & 7)));
#pragma unroll
                for (int nf = 0; nf < 4; nf++) {
                    MMA16816(acc[mf][nf], ah, bh[nf]);
                    MMA16816(acc[mf][nf], ah, bl[nf]);
                    MMA16816(acc[mf][nf], al, bh[nf]);
                }
            }
        }
        __syncthreads();
        stage++; if (stage == 3) stage = 0;
    }

    const int rbase = i0 + wm * 64 + (lane >> 2);
    const int cbase = j0 + wn * 32 + 2 * (lane & 3);
#pragma unroll
    for (int mf = 0; mf < 4; mf++) {
        int gi0 = rbase + mf * 16;
        float* row0 = attn + ((size_t)z * L_ + gi0) * L_;
        float* row1 = row0 + 8 * L_;
#pragma unroll
        for (int nf = 0; nf < 4; nf++) {
            int gj = cbase + nf * 8;
            *(float2*)(row0 + gj) = make_float2(acc[mf][nf][0]*0.125f,
                                                acc[mf][nf][1]*0.125f);
            *(float2*)(row1 + gj) = make_float2(acc[mf][nf][2]*0.125f,
                                                acc[mf][nf][3]*0.125f);
        }
    }
}

// ---------------------------------------------------------------------------
// Row softmax in-place on attn; mask; head-0 duplicate.
// ---------------------------------------------------------------------------
__global__ __launch_bounds__(256) void softmax_kernel(
    float* __restrict__ attn, const unsigned char* __restrict__ mask,
    float* __restrict__ one_head)
{
    const int r = blockIdx.x;
    const int i = r & (L_-1);
    const int bh = r >> 10;
    const int h = bh & (H_-1), b = bh >> 3;
    float* row = attn + (size_t)r * L_;
    const unsigned char* mrow = mask + ((size_t)(b*L_ + i)) * L_;
    const int t4 = threadIdx.x * 4;

    float4 v = *(const float4*)(row + t4);
    uchar4 m = *(const uchar4*)(mrow + t4);
    float x0 = m.x ? -INFINITY : v.x;
    float x1 = m.y ? -INFINITY : v.y;
    float x2 = m.z ? -INFINITY : v.z;
    float x3 = m.w ? -INFINITY : v.w;

    __shared__ float sm[8], ss[8];
    float mx = fmaxf(fmaxf(x0, x1), fmaxf(x2, x3));
#pragma unroll
    for (int o = 16; o; o >>= 1) mx = fmaxf(mx, __shfl_xor_sync(0xffffffffu, mx, o));
    if ((threadIdx.x & 31) == 0) sm[threadIdx.x >> 5] = mx;
    __syncthreads();
    if (threadIdx.x < 32) {
        float t = (threadIdx.x < 8) ? sm[threadIdx.x] : -INFINITY;
#pragma unroll
        for (int o = 4; o; o >>= 1) t = fmaxf(t, __shfl_xor_sync(0xffffffffu, t, o));
        if (threadIdx.x == 0) sm[0] = t;
    }
    __syncthreads();
    mx = sm[0];

    float e0 = __expf(x0 - mx), e1 = __expf(x1 - mx);
    float e2 = __expf(x2 - mx), e3 = __expf(x3 - mx);
    float s = (e0 + e1) + (e2 + e3);
#pragma unroll
    for (int o = 16; o; o >>= 1) s += __shfl_xor_sync(0xffffffffu, s, o);
    if ((threadIdx.x & 31) == 0) ss[threadIdx.x >> 5] = s;
    __syncthreads();
    if (threadIdx.x < 32) {
        float t = (threadIdx.x < 8) ? ss[threadIdx.x] : 0.f;
#pragma unroll
        for (int o = 4; o; o >>= 1) t += __shfl_xor_sync(0xffffffffu, t, o);
        if (threadIdx.x == 0) ss[0] = t;
    }
    __syncthreads();
    float inv = 1.0f / ss[0];

    float4 o = make_float4(e0*inv, e1*inv, e2*inv, e3*inv);
    *(float4*)(row + t4) = o;
    if (h == 0)
        *(float4*)(one_head + ((size_t)(b*L_ + i)) * L_ + t4) = o;
}

// ---------------------------------------------------------------------------
// ctx via mma: per (b,h): C[1024,64] = attn @ v_head.
// ---------------------------------------------------------------------------
#define CTX_STAGE 24576

__global__ __launch_bounds__(256, 2) void ctx_mma_kernel(const float* __restrict__ attn)
{
    __shared__ char smem[2 * CTX_STAGE];
    const uint32_t sbase = smem_u32(smem);

    const int tid  = threadIdx.x;
    const int wid  = tid >> 5, lane = tid & 31;
    const int wm   = wid >> 2, wn = wid & 3;

    const int z  = blockIdx.y;
    const int b = z >> 3, h = z & 7;
    const int i0 = blockIdx.x * 128;

    const float* A = attn + ((size_t)z * L_ + i0) * L_;
    const __nv_bfloat16* vh = g_vt_hi + (size_t)z * DK_ * L_;
    const __nv_bfloat16* vl = g_vt_lo + (size_t)z * DK_ * L_;

    auto issueB = [&](int s, int c) {
        const uint32_t sb = sbase + s * CTX_STAGE + 16384;
#pragma unroll
        for (int q = 0; q < 2; q++) {
            int u  = q * 256 + tid;
            int r  = u >> 3, cj = u & 7;
            const __nv_bfloat16* src =
                (cj < 4 ? vh : vl) + (size_t)r * L_ + c * 32 + (cj & 3) * 8;
            CP_ASYNC16(sb + r * 128 + 16 * (cj ^ (r & 7)), src);
        }
    };
    float fa[2][8];
    auto ldgA = [&](int c) {
#pragma unroll
        for (int q = 0; q < 2; q++) {
            int u = q * 256 + tid;
            int r = u >> 2, seg = u & 3;
            const float4* p = (const float4*)(A + (size_t)r * L_ + c * 32 + seg * 8);
            float4 v0 = p[0], v1 = p[1];
            fa[q][0]=v0.x; fa[q][1]=v0.y; fa[q][2]=v0.z; fa[q][3]=v0.w;
            fa[q][4]=v1.x; fa[q][5]=v1.y; fa[q][6]=v1.z; fa[q][7]=v1.w;
        }
    };
    auto stsA = [&](int s) {
#pragma unroll
        for (int q = 0; q < 2; q++) {
            int u = q * 256 + tid;
            int r = u >> 2, seg = u & 3;
            float hh[8], ll[8];
#pragma unroll
            for (int e = 0; e < 8; e++) { hh[e] = bhi(fa[q][e]); ll[e] = fa[q][e] - hh[e]; }
            *(uint4*)(smem + s * CTX_STAGE + r * 128 + 16 * ((seg)     ^ (r & 7))) =
                make_uint4(pk2(hh[0],hh[1]), pk2(hh[2],hh[3]),
                           pk2(hh[4],hh[5]), pk2(hh[6],hh[7]));
            *(uint4*)(smem + s * CTX_STAGE + r * 128 + 16 * ((seg + 4) ^ (r & 7))) =
                make_uint4(pk2(ll[0],ll[1]), pk2(ll[2],ll[3]),
                           pk2(ll[4],ll[5]), pk2(ll[6],ll[7]));
        }
    };

    float acc[4][2][4];
#pragma unroll
    for (int i = 0; i < 4; i++)
#pragma unroll
        for (int j = 0; j < 2; j++)
#pragma unroll
            for (int e = 0; e < 4; e++) acc[i][j][e] = 0.f;

    ldgA(0);
    issueB(0, 0); CP_COMMIT();

    const int lrow = (lane & 7) + 8 * ((lane >> 3) & 1);
    const int lchk = lane >> 4;

    for (int c = 0; c < 32; c++) {
        const int s = c & 1;
        stsA(s);
        if (c + 1 < 32) {
            ldgA(c + 1);
            issueB(s ^ 1, c + 1); CP_COMMIT(); CP_WAIT(1);
        } else {
            CP_WAIT(0);
        }
        __syncthreads();

        const uint32_t sA = sbase + s * CTX_STAGE;
        const uint32_t sB = sA + 16384;

#pragma unroll
        for (int ks = 0; ks < 2; ks++) {
            uint32_t bh[2][2], bl[2][2];
            {
                int r  = wn * 16 + lrow;
                int ch = ks * 2 + lchk;
                uint32_t r0, r1, r2, r3;
                LDSM4(r0, r1, r2, r3, sB + r * 128 + 16 * ((ch)     ^ (r & 7)));
                bh[0][0] = r0; bh[0][1] = r2; bh[1][0] = r1; bh[1][1] = r3;
                LDSM4(r0, r1, r2, r3, sB + r * 128 + 16 * ((ch + 4) ^ (r & 7)));
                bl[0][0] = r0; bl[0][1] = r2; bl[1][0] = r1; bl[1][1] = r3;
            }
#pragma unroll
            for (int mf = 0; mf < 4; mf++) {
                int r  = wm * 64 + mf * 16 + lrow;
                int ch = ks * 2 + lchk;
                uint32_t ah[4], al[4];
                LDSM4(ah[0], ah[1], ah[2], ah[3],
                      sA + r * 128 + 16 * ((ch)     ^ (r & 7)));
                LDSM4(al[0], al[1], al[2], al[3],
                      sA + r * 128 + 16 * ((ch + 4) ^ (r & 7)));
#pragma unroll
                for (int nf = 0; nf < 2; nf++) {
                    MMA16816(acc[mf][nf], ah, bh[nf]);
                    MMA16816(acc[mf][nf], ah, bl[nf]);
                    MMA16816(acc[mf][nf], al, bh[nf]);
                }
            }
        }
        __syncthreads();
    }

    const int rbase = i0 + wm * 64 + (lane >> 2);
    const int cb = h * DK_ + wn * 16 + 2 * (lane & 3);
#pragma unroll
    for (int mf = 0; mf < 4; mf++) {
        int gi = rbase + mf * 16;
        size_t ro0 = ((size_t)(b * L_) + gi) * D_;
        size_t ro1 = ro0 + 8 * D_;
#pragma unroll
        for (int nf = 0; nf < 2; nf++) {
            int gj = cb + nf * 8;
            float v0 = acc[mf][nf][0], v1 = acc[mf][nf][1];
            float v2 = acc[mf][nf][2], v3 = acc[mf][nf][3];
            float h0 = bhi(v0), h1 = bhi(v1), h2 = bhi(v2), h3 = bhi(v3);
            *(unsigned*)(g_ctx_hi + ro0 + gj) = pk2(h0, h1);
            *(unsigned*)(g_ctx_lo + ro0 + gj) = pk2(v0 - h0, v1 - h1);
            *(unsigned*)(g_ctx_hi + ro1 + gj) = pk2(h2, h3);
            *(unsigned*)(g_ctx_lo + ro1 + gj) = pk2(v2 - h2, v3 - h3);
        }
    }
}

// ---------------------------------------------------------------------------
extern "C" void kernel_launch(void* const* d_in, const int* in_sizes, int n_in,
                              void* d_out, int out_size)
{
    const float* q      = (const float*)d_in[0];
    const float* k      = (const float*)d_in[1];
    const float* v      = (const float*)d_in[2];
    const unsigned char* mask = (const unsigned char*)d_in[3];
    const float* Wq     = (const float*)d_in[4];
    const float* bq     = (const float*)d_in[5];
    const float* Wk     = (const float*)d_in[6];
    const float* bk     = (const float*)d_in[7];
    const float* Wv     = (const float*)d_in[8];
    const float* bv     = (const float*)d_in[9];
    const float* Wker   = (const float*)d_in[10];
    const float* bker   = (const float*)d_in[11];
    const float* Wproj  = (const float*)d_in[15];
    const float* bproj  = (const float*)d_in[16];

    float* out      = (float*)d_out;
    float* attn     = out + (size_t)B_ * L_ * D_;
    float* one_head = attn + (size_t)B_ * H_ * L_ * L_;

    void* p;
    __nv_bfloat16 *iqh, *iql, *ikh, *ikl, *ivh, *ivl, *wh, *wl, *ch, *cl;
    __nv_bfloat16 *qsh, *qsl, *ksh, *ksl, *vsh, *vsl;
    cudaGetSymbolAddress(&p, g_inq_hi); iqh = (__nv_bfloat16*)p;
    cudaGetSymbolAddress(&p, g_inq_lo); iql = (__nv_bfloat16*)p;
    cudaGetSymbolAddress(&p, g_ink_hi); ikh = (__nv_bfloat16*)p;
    cudaGetSymbolAddress(&p, g_ink_lo); ikl = (__nv_bfloat16*)p;
    cudaGetSymbolAddress(&p, g_inv_hi); ivh = (__nv_bfloat16*)p;
    cudaGetSymbolAddress(&p, g_inv_lo); ivl = (__nv_bfloat16*)p;
    cudaGetSymbolAddress(&p, g_w_hi);   wh  = (__nv_bfloat16*)p;
    cudaGetSymbolAddress(&p, g_w_lo);   wl  = (__nv_bfloat16*)p;
    cudaGetSymbolAddress(&p, g_ctx_hi); ch  = (__nv_bfloat16*)p;
    cudaGetSymbolAddress(&p, g_ctx_lo); cl  = (__nv_bfloat16*)p;
    cudaGetSymbolAddress(&p, g_qs_hi);  qsh = (__nv_bfloat16*)p;
    cudaGetSymbolAddress(&p, g_qs_lo);  qsl = (__nv_bfloat16*)p;
    cudaGetSymbolAddress(&p, g_ks_hi);  ksh = (__nv_bfloat16*)p;
    cudaGetSymbolAddress(&p, g_ks_lo);  ksl = (__nv_bfloat16*)p;
    cudaGetSymbolAddress(&p, g_vs_hi);  vsh = (__nv_bfloat16*)p;
    cudaGetSymbolAddress(&p, g_vs_lo);  vsl = (__nv_bfloat16*)p;

    static bool attr_done = false;
    if (!attr_done) {
        cudaFuncSetAttribute(logits_mma_kernel,
            cudaFuncAttributeMaxDynamicSharedMemorySize, LOG_SMEM);
        cudaFuncSetAttribute(gemm_mma_nt,
            cudaFuncAttributeMaxDynamicSharedMemorySize, GM_SMEM);
        cudaFuncSetAttribute(gemm_mma_split,
            cudaFuncAttributeMaxDynamicSharedMemorySize, GM_SMEM);
        attr_done = true;
    }

    const int M = B_ * L_;        // 8192
    const int NE = M * D_;
    const int NW = D_ * D_;
    dim3 blk(256);

    // 0) splits + weight prep (fused launches)
    conv_split3_kernel<<<dim3((NE/8 + 255)/256, 3), 256>>>(q, k, v, NE/8);
    conv_split4_kernel<<<dim3((NW/8 + 255)/256, 4), 256>>>(Wq, Wk, Wv, Wproj, NW/8);
    wker_prep_kernel<<<(H_*WKN*8 + 255)/256, 256>>>(Wker);
    bcat_kernel<<<(H_*WKN + 255)/256, 256>>>(bker);

    // 1) projections (tensor cores) -> bf16 hi/lo directly (2-stage, proven)
    gemm_mma_split<<<dim3(D_/128, M/128), blk, GM_SMEM>>>(iqh, iql, wh,        wl,        bq, qsh, qsl);
    gemm_mma_split<<<dim3(D_/128, M/128), blk, GM_SMEM>>>(ikh, ikl, wh + NW,   wl + NW,   bk, ksh, ksl);
    gemm_mma_split<<<dim3(D_/128, M/128), blk, GM_SMEM>>>(ivh, ivl, wh + 2*NW, wl + 2*NW, bv, vsh, vsl);

    // 2) operand prep (no Kcat materialization anymore)
    qcat_mma_kernel<<<dim3(WKN/128, L_/128, B_*H_), blk>>>();
    vt_kernel<<<dim3(L_/128, B_*H_), blk>>>();

    // 3) tensor-core logits (B = in-smem shifted k_s panel) -> attn region
    logits_mma_kernel<<<dim3(L_/128, L_/128, B_*H_), 256, LOG_SMEM>>>(attn);

    // 4) softmax in place (+ one_head copy)
    softmax_kernel<<<B_*H_*L_, 256>>>(attn, mask, one_head);

    // 5) ctx = attn @ v_s -> g_ctx hi/lo
    ctx_mma_kernel<<<dim3(L_/128, B_*H_), blk>>>(attn);

    // 6) out = ctx @ Wproj^T + bproj (2-stage, proven)
    gemm_mma_nt<<<dim3(D_/128, M/128), blk, GM_SMEM>>>(ch, cl, wh + 3*NW, wl + 3*NW, bproj, out, D_, D_);
}

// round 15
// speedup vs baseline: 1.0762x; 1.0071x over previous
#include <cuda_runtime.h>
#include <cuda_bf16.h>
#include <cstdint>

#define B_   8
#define L_   1024
#define D_   512
#define H_   8
#define DK_  64
#define KW_  7
#define PAD_ 3
#define NCAT 448    /* KW*DK */
#define WKN  512    /* padded Wker N for qcat GEMM */

// ---------------- scratch (device globals; no runtime allocation) ----------
__device__ float g_bcat[H_*WKN];
// q/k/v_s bf16 split (written directly by the projections), layout [B*L, 512]
__device__ __align__(16) __nv_bfloat16 g_qs_hi[B_*L_*D_];
__device__ __align__(16) __nv_bfloat16 g_qs_lo[B_*L_*D_];
__device__ __align__(16) __nv_bfloat16 g_ks_hi[B_*L_*D_];
__device__ __align__(16) __nv_bfloat16 g_ks_lo[B_*L_*D_];
__device__ __align__(16) __nv_bfloat16 g_vs_hi[B_*L_*D_];
__device__ __align__(16) __nv_bfloat16 g_vs_lo[B_*L_*D_];
// Wker permuted+padded: [h][n=0..511][d=0..63]
__device__ __align__(16) __nv_bfloat16 g_wker_hi[H_*WKN*DK_];
__device__ __align__(16) __nv_bfloat16 g_wker_lo[H_*WKN*DK_];
// Qcat bf16 hi/lo (compact stride 448)
__device__ __align__(16) __nv_bfloat16 g_qcat_hi[(size_t)B_*H_*L_*NCAT];
__device__ __align__(16) __nv_bfloat16 g_qcat_lo[(size_t)B_*H_*L_*NCAT];
// projection inputs (bf16 split)
__device__ __align__(16) __nv_bfloat16 g_inq_hi[B_*L_*D_];
__device__ __align__(16) __nv_bfloat16 g_inq_lo[B_*L_*D_];
__device__ __align__(16) __nv_bfloat16 g_ink_hi[B_*L_*D_];
__device__ __align__(16) __nv_bfloat16 g_ink_lo[B_*L_*D_];
__device__ __align__(16) __nv_bfloat16 g_inv_hi[B_*L_*D_];
__device__ __align__(16) __nv_bfloat16 g_inv_lo[B_*L_*D_];
// weights (bf16 split): slots 0=Wq 1=Wk 2=Wv 3=Wproj
__device__ __align__(16) __nv_bfloat16 g_w_hi[4*D_*D_];
__device__ __align__(16) __nv_bfloat16 g_w_lo[4*D_*D_];
// v transposed per head: [z][n=0..63][k=0..1023]
__device__ __align__(16) __nv_bfloat16 g_vt_hi[(size_t)B_*H_*DK_*L_];
__device__ __align__(16) __nv_bfloat16 g_vt_lo[(size_t)B_*H_*DK_*L_];
// ctx in bf16 split, layout [B*L, 512]
__device__ __align__(16) __nv_bfloat16 g_ctx_hi[B_*L_*D_];
__device__ __align__(16) __nv_bfloat16 g_ctx_lo[B_*L_*D_];

// ====================== baseline-PTX tensor helpers ========================
static __device__ __forceinline__ uint32_t smem_u32(const void* p){
    uint32_t a;
    asm("{ .reg .u64 t; cvta.to.shared.u64 t, %1; cvt.u32.u64 %0, t; }"
        : "=r"(a) : "l"(p));
    return a;
}
#define CP_ASYNC16(dst, src) \
    asm volatile("cp.async.cg.shared.global [%0], [%1], 16;" \
                 :: "r"(dst), "l"(src) : "memory")
#define CP_COMMIT() asm volatile("cp.async.commit_group;" ::: "memory")
#define CP_WAIT(n)  asm volatile("cp.async.wait_group %0;" :: "n"(n) : "memory")
#define LDSM4(r0, r1, r2, r3, addr) \
    asm volatile("ldmatrix.sync.aligned.m8n8.x4.shared.b16 {%0,%1,%2,%3}, [%4];" \
                 : "=r"(r0), "=r"(r1), "=r"(r2), "=r"(r3) : "r"(addr))
#define MMA16816(d, a, b) \
    asm volatile("mma.sync.aligned.m16n8k16.row.col.f32.bf16.bf16.f32 " \
                 "{%0,%1,%2,%3},{%4,%5,%6,%7},{%8,%9},{%0,%1,%2,%3};" \
                 : "+f"((d)[0]), "+f"((d)[1]), "+f"((d)[2]), "+f"((d)[3]) \
                 : "r"((a)[0]), "r"((a)[1]), "r"((a)[2]), "r"((a)[3]), \
                   "r"((b)[0]), "r"((b)[1]))

static __device__ __forceinline__ unsigned pk2(float a, float b){
    __nv_bfloat162 t = __floats2bfloat162_rn(a, b);
    return *reinterpret_cast<unsigned*>(&t);
}
static __device__ __forceinline__ float bhi(float x){
    return __bfloat162float(__float2bfloat16_rn(x));
}

// ---------------------------------------------------------------------------
// conv_split3: fp32 -> bf16 hi/lo for q,k,v inputs in one launch (y = slot)
// ---------------------------------------------------------------------------
__global__ __launch_bounds__(256) void conv_split3_kernel(
    const float* __restrict__ s0, const float* __restrict__ s1,
    const float* __restrict__ s2, int n8)
{
    int i = blockIdx.x * 256 + threadIdx.x;
    if (i >= n8) return;
    const float* src; __nv_bfloat16 *dh, *dl;
    if (blockIdx.y == 0)      { src = s0; dh = g_inq_hi; dl = g_inq_lo; }
    else if (blockIdx.y == 1) { src = s1; dh = g_ink_hi; dl = g_ink_lo; }
    else                      { src = s2; dh = g_inv_hi; dl = g_inv_lo; }
    const float4* s = (const float4*)(src + (size_t)i * 8);
    float4 v0 = s[0], v1 = s[1];
    float f[8] = {v0.x, v0.y, v0.z, v0.w, v1.x, v1.y, v1.z, v1.w};
    float hh[8], ll[8];
#pragma unroll
    for (int e = 0; e < 8; e++) { hh[e] = bhi(f[e]); ll[e] = f[e] - hh[e]; }
    *(uint4*)(dh + (size_t)i * 8) = make_uint4(pk2(hh[0],hh[1]), pk2(hh[2],hh[3]),
                                               pk2(hh[4],hh[5]), pk2(hh[6],hh[7]));
    *(uint4*)(dl + (size_t)i * 8) = make_uint4(pk2(ll[0],ll[1]), pk2(ll[2],ll[3]),
                                               pk2(ll[4],ll[5]), pk2(ll[6],ll[7]));
}

// conv_split4: the 4 weight matrices into g_w slots (y = slot)
__global__ __launch_bounds__(256) void conv_split4_kernel(
    const float* __restrict__ s0, const float* __restrict__ s1,
    const float* __restrict__ s2, const float* __restrict__ s3, int n8)
{
    int i = blockIdx.x * 256 + threadIdx.x;
    if (i >= n8) return;
    const float* srcs[4] = {s0, s1, s2, s3};
    const float* src = srcs[blockIdx.y];
    size_t slot = (size_t)blockIdx.y * D_ * D_;
    const float4* s = (const float4*)(src + (size_t)i * 8);
    float4 v0 = s[0], v1 = s[1];
    float f[8] = {v0.x, v0.y, v0.z, v0.w, v1.x, v1.y, v1.z, v1.w};
    float hh[8], ll[8];
#pragma unroll
    for (int e = 0; e < 8; e++) { hh[e] = bhi(f[e]); ll[e] = f[e] - hh[e]; }
    *(uint4*)(g_w_hi + slot + (size_t)i * 8) =
        make_uint4(pk2(hh[0],hh[1]), pk2(hh[2],hh[3]),
                   pk2(hh[4],hh[5]), pk2(hh[6],hh[7]));
    *(uint4*)(g_w_lo + slot + (size_t)i * 8) =
        make_uint4(pk2(ll[0],ll[1]), pk2(ll[2],ll[3]),
                   pk2(ll[4],ll[5]), pk2(ll[6],ll[7]));
}

// ---------------------------------------------------------------------------
// wker_prep (+ folded bcat): g_wker[h][n][d] = Wker[h, n&63, n>>6, d] (n<448)
// threads with idx >= H*WKN*8 handle bcat entries instead.
// ---------------------------------------------------------------------------
__global__ __launch_bounds__(256) void wker_prep_kernel(
    const float* __restrict__ Wker, const float* __restrict__ bker)
{
    int idx = blockIdx.x * 256 + threadIdx.x;
    const int NW8 = H_ * WKN * 8;                 // 32768
    if (idx < NW8) {
        int d8 = (idx & 7) * 8;
        int n  = (idx >> 3) & (WKN - 1);
        int h  = idx >> 12;
        float f[8] = {0,0,0,0,0,0,0,0};
        if (n < NCAT) {
            int t = n >> 6, c = n & 63;
            const float* src = Wker + (((size_t)(h*DK_ + c)) * KW_ + t) * DK_ + d8;
            float4 v0 = *(const float4*)src, v1 = *(const float4*)(src + 4);
            f[0]=v0.x; f[1]=v0.y; f[2]=v0.z; f[3]=v0.w;
            f[4]=v1.x; f[5]=v1.y; f[6]=v1.z; f[7]=v1.w;
        }
        float hh[8], ll[8];
#pragma unroll
        for (int e = 0; e < 8; e++) { hh[e] = bhi(f[e]); ll[e] = f[e] - hh[e]; }
        size_t off = ((size_t)h * WKN + n) * DK_ + d8;
        *(uint4*)(g_wker_hi + off) = make_uint4(pk2(hh[0],hh[1]), pk2(hh[2],hh[3]),
                                                pk2(hh[4],hh[5]), pk2(hh[6],hh[7]));
        *(uint4*)(g_wker_lo + off) = make_uint4(pk2(ll[0],ll[1]), pk2(ll[2],ll[3]),
                                                pk2(ll[4],ll[5]), pk2(ll[6],ll[7]));
    } else {
        int n = idx - NW8;                        // 0 .. H*WKN-1
        if (n < H_ * WKN) {
            int h = n >> 9, r = n & (WKN - 1), t = r >> 6, c = r & 63;
            g_bcat[n] = (r < NCAT) ? bker[(size_t)(h*DK_ + c) * KW_ + t] : 0.f;
        }
    }
}

// ---------------------------------------------------------------------------
// 2-stage mma GEMM pieces (tile 128x128, 8 warps 2x4) -- proven config
// ---------------------------------------------------------------------------
#define GM_STAGE 32768
#define GM_SMEM  (2*GM_STAGE)

// ---------------------------------------------------------------------------
// out-projection GEMM: C[M,N] fp32 = A@B^T + bias[N].  2-stage.  2 CTAs/SM.
// ---------------------------------------------------------------------------
__global__ __launch_bounds__(256, 2) void gemm_mma_nt(
    const __nv_bfloat16* __restrict__ Ah, const __nv_bfloat16* __restrict__ Al,
    const __nv_bfloat16* __restrict__ Bh, const __nv_bfloat16* __restrict__ Bl,
    const float* __restrict__ bias, float* __restrict__ C, int K, int N)
{
    extern __shared__ char smem[];
    const uint32_t sbase = smem_u32(smem);
    const int kc = K >> 5;

    const int tid  = threadIdx.x;
    const int wid  = tid >> 5, lane = tid & 31;
    const int wm   = wid >> 2, wn = wid & 3;

    const int i0 = blockIdx.y * 128;
    const int j0 = blockIdx.x * 128;

    const __nv_bfloat16* ah = Ah + (size_t)i0 * K;
    const __nv_bfloat16* al = Al + (size_t)i0 * K;
    const __nv_bfloat16* bh_ = Bh + (size_t)j0 * K;
    const __nv_bfloat16* bl_ = Bl + (size_t)j0 * K;

    auto issue = [&](int s, int c) {
        const uint32_t sb = sbase + s * GM_STAGE;
#pragma unroll
        for (int q = 0; q < 4; q++) {
            int u  = q * 256 + tid;
            int r  = u >> 3, cj = u & 7;
            const __nv_bfloat16* src =
                (cj < 4 ? ah : al) + (size_t)r * K + c * 32 + (cj & 3) * 8;
            CP_ASYNC16(sb + r * 128 + 16 * (cj ^ (r & 7)), src);
        }
#pragma unroll
        for (int q = 0; q < 4; q++) {
            int u  = q * 256 + tid;
            int r  = u >> 3, cj = u & 7;
            const __nv_bfloat16* src =
                (cj < 4 ? bh_ : bl_) + (size_t)r * K + c * 32 + (cj & 3) * 8;
            CP_ASYNC16(sb + 16384 + r * 128 + 16 * (cj ^ (r & 7)), src);
        }
    };

    float acc[4][4][4];
#pragma unroll
    for (int i = 0; i < 4; i++)
#pragma unroll
        for (int j = 0; j < 4; j++)
#pragma unroll
            for (int e = 0; e < 4; e++) acc[i][j][e] = 0.f;

    issue(0, 0);
    CP_COMMIT();

    const int lrow = (lane & 7) + 8 * ((lane >> 3) & 1);
    const int lchk = lane >> 4;

    for (int c = 0; c < kc; c++) {
        const int s = c & 1;
        if (c + 1 < kc) { issue(s ^ 1, c + 1); CP_COMMIT(); CP_WAIT(1); }
        else            { CP_WAIT(0); }
        __syncthreads();

        const uint32_t sA = sbase + s * GM_STAGE;
        const uint32_t sB = sA + 16384;

#pragma unroll
        for (int ks = 0; ks < 2; ks++) {
            uint32_t bh[4][2], bl[4][2];
#pragma unroll
            for (int g = 0; g < 2; g++) {
                int r  = wn * 32 + g * 16 + lrow;
                int ch = ks * 2 + lchk;
                uint32_t r0, r1, r2, r3;
                LDSM4(r0, r1, r2, r3, sB + r * 128 + 16 * ((ch)     ^ (r & 7)));
                bh[2*g][0] = r0; bh[2*g][1] = r2;
                bh[2*g+1][0] = r1; bh[2*g+1][1] = r3;
                LDSM4(r0, r1, r2, r3, sB + r * 128 + 16 * ((ch + 4) ^ (r & 7)));
                bl[2*g][0] = r0; bl[2*g][1] = r2;
                bl[2*g+1][0] = r1; bl[2*g+1][1] = r3;
            }
#pragma unroll
            for (int mf = 0; mf < 4; mf++) {
                int r  = wm * 64 + mf * 16 + lrow;
                int ch = ks * 2 + lchk;
                uint32_t ah_[4], al_[4];
                LDSM4(ah_[0], ah_[1], ah_[2], ah_[3],
                      sA + r * 128 + 16 * ((ch)     ^ (r & 7)));
                LDSM4(al_[0], al_[1], al_[2], al_[3],
                      sA + r * 128 + 16 * ((ch + 4) ^ (r & 7)));
#pragma unroll
                for (int nf = 0; nf < 4; nf++) {
                    MMA16816(acc[mf][nf], ah_, bh[nf]);
                    MMA16816(acc[mf][nf], ah_, bl[nf]);
                    MMA16816(acc[mf][nf], al_, bh[nf]);
                }
            }
        }
        __syncthreads();
    }

    const int rbase = i0 + wm * 64 + (lane >> 2);
    const int cbase = j0 + wn * 32 + 2 * (lane & 3);
#pragma unroll
    for (int mf = 0; mf < 4; mf++) {
        int gi = rbase + mf * 16;
        float* row0 = C + (size_t)gi * N;
        float* row1 = row0 + 8 * N;
#pragma unroll
        for (int nf = 0; nf < 4; nf++) {
            int gj = cbase + nf * 8;
            float b0 = bias[gj], b1 = bias[gj + 1];
            *(float2*)(row0 + gj) = make_float2(acc[mf][nf][0] + b0,
                                                acc[mf][nf][1] + b1);
            *(float2*)(row1 + gj) = make_float2(acc[mf][nf][2] + b0,
                                                acc[mf][nf][3] + b1);
        }
    }
}

// ---------------------------------------------------------------------------
// batched projection GEMM writing bf16 hi/lo ONLY.  K = N = 512, 16 chunks,
// 2-stage.  grid (4, 64, 3): z selects {q, k, v} operand set.
// ---------------------------------------------------------------------------
__global__ __launch_bounds__(256, 2) void gemm_mma_split3(
    const float* __restrict__ bq, const float* __restrict__ bk,
    const float* __restrict__ bv)
{
    extern __shared__ char smem[];
    const uint32_t sbase = smem_u32(smem);
    const int K = D_;

    const int tid  = threadIdx.x;
    const int wid  = tid >> 5, lane = tid & 31;
    const int wm   = wid >> 2, wn = wid & 3;

    const int i0 = blockIdx.y * 128;
    const int j0 = blockIdx.x * 128;
    const int sel = blockIdx.z;

    const __nv_bfloat16 *Ah, *Al;
    const float* bias;
    __nv_bfloat16 *Ch, *Cl;
    size_t wslot;
    if (sel == 0) { Ah = g_inq_hi; Al = g_inq_lo; bias = bq; Ch = g_qs_hi; Cl = g_qs_lo; wslot = 0; }
    else if (sel == 1) { Ah = g_ink_hi; Al = g_ink_lo; bias = bk; Ch = g_ks_hi; Cl = g_ks_lo; wslot = (size_t)D_*D_; }
    else { Ah = g_inv_hi; Al = g_inv_lo; bias = bv; Ch = g_vs_hi; Cl = g_vs_lo; wslot = (size_t)2*D_*D_; }

    const __nv_bfloat16* ah = Ah + (size_t)i0 * K;
    const __nv_bfloat16* al = Al + (size_t)i0 * K;
    const __nv_bfloat16* bh_ = g_w_hi + wslot + (size_t)j0 * K;
    const __nv_bfloat16* bl_ = g_w_lo + wslot + (size_t)j0 * K;

    auto issue = [&](int s, int c) {
        const uint32_t sb = sbase + s * GM_STAGE;
#pragma unroll
        for (int q = 0; q < 4; q++) {
            int u  = q * 256 + tid;
            int r  = u >> 3, cj = u & 7;
            const __nv_bfloat16* src =
                (cj < 4 ? ah : al) + (size_t)r * K + c * 32 + (cj & 3) * 8;
            CP_ASYNC16(sb + r * 128 + 16 * (cj ^ (r & 7)), src);
        }
#pragma unroll
        for (int q = 0; q < 4; q++) {
            int u  = q * 256 + tid;
            int r  = u >> 3, cj = u & 7;
            const __nv_bfloat16* src =
                (cj < 4 ? bh_ : bl_) + (size_t)r * K + c * 32 + (cj & 3) * 8;
            CP_ASYNC16(sb + 16384 + r * 128 + 16 * (cj ^ (r & 7)), src);
        }
    };

    float acc[4][4][4];
#pragma unroll
    for (int i = 0; i < 4; i++)
#pragma unroll
        for (int j = 0; j < 4; j++)
#pragma unroll
            for (int e = 0; e < 4; e++) acc[i][j][e] = 0.f;

    issue(0, 0);
    CP_COMMIT();

    const int lrow = (lane & 7) + 8 * ((lane >> 3) & 1);
    const int lchk = lane >> 4;

    for (int c = 0; c < 16; c++) {
        const int s = c & 1;
        if (c + 1 < 16) { issue(s ^ 1, c + 1); CP_COMMIT(); CP_WAIT(1); }
        else            { CP_WAIT(0); }
        __syncthreads();

        const uint32_t sA = sbase + s * GM_STAGE;
        const uint32_t sB = sA + 16384;

#pragma unroll
        for (int ks = 0; ks < 2; ks++) {
            uint32_t bh[4][2], bl[4][2];
#pragma unroll
            for (int g = 0; g < 2; g++) {
                int r  = wn * 32 + g * 16 + lrow;
                int ch = ks * 2 + lchk;
                uint32_t r0, r1, r2, r3;
                LDSM4(r0, r1, r2, r3, sB + r * 128 + 16 * ((ch)     ^ (r & 7)));
                bh[2*g][0] = r0; bh[2*g][1] = r2;
                bh[2*g+1][0] = r1; bh[2*g+1][1] = r3;
                LDSM4(r0, r1, r2, r3, sB + r * 128 + 16 * ((ch + 4) ^ (r & 7)));
                bl[2*g][0] = r0; bl[2*g][1] = r2;
                bl[2*g+1][0] = r1; bl[2*g+1][1] = r3;
            }
#pragma unroll
            for (int mf = 0; mf < 4; mf++) {
                int r  = wm * 64 + mf * 16 + lrow;
                int ch = ks * 2 + lchk;
                uint32_t ah_[4], al_[4];
                LDSM4(ah_[0], ah_[1], ah_[2], ah_[3],
                      sA + r * 128 + 16 * ((ch)     ^ (r & 7)));
                LDSM4(al_[0], al_[1], al_[2], al_[3],
                      sA + r * 128 + 16 * ((ch + 4) ^ (r & 7)));
#pragma unroll
                for (int nf = 0; nf < 4; nf++) {
                    MMA16816(acc[mf][nf], ah_, bh[nf]);
                    MMA16816(acc[mf][nf], ah_, bl[nf]);
                    MMA16816(acc[mf][nf], al_, bh[nf]);
                }
            }
        }
        __syncthreads();
    }

    const int rbase = i0 + wm * 64 + (lane >> 2);
    const int cbase = j0 + wn * 32 + 2 * (lane & 3);
#pragma unroll
    for (int mf = 0; mf < 4; mf++) {
        int gi = rbase + mf * 16;
        size_t ro0 = (size_t)gi * D_, ro1 = ro0 + 8 * D_;
#pragma unroll
        for (int nf = 0; nf < 4; nf++) {
            int gj = cbase + nf * 8;
            float b0 = bias[gj], b1 = bias[gj + 1];
            float v0 = acc[mf][nf][0] + b0, v1 = acc[mf][nf][1] + b1;
            float v2 = acc[mf][nf][2] + b0, v3 = acc[mf][nf][3] + b1;
            float h0 = bhi(v0), h1 = bhi(v1), h2 = bhi(v2), h3 = bhi(v3);
            *(unsigned*)(Ch + ro0 + gj) = pk2(h0, h1);
            *(unsigned*)(Cl + ro0 + gj) = pk2(v0 - h0, v1 - h1);
            *(unsigned*)(Ch + ro1 + gj) = pk2(h2, h3);
            *(unsigned*)(Cl + ro1 + gj) = pk2(v2 - h2, v3 - h3);
        }
    }
}

// ---------------------------------------------------------------------------
// qcat via mma: per z: Qcat[1024, n<448] = q_s_head[1024,64] @ wker[512,64]^T
//   + bcat. K=64 -> 2 chunks.  grid (4, 8, 64).  compact stride 448.
// ---------------------------------------------------------------------------
__global__ __launch_bounds__(256, 2) void qcat_mma_kernel()
{
    __shared__ char smem[2 * GM_STAGE];
    const uint32_t sbase = smem_u32(smem);

    const int tid  = threadIdx.x;
    const int wid  = tid >> 5, lane = tid & 31;
    const int wm   = wid >> 2, wn = wid & 3;

    const int z  = blockIdx.z;
    const int b = z >> 3, h = z & 7;
    const int i0 = blockIdx.y * 128;
    const int n0 = blockIdx.x * 128;

    const __nv_bfloat16* ah = g_qs_hi + ((size_t)(b*L_ + i0)) * D_ + h*DK_;
    const __nv_bfloat16* al = g_qs_lo + ((size_t)(b*L_ + i0)) * D_ + h*DK_;
    const __nv_bfloat16* bh_ = g_wker_hi + ((size_t)h * WKN + n0) * DK_;
    const __nv_bfloat16* bl_ = g_wker_lo + ((size_t)h * WKN + n0) * DK_;

    auto issue = [&](int s, int c) {
        const uint32_t sb = sbase + s * GM_STAGE;
#pragma unroll
        for (int q = 0; q < 4; q++) {
            int u  = q * 256 + tid;
            int r  = u >> 3, cj = u & 7;
            const __nv_bfloat16* src =
                (cj < 4 ? ah : al) + (size_t)r * D_ + c * 32 + (cj & 3) * 8;
            CP_ASYNC16(sb + r * 128 + 16 * (cj ^ (r & 7)), src);
        }
#pragma unroll
        for (int q = 0; q < 4; q++) {
            int u  = q * 256 + tid;
            int r  = u >> 3, cj = u & 7;
            const __nv_bfloat16* src =
                (cj < 4 ? bh_ : bl_) + (size_t)r * DK_ + c * 32 + (cj & 3) * 8;
            CP_ASYNC16(sb + 16384 + r * 128 + 16 * (cj ^ (r & 7)), src);
        }
    };

    float acc[4][4][4];
#pragma unroll
    for (int i = 0; i < 4; i++)
#pragma unroll
        for (int j = 0; j < 4; j++)
#pragma unroll
            for (int e = 0; e < 4; e++) acc[i][j][e] = 0.f;

    issue(0, 0);
    CP_COMMIT();

    const int lrow = (lane & 7) + 8 * ((lane >> 3) & 1);
    const int lchk = lane >> 4;

    for (int c = 0; c < 2; c++) {
        const int s = c & 1;
        if (c == 0) { issue(1, 1); CP_COMMIT(); CP_WAIT(1); }
        else        { CP_WAIT(0); }
        __syncthreads();

        const uint32_t sA = sbase + s * GM_STAGE;
        const uint32_t sB = sA + 16384;

#pragma unroll
        for (int ks = 0; ks < 2; ks++) {
            uint32_t bh[4][2], bl[4][2];
#pragma unroll
            for (int g = 0; g < 2; g++) {
                int r  = wn * 32 + g * 16 + lrow;
                int ch = ks * 2 + lchk;
                uint32_t r0, r1, r2, r3;
                LDSM4(r0, r1, r2, r3, sB + r * 128 + 16 * ((ch)     ^ (r & 7)));
                bh[2*g][0] = r0; bh[2*g][1] = r2;
                bh[2*g+1][0] = r1; bh[2*g+1][1] = r3;
                LDSM4(r0, r1, r2, r3, sB + r * 128 + 16 * ((ch + 4) ^ (r & 7)));
                bl[2*g][0] = r0; bl[2*g][1] = r2;
                bl[2*g+1][0] = r1; bl[2*g+1][1] = r3;
            }
#pragma unroll
            for (int mf = 0; mf < 4; mf++) {
                int r  = wm * 64 + mf * 16 + lrow;
                int ch = ks * 2 + lchk;
                uint32_t ah_[4], al_[4];
                LDSM4(ah_[0], ah_[1], ah_[2], ah_[3],
                      sA + r * 128 + 16 * ((ch)     ^ (r & 7)));
                LDSM4(al_[0], al_[1], al_[2], al_[3],
                      sA + r * 128 + 16 * ((ch + 4) ^ (r & 7)));
#pragma unroll
                for (int nf = 0; nf < 4; nf++) {
                    MMA16816(acc[mf][nf], ah_, bh[nf]);
                    MMA16816(acc[mf][nf], ah_, bl[nf]);
                    MMA16816(acc[mf][nf], al_, bh[nf]);
                }
            }
        }
        __syncthreads();
    }

    __nv_bfloat16* Ch = g_qcat_hi + (size_t)z * L_ * NCAT;
    __nv_bfloat16* Cl = g_qcat_lo + (size_t)z * L_ * NCAT;
    const int rbase = i0 + wm * 64 + (lane >> 2);
    const int cbase = n0 + wn * 32 + 2 * (lane & 3);
#pragma unroll
    for (int mf = 0; mf < 4; mf++) {
        int gi = rbase + mf * 16;
        size_t ro0 = (size_t)gi * NCAT, ro1 = ro0 + 8 * NCAT;
#pragma unroll
        for (int nf = 0; nf < 4; nf++) {
            int gj = cbase + nf * 8;
            if (gj >= NCAT) continue;
            float b0 = g_bcat[h*WKN + gj], b1 = g_bcat[h*WKN + gj + 1];
            float v0 = acc[mf][nf][0] + b0, v1 = acc[mf][nf][1] + b1;
            float v2 = acc[mf][nf][2] + b0, v3 = acc[mf][nf][3] + b1;
            float h0 = bhi(v0), h1 = bhi(v1), h2 = bhi(v2), h3 = bhi(v3);
            *(unsigned*)(Ch + ro0 + gj) = pk2(h0, h1);
            *(unsigned*)(Cl + ro0 + gj) = pk2(v0 - h0, v1 - h1);
            *(unsigned*)(Ch + ro1 + gj) = pk2(h2, h3);
            *(unsigned*)(Cl + ro1 + gj) = pk2(v2 - h2, v3 - h3);
        }
    }
}

// ---------------------------------------------------------------------------
// vt transpose (bf16): vt[z][n][k] = v_s[b][k][h*64+n], hi/lo packed in smem.
// ---------------------------------------------------------------------------
__global__ __launch_bounds__(256) void vt_kernel()
{
    __shared__ uint32_t t[128][65];   // hi | lo<<16 per element
    const int z = blockIdx.y;
    const int b = z >> 3, h = z & 7;
    const int k0 = blockIdx.x * 128;
    const int tid = threadIdx.x;

#pragma unroll
    for (int q = 0; q < 4; q++) {          // 1024 units of 8 elems
        int u = q * 256 + tid;
        int r = u >> 3, c8 = (u & 7) * 8;
        size_t so = ((size_t)(b*L_ + k0 + r)) * D_ + h*DK_ + c8;
        uint4 vh = *(const uint4*)(g_vs_hi + so);
        uint4 vl = *(const uint4*)(g_vs_lo + so);
        uint32_t hw[4] = {vh.x, vh.y, vh.z, vh.w};
        uint32_t lw[4] = {vl.x, vl.y, vl.z, vl.w};
#pragma unroll
        for (int e = 0; e < 4; e++) {
            t[r][c8 + 2*e]     = (hw[e] & 0xffffu) | (lw[e] << 16);
            t[r][c8 + 2*e + 1] = (hw[e] >> 16)     | (lw[e] & 0xffff0000u);
        }
    }
    __syncthreads();

#pragma unroll
    for (int q = 0; q < 4; q++) {          // 64 n x 16 k-groups of 8
        int u = q * 256 + tid;
        int n = u >> 4, k8 = (u & 15) * 8;
        uint32_t hi4[4], lo4[4];
#pragma unroll
        for (int e = 0; e < 4; e++) {
            uint32_t a = t[k8 + 2*e][n];
            uint32_t c = t[k8 + 2*e + 1][n];
            hi4[e] = (a & 0xffffu) | ((c & 0xffffu) << 16);
            lo4[e] = (a >> 16)     | (c & 0xffff0000u);
        }
        size_t off = (size_t)z * DK_ * L_ + (size_t)n * L_ + k0 + k8;
        *(uint4*)(g_vt_hi + off) = make_uint4(hi4[0], hi4[1], hi4[2], hi4[3]);
        *(uint4*)(g_vt_lo + off) = make_uint4(lo4[0], lo4[1], lo4[2], lo4[3]);
    }
}

// ---------------------------------------------------------------------------
// Logits v3 (R14 winner): 128x128 tile, A=Qcat 3-stage streamed,
// B = k_s panel loaded once into smem with conv t-shift as smem row offset.
// ---------------------------------------------------------------------------
#define LOG_ASTAGE   16384
#define LOG_PANEL    17152              /* 134 rows * 128 B */
#define LOG_PANEL_HI (3*LOG_ASTAGE)
#define LOG_PANEL_LO (LOG_PANEL_HI + LOG_PANEL)
#define LOG_SMEM     (LOG_PANEL_LO + LOG_PANEL)

__global__ __launch_bounds__(256, 2) void logits_mma_kernel(float* __restrict__ attn)
{
    extern __shared__ char smem[];
    const uint32_t sbase = smem_u32(smem);
    const uint32_t pHI = sbase + LOG_PANEL_HI;
    const uint32_t pLO = sbase + LOG_PANEL_LO;

    const int tid  = threadIdx.x;
    const int wid  = tid >> 5, lane = tid & 31;
    const int wm   = wid >> 2, wn = wid & 3;

    const int z  = blockIdx.z;
    const int b = z >> 3, h = z & 7;
    const int i0 = blockIdx.y * 128;
    const int j0 = blockIdx.x * 128;

    const __nv_bfloat16* qh = g_qcat_hi + (size_t)z * L_ * NCAT + (size_t)i0 * NCAT;
    const __nv_bfloat16* ql = g_qcat_lo + (size_t)z * L_ * NCAT + (size_t)i0 * NCAT;
    const __nv_bfloat16* ksh = g_ks_hi + ((size_t)(b*L_)) * D_ + h*DK_;
    const __nv_bfloat16* ksl = g_ks_lo + ((size_t)(b*L_)) * D_ + h*DK_;

    auto issueA = [&](int s, int c) {
        const uint32_t sb = sbase + s * LOG_ASTAGE;
#pragma unroll
        for (int q = 0; q < 4; q++) {
            int u  = q * 256 + tid;
            int r  = u >> 3, cj = u & 7;
            const __nv_bfloat16* src =
                (cj < 4 ? qh : ql) + (size_t)r * NCAT + c * 32 + (cj & 3) * 8;
            CP_ASYNC16(sb + r * 128 + 16 * (cj ^ (r & 7)), src);
        }
    };

    // ---- panel load: rows j0-3 .. j0+130, 8 groups of 8 cols each ----
    for (int u = tid; u < 134 * 8; u += 256) {
        int r  = u >> 3, g8 = u & 7;
        int j  = j0 + r - PAD_;
        uint32_t dh = pHI + r * 128 + 16 * (g8 ^ (r & 7));
        uint32_t dl = pLO + r * 128 + 16 * (g8 ^ (r & 7));
        if (j >= 0 && j < L_) {
            CP_ASYNC16(dh, ksh + (size_t)j * D_ + g8 * 8);
            CP_ASYNC16(dl, ksl + (size_t)j * D_ + g8 * 8);
        } else {
            *(uint4*)(smem + (dh - sbase)) = make_uint4(0,0,0,0);
            *(uint4*)(smem + (dl - sbase)) = make_uint4(0,0,0,0);
        }
    }
    issueA(0, 0); CP_COMMIT();   // group: panel + A0
    issueA(1, 1); CP_COMMIT();   // group: A1

    float acc[4][4][4];
#pragma unroll
    for (int i = 0; i < 4; i++)
#pragma unroll
        for (int j = 0; j < 4; j++)
#pragma unroll
            for (int e = 0; e < 4; e++) acc[i][j][e] = 0.f;

    const int lrow = (lane & 7) + 8 * ((lane >> 3) & 1);
    const int lchk = lane >> 4;

    int stage = 0;
    for (int c = 0; c < 14; c++) {
        if (c + 2 < 14) {
            int s2 = stage + 2; if (s2 >= 3) s2 -= 3;
            issueA(s2, c + 2); CP_COMMIT(); CP_WAIT(2);
        } else if (c + 1 < 14) { CP_WAIT(1); }
        else                   { CP_WAIT(0); }
        __syncthreads();

        const uint32_t sA = sbase + stage * LOG_ASTAGE;
        const int t    = c >> 1;
        const int half = c & 1;

#pragma unroll
        for (int ks = 0; ks < 2; ks++) {
            uint32_t bh[4][2], bl[4][2];
#pragma unroll
            for (int g = 0; g < 2; g++) {
                int rr = wn * 32 + g * 16 + lrow + t;        // shifted panel row
                int g8 = half * 4 + ks * 2 + lchk;
                uint32_t r0, r1, r2, r3;
                LDSM4(r0, r1, r2, r3, pHI + rr * 128 + 16 * (g8 ^ (rr & 7)));
                bh[2*g][0] = r0; bh[2*g][1] = r2;
                bh[2*g+1][0] = r1; bh[2*g+1][1] = r3;
                LDSM4(r0, r1, r2, r3, pLO + rr * 128 + 16 * (g8 ^ (rr & 7)));
                bl[2*g][0] = r0; bl[2*g][1] = r2;
                bl[2*g+1][0] = r1; bl[2*g+1][1] = r3;
            }
#pragma unroll
            for (int mf = 0; mf < 4; mf++) {
                int r  = wm * 64 + mf * 16 + lrow;
                int ch = ks * 2 + lchk;
                uint32_t ah[4], al[4];
                LDSM4(ah[0], ah[1], ah[2], ah[3],
                      sA + r * 128 + 16 * ((ch)     ^ (r & 7)));
                LDSM4(al[0], al[1], al[2], al[3],
                      sA + r * 128 + 16 * ((ch + 4) ^ (r & 7)));
#pragma unroll
                for (int nf = 0; nf < 4; nf++) {
                    MMA16816(acc[mf][nf], ah, bh[nf]);
                    MMA16816(acc[mf][nf], ah, bl[nf]);
                    MMA16816(acc[mf][nf], al, bh[nf]);
                }
            }
        }
        __syncthreads();
        stage++; if (stage == 3) stage = 0;
    }

    const int rbase = i0 + wm * 64 + (lane >> 2);
    const int cbase = j0 + wn * 32 + 2 * (lane & 3);
#pragma unroll
    for (int mf = 0; mf < 4; mf++) {
        int gi0 = rbase + mf * 16;
        float* row0 = attn + ((size_t)z * L_ + gi0) * L_;
        float* row1 = row0 + 8 * L_;
#pragma unroll
        for (int nf = 0; nf < 4; nf++) {
            int gj = cbase + nf * 8;
            *(float2*)(row0 + gj) = make_float2(acc[mf][nf][0]*0.125f,
                                                acc[mf][nf][1]*0.125f);
            *(float2*)(row1 + gj) = make_float2(acc[mf][nf][2]*0.125f,
                                                acc[mf][nf][3]*0.125f);
        }
    }
}

// ---------------------------------------------------------------------------
// Row softmax in-place on attn; mask; head-0 duplicate.
// ---------------------------------------------------------------------------
__global__ __launch_bounds__(256) void softmax_kernel(
    float* __restrict__ attn, const unsigned char* __restrict__ mask,
    float* __restrict__ one_head)
{
    const int r = blockIdx.x;
    const int i = r & (L_-1);
    const int bh = r >> 10;
    const int h = bh & (H_-1), b = bh >> 3;
    float* row = attn + (size_t)r * L_;
    const unsigned char* mrow = mask + ((size_t)(b*L_ + i)) * L_;
    const int t4 = threadIdx.x * 4;

    float4 v = *(const float4*)(row + t4);
    uchar4 m = *(const uchar4*)(mrow + t4);
    float x0 = m.x ? -INFINITY : v.x;
    float x1 = m.y ? -INFINITY : v.y;
    float x2 = m.z ? -INFINITY : v.z;
    float x3 = m.w ? -INFINITY : v.w;

    __shared__ float sm[8], ss[8];
    float mx = fmaxf(fmaxf(x0, x1), fmaxf(x2, x3));
#pragma unroll
    for (int o = 16; o; o >>= 1) mx = fmaxf(mx, __shfl_xor_sync(0xffffffffu, mx, o));
    if ((threadIdx.x & 31) == 0) sm[threadIdx.x >> 5] = mx;
    __syncthreads();
    if (threadIdx.x < 32) {
        float t = (threadIdx.x < 8) ? sm[threadIdx.x] : -INFINITY;
#pragma unroll
        for (int o = 4; o; o >>= 1) t = fmaxf(t, __shfl_xor_sync(0xffffffffu, t, o));
        if (threadIdx.x == 0) sm[0] = t;
    }
    __syncthreads();
    mx = sm[0];

    float e0 = __expf(x0 - mx), e1 = __expf(x1 - mx);
    float e2 = __expf(x2 - mx), e3 = __expf(x3 - mx);
    float s = (e0 + e1) + (e2 + e3);
#pragma unroll
    for (int o = 16; o; o >>= 1) s += __shfl_xor_sync(0xffffffffu, s, o);
    if ((threadIdx.x & 31) == 0) ss[threadIdx.x >> 5] = s;
    __syncthreads();
    if (threadIdx.x < 32) {
        float t = (threadIdx.x < 8) ? ss[threadIdx.x] : 0.f;
#pragma unroll
        for (int o = 4; o; o >>= 1) t += __shfl_xor_sync(0xffffffffu, t, o);
        if (threadIdx.x == 0) ss[0] = t;
    }
    __syncthreads();
    float inv = 1.0f / ss[0];

    float4 o = make_float4(e0*inv, e1*inv, e2*inv, e3*inv);
    *(float4*)(row + t4) = o;
    if (h == 0)
        *(float4*)(one_head + ((size_t)(b*L_ + i)) * L_ + t4) = o;
}

// ---------------------------------------------------------------------------
// ctx via mma: per (b,h): C[1024,64] = attn @ v_head.
// ---------------------------------------------------------------------------
#define CTX_STAGE 24576

__global__ __launch_bounds__(256, 2) void ctx_mma_kernel(const float* __restrict__ attn)
{
    __shared__ char smem[2 * CTX_STAGE];
    const uint32_t sbase = smem_u32(smem);

    const int tid  = threadIdx.x;
    const int wid  = tid >> 5, lane = tid & 31;
    const int wm   = wid >> 2, wn = wid & 3;

    const int z  = blockIdx.y;
    const int b = z >> 3, h = z & 7;
    const int i0 = blockIdx.x * 128;

    const float* A = attn + ((size_t)z * L_ + i0) * L_;
    const __nv_bfloat16* vh = g_vt_hi + (size_t)z * DK_ * L_;
    const __nv_bfloat16* vl = g_vt_lo + (size_t)z * DK_ * L_;

    auto issueB = [&](int s, int c) {
        const uint32_t sb = sbase + s * CTX_STAGE + 16384;
#pragma unroll
        for (int q = 0; q < 2; q++) {
            int u  = q * 256 + tid;
            int r  = u >> 3, cj = u & 7;
            const __nv_bfloat16* src =
                (cj < 4 ? vh : vl) + (size_t)r * L_ + c * 32 + (cj & 3) * 8;
            CP_ASYNC16(sb + r * 128 + 16 * (cj ^ (r & 7)), src);
        }
    };
    float fa[2][8];
    auto ldgA = [&](int c) {
#pragma unroll
        for (int q = 0; q < 2; q++) {
            int u = q * 256 + tid;
            int r = u >> 2, seg = u & 3;
            const float4* p = (const float4*)(A + (size_t)r * L_ + c * 32 + seg * 8);
            float4 v0 = p[0], v1 = p[1];
            fa[q][0]=v0.x; fa[q][1]=v0.y; fa[q][2]=v0.z; fa[q][3]=v0.w;
            fa[q][4]=v1.x; fa[q][5]=v1.y; fa[q][6]=v1.z; fa[q][7]=v1.w;
        }
    };
    auto stsA = [&](int s) {
#pragma unroll
        for (int q = 0; q < 2; q++) {
            int u = q * 256 + tid;
            int r = u >> 2, seg = u & 3;
            float hh[8], ll[8];
#pragma unroll
            for (int e = 0; e < 8; e++) { hh[e] = bhi(fa[q][e]); ll[e] = fa[q][e] - hh[e]; }
            *(uint4*)(smem + s * CTX_STAGE + r * 128 + 16 * ((seg)     ^ (r & 7))) =
                make_uint4(pk2(hh[0],hh[1]), pk2(hh[2],hh[3]),
                           pk2(hh[4],hh[5]), pk2(hh[6],hh[7]));
            *(uint4*)(smem + s * CTX_STAGE + r * 128 + 16 * ((seg + 4) ^ (r & 7))) =
                make_uint4(pk2(ll[0],ll[1]), pk2(ll[2],ll[3]),
                           pk2(ll[4],ll[5]), pk2(ll[6],ll[7]));
        }
    };

    float acc[4][2][4];
#pragma unroll
    for (int i = 0; i < 4; i++)
#pragma unroll
        for (int j = 0; j < 2; j++)
#pragma unroll
            for (int e = 0; e < 4; e++) acc[i][j][e] = 0.f;

    ldgA(0);
    issueB(0, 0); CP_COMMIT();

    const int lrow = (lane & 7) + 8 * ((lane >> 3) & 1);
    const int lchk = lane >> 4;

    for (int c = 0; c < 32; c++) {
        const int s = c & 1;
        stsA(s);
        if (c + 1 < 32) {
            ldgA(c + 1);
            issueB(s ^ 1, c + 1); CP_COMMIT(); CP_WAIT(1);
        } else {
            CP_WAIT(0);
        }
        __syncthreads();

        const uint32_t sA = sbase + s * CTX_STAGE;
        const uint32_t sB = sA + 16384;

#pragma unroll
        for (int ks = 0; ks < 2; ks++) {
            uint32_t bh[2][2], bl[2][2];
            {
                int r  = wn * 16 + lrow;
                int ch = ks * 2 + lchk;
                uint32_t r0, r1, r2, r3;
                LDSM4(r0, r1, r2, r3, sB + r * 128 + 16 * ((ch)     ^ (r & 7)));
                bh[0][0] = r0; bh[0][1] = r2; bh[1][0] = r1; bh[1][1] = r3;
                LDSM4(r0, r1, r2, r3, sB + r * 128 + 16 * ((ch + 4) ^ (r & 7)));
                bl[0][0] = r0; bl[0][1] = r2; bl[1][0] = r1; bl[1][1] = r3;
            }
#pragma unroll
            for (int mf = 0; mf < 4; mf++) {
                int r  = wm * 64 + mf * 16 + lrow;
                int ch = ks * 2 + lchk;
                uint32_t ah[4], al[4];
                LDSM4(ah[0], ah[1], ah[2], ah[3],
                      sA + r * 128 + 16 * ((ch)     ^ (r & 7)));
                LDSM4(al[0], al[1], al[2], al[3],
                      sA + r * 128 + 16 * ((ch + 4) ^ (r & 7)));
#pragma unroll
                for (int nf = 0; nf < 2; nf++) {
                    MMA16816(acc[mf][nf], ah, bh[nf]);
                    MMA16816(acc[mf][nf], ah, bl[nf]);
                    MMA16816(acc[mf][nf], al, bh[nf]);
                }
            }
        }
        __syncthreads();
    }

    const int rbase = i0 + wm * 64 + (lane >> 2);
    const int cb = h * DK_ + wn * 16 + 2 * (lane & 3);
#pragma unroll
    for (int mf = 0; mf < 4; mf++) {
        int gi = rbase + mf * 16;
        size_t ro0 = ((size_t)(b * L_) + gi) * D_;
        size_t ro1 = ro0 + 8 * D_;
#pragma unroll
        for (int nf = 0; nf < 2; nf++) {
            int gj = cb + nf * 8;
            float v0 = acc[mf][nf][0], v1 = acc[mf][nf][1];
            float v2 = acc[mf][nf][2], v3 = acc[mf][nf][3];
            float h0 = bhi(v0), h1 = bhi(v1), h2 = bhi(v2), h3 = bhi(v3);
            *(unsigned*)(g_ctx_hi + ro0 + gj) = pk2(h0, h1);
            *(unsigned*)(g_ctx_lo + ro0 + gj) = pk2(v0 - h0, v1 - h1);
            *(unsigned*)(g_ctx_hi + ro1 + gj) = pk2(h2, h3);
            *(unsigned*)(g_ctx_lo + ro1 + gj) = pk2(v2 - h2, v3 - h3);
        }
    }
}

// ---------------------------------------------------------------------------
extern "C" void kernel_launch(void* const* d_in, const int* in_sizes, int n_in,
                              void* d_out, int out_size)
{
    const float* q      = (const float*)d_in[0];
    const float* k      = (const float*)d_in[1];
    const float* v      = (const float*)d_in[2];
    const unsigned char* mask = (const unsigned char*)d_in[3];
    const float* Wq     = (const float*)d_in[4];
    const float* bq     = (const float*)d_in[5];
    const float* Wk     = (const float*)d_in[6];
    const float* bk     = (const float*)d_in[7];
    const float* Wv     = (const float*)d_in[8];
    const float* bv     = (const float*)d_in[9];
    const float* Wker   = (const float*)d_in[10];
    const float* bker   = (const float*)d_in[11];
    const float* Wproj  = (const float*)d_in[15];
    const float* bproj  = (const float*)d_in[16];

    float* out      = (float*)d_out;
    float* attn     = out + (size_t)B_ * L_ * D_;
    float* one_head = attn + (size_t)B_ * H_ * L_ * L_;

    void* p;
    __nv_bfloat16 *wh, *wl, *ch, *cl;
    cudaGetSymbolAddress(&p, g_w_hi);   wh  = (__nv_bfloat16*)p;
    cudaGetSymbolAddress(&p, g_w_lo);   wl  = (__nv_bfloat16*)p;
    cudaGetSymbolAddress(&p, g_ctx_hi); ch  = (__nv_bfloat16*)p;
    cudaGetSymbolAddress(&p, g_ctx_lo); cl  = (__nv_bfloat16*)p;

    static bool attr_done = false;
    if (!attr_done) {
        cudaFuncSetAttribute(logits_mma_kernel,
            cudaFuncAttributeMaxDynamicSharedMemorySize, LOG_SMEM);
        cudaFuncSetAttribute(gemm_mma_nt,
            cudaFuncAttributeMaxDynamicSharedMemorySize, GM_SMEM);
        cudaFuncSetAttribute(gemm_mma_split3,
            cudaFuncAttributeMaxDynamicSharedMemorySize, GM_SMEM);
        attr_done = true;
    }

    const int M = B_ * L_;        // 8192
    const int NE = M * D_;
    const int NW = D_ * D_;
    dim3 blk(256);

    // 0) splits + weight prep (fused launches; bcat folded into wker_prep)
    conv_split3_kernel<<<dim3((NE/8 + 255)/256, 3), 256>>>(q, k, v, NE/8);
    conv_split4_kernel<<<dim3((NW/8 + 255)/256, 4), 256>>>(Wq, Wk, Wv, Wproj, NW/8);
    wker_prep_kernel<<<(H_*WKN*8 + H_*WKN + 255)/256, 256>>>(Wker, bker);

    // 1) q/k/v projections in ONE batched launch (768 CTAs)
    gemm_mma_split3<<<dim3(D_/128, M/128, 3), blk, GM_SMEM>>>(bq, bk, bv);

    // 2) operand prep
    qcat_mma_kernel<<<dim3(WKN/128, L_/128, B_*H_), blk>>>();
    vt_kernel<<<dim3(L_/128, B_*H_), blk>>>();

    // 3) tensor-core logits (B = in-smem shifted k_s panel) -> attn region
    logits_mma_kernel<<<dim3(L_/128, L_/128, B_*H_), 256, LOG_SMEM>>>(attn);

    // 4) softmax in place (+ one_head copy)
    softmax_kernel<<<B_*H_*L_, 256>>>(attn, mask, one_head);

    // 5) ctx = attn @ v_s -> g_ctx hi/lo
    ctx_mma_kernel<<<dim3(L_/128, B_*H_), blk>>>(attn);

    // 6) out = ctx @ Wproj^T + bproj
    gemm_mma_nt<<<dim3(D_/128, M/128), blk, GM_SMEM>>>(ch, cl, wh + 3*NW, wl + 3*NW, bproj, out, D_, D_);
}

// round 16
// speedup vs baseline: 1.0788x; 1.0025x over previous
#include <cuda_runtime.h>
#include <cuda_bf16.h>
#include <cstdint>

#define B_   8
#define L_   1024
#define D_   512
#define H_   8
#define DK_  64
#define KW_  7
#define PAD_ 3
#define NCAT 448    /* KW*DK */
#define WKN  512    /* padded Wker N for qcat GEMM */

// ---------------- scratch (device globals; no runtime allocation) ----------
__device__ float g_bcat[H_*WKN];
__device__ __align__(16) __nv_bfloat16 g_qs_hi[B_*L_*D_];
__device__ __align__(16) __nv_bfloat16 g_qs_lo[B_*L_*D_];
__device__ __align__(16) __nv_bfloat16 g_ks_hi[B_*L_*D_];
__device__ __align__(16) __nv_bfloat16 g_ks_lo[B_*L_*D_];
__device__ __align__(16) __nv_bfloat16 g_vs_hi[B_*L_*D_];
__device__ __align__(16) __nv_bfloat16 g_vs_lo[B_*L_*D_];
__device__ __align__(16) __nv_bfloat16 g_wker_hi[H_*WKN*DK_];
__device__ __align__(16) __nv_bfloat16 g_wker_lo[H_*WKN*DK_];
__device__ __align__(16) __nv_bfloat16 g_qcat_hi[(size_t)B_*H_*L_*NCAT];
__device__ __align__(16) __nv_bfloat16 g_qcat_lo[(size_t)B_*H_*L_*NCAT];
__device__ __align__(16) __nv_bfloat16 g_inq_hi[B_*L_*D_];
__device__ __align__(16) __nv_bfloat16 g_inq_lo[B_*L_*D_];
__device__ __align__(16) __nv_bfloat16 g_ink_hi[B_*L_*D_];
__device__ __align__(16) __nv_bfloat16 g_ink_lo[B_*L_*D_];
__device__ __align__(16) __nv_bfloat16 g_inv_hi[B_*L_*D_];
__device__ __align__(16) __nv_bfloat16 g_inv_lo[B_*L_*D_];
__device__ __align__(16) __nv_bfloat16 g_w_hi[4*D_*D_];
__device__ __align__(16) __nv_bfloat16 g_w_lo[4*D_*D_];
__device__ __align__(16) __nv_bfloat16 g_vt_hi[(size_t)B_*H_*DK_*L_];
__device__ __align__(16) __nv_bfloat16 g_vt_lo[(size_t)B_*H_*DK_*L_];
__device__ __align__(16) __nv_bfloat16 g_ctx_hi[B_*L_*D_];
__device__ __align__(16) __nv_bfloat16 g_ctx_lo[B_*L_*D_];

// ====================== baseline-PTX tensor helpers ========================
static __device__ __forceinline__ uint32_t smem_u32(const void* p){
    uint32_t a;
    asm("{ .reg .u64 t; cvta.to.shared.u64 t, %1; cvt.u32.u64 %0, t; }"
        : "=r"(a) : "l"(p));
    return a;
}
#define CP_ASYNC16(dst, src) \
    asm volatile("cp.async.cg.shared.global [%0], [%1], 16;" \
                 :: "r"(dst), "l"(src) : "memory")
#define CP_COMMIT() asm volatile("cp.async.commit_group;" ::: "memory")
#define CP_WAIT(n)  asm volatile("cp.async.wait_group %0;" :: "n"(n) : "memory")
#define LDSM4(r0, r1, r2, r3, addr) \
    asm volatile("ldmatrix.sync.aligned.m8n8.x4.shared.b16 {%0,%1,%2,%3}, [%4];" \
                 : "=r"(r0), "=r"(r1), "=r"(r2), "=r"(r3) : "r"(addr))
#define MMA16816(d, a, b) \
    asm volatile("mma.sync.aligned.m16n8k16.row.col.f32.bf16.bf16.f32 " \
                 "{%0,%1,%2,%3},{%4,%5,%6,%7},{%8,%9},{%0,%1,%2,%3};" \
                 : "+f"((d)[0]), "+f"((d)[1]), "+f"((d)[2]), "+f"((d)[3]) \
                 : "r"((a)[0]), "r"((a)[1]), "r"((a)[2]), "r"((a)[3]), \
                   "r"((b)[0]), "r"((b)[1]))

static __device__ __forceinline__ unsigned pk2(float a, float b){
    __nv_bfloat162 t = __floats2bfloat162_rn(a, b);
    return *reinterpret_cast<unsigned*>(&t);
}
static __device__ __forceinline__ float bhi(float x){
    return __bfloat162float(__float2bfloat16_rn(x));
}

// ---------------------------------------------------------------------------
// conv_split3: fp32 -> bf16 hi/lo for q,k,v inputs in one launch (y = slot)
// ---------------------------------------------------------------------------
__global__ __launch_bounds__(256) void conv_split3_kernel(
    const float* __restrict__ s0, const float* __restrict__ s1,
    const float* __restrict__ s2, int n8)
{
    int i = blockIdx.x * 256 + threadIdx.x;
    if (i >= n8) return;
    const float* src; __nv_bfloat16 *dh, *dl;
    if (blockIdx.y == 0)      { src = s0; dh = g_inq_hi; dl = g_inq_lo; }
    else if (blockIdx.y == 1) { src = s1; dh = g_ink_hi; dl = g_ink_lo; }
    else                      { src = s2; dh = g_inv_hi; dl = g_inv_lo; }
    const float4* s = (const float4*)(src + (size_t)i * 8);
    float4 v0 = s[0], v1 = s[1];
    float f[8] = {v0.x, v0.y, v0.z, v0.w, v1.x, v1.y, v1.z, v1.w};
    float hh[8], ll[8];
#pragma unroll
    for (int e = 0; e < 8; e++) { hh[e] = bhi(f[e]); ll[e] = f[e] - hh[e]; }
    *(uint4*)(dh + (size_t)i * 8) = make_uint4(pk2(hh[0],hh[1]), pk2(hh[2],hh[3]),
                                               pk2(hh[4],hh[5]), pk2(hh[6],hh[7]));
    *(uint4*)(dl + (size_t)i * 8) = make_uint4(pk2(ll[0],ll[1]), pk2(ll[2],ll[3]),
                                               pk2(ll[4],ll[5]), pk2(ll[6],ll[7]));
}

// conv_split4: the 4 weight matrices into g_w slots (y = slot)
__global__ __launch_bounds__(256) void conv_split4_kernel(
    const float* __restrict__ s0, const float* __restrict__ s1,
    const float* __restrict__ s2, const float* __restrict__ s3, int n8)
{
    int i = blockIdx.x * 256 + threadIdx.x;
    if (i >= n8) return;
    const float* srcs[4] = {s0, s1, s2, s3};
    const float* src = srcs[blockIdx.y];
    size_t slot = (size_t)blockIdx.y * D_ * D_;
    const float4* s = (const float4*)(src + (size_t)i * 8);
    float4 v0 = s[0], v1 = s[1];
    float f[8] = {v0.x, v0.y, v0.z, v0.w, v1.x, v1.y, v1.z, v1.w};
    float hh[8], ll[8];
#pragma unroll
    for (int e = 0; e < 8; e++) { hh[e] = bhi(f[e]); ll[e] = f[e] - hh[e]; }
    *(uint4*)(g_w_hi + slot + (size_t)i * 8) =
        make_uint4(pk2(hh[0],hh[1]), pk2(hh[2],hh[3]),
                   pk2(hh[4],hh[5]), pk2(hh[6],hh[7]));
    *(uint4*)(g_w_lo + slot + (size_t)i * 8) =
        make_uint4(pk2(ll[0],ll[1]), pk2(ll[2],ll[3]),
                   pk2(ll[4],ll[5]), pk2(ll[6],ll[7]));
}

// ---------------------------------------------------------------------------
// wker_prep (+ folded bcat)
// ---------------------------------------------------------------------------
__global__ __launch_bounds__(256) void wker_prep_kernel(
    const float* __restrict__ Wker, const float* __restrict__ bker)
{
    int idx = blockIdx.x * 256 + threadIdx.x;
    const int NW8 = H_ * WKN * 8;
    if (idx < NW8) {
        int d8 = (idx & 7) * 8;
        int n  = (idx >> 3) & (WKN - 1);
        int h  = idx >> 12;
        float f[8] = {0,0,0,0,0,0,0,0};
        if (n < NCAT) {
            int t = n >> 6, c = n & 63;
            const float* src = Wker + (((size_t)(h*DK_ + c)) * KW_ + t) * DK_ + d8;
            float4 v0 = *(const float4*)src, v1 = *(const float4*)(src + 4);
            f[0]=v0.x; f[1]=v0.y; f[2]=v0.z; f[3]=v0.w;
            f[4]=v1.x; f[5]=v1.y; f[6]=v1.z; f[7]=v1.w;
        }
        float hh[8], ll[8];
#pragma unroll
        for (int e = 0; e < 8; e++) { hh[e] = bhi(f[e]); ll[e] = f[e] - hh[e]; }
        size_t off = ((size_t)h * WKN + n) * DK_ + d8;
        *(uint4*)(g_wker_hi + off) = make_uint4(pk2(hh[0],hh[1]), pk2(hh[2],hh[3]),
                                                pk2(hh[4],hh[5]), pk2(hh[6],hh[7]));
        *(uint4*)(g_wker_lo + off) = make_uint4(pk2(ll[0],ll[1]), pk2(ll[2],ll[3]),
                                                pk2(ll[4],ll[5]), pk2(ll[6],ll[7]));
    } else {
        int n = idx - NW8;
        if (n < H_ * WKN) {
            int h = n >> 9, r = n & (WKN - 1), t = r >> 6, c = r & 63;
            g_bcat[n] = (r < NCAT) ? bker[(size_t)(h*DK_ + c) * KW_ + t] : 0.f;
        }
    }
}

#define GM_STAGE 32768
#define GM_SMEM  (2*GM_STAGE)
#define GM_SMEM3 (3*GM_STAGE)

// ---------------------------------------------------------------------------
// out-projection GEMM: 3-stage, SINGLE barrier per k-chunk.  2 CTAs/SM.
// loop: CP_WAIT -> sync -> issue(c+2) -> compute(c)
// ---------------------------------------------------------------------------
__global__ __launch_bounds__(256, 2) void gemm_mma_nt(
    const __nv_bfloat16* __restrict__ Ah, const __nv_bfloat16* __restrict__ Al,
    const __nv_bfloat16* __restrict__ Bh, const __nv_bfloat16* __restrict__ Bl,
    const float* __restrict__ bias, float* __restrict__ C, int K, int N)
{
    extern __shared__ char smem[];
    const uint32_t sbase = smem_u32(smem);
    const int kc = K >> 5;

    const int tid  = threadIdx.x;
    const int wid  = tid >> 5, lane = tid & 31;
    const int wm   = wid >> 2, wn = wid & 3;

    const int i0 = blockIdx.y * 128;
    const int j0 = blockIdx.x * 128;

    const __nv_bfloat16* ah = Ah + (size_t)i0 * K;
    const __nv_bfloat16* al = Al + (size_t)i0 * K;
    const __nv_bfloat16* bh_ = Bh + (size_t)j0 * K;
    const __nv_bfloat16* bl_ = Bl + (size_t)j0 * K;

    auto issue = [&](int s, int c) {
        const uint32_t sb = sbase + s * GM_STAGE;
#pragma unroll
        for (int q = 0; q < 4; q++) {
            int u  = q * 256 + tid;
            int r  = u >> 3, cj = u & 7;
            const __nv_bfloat16* src =
                (cj < 4 ? ah : al) + (size_t)r * K + c * 32 + (cj & 3) * 8;
            CP_ASYNC16(sb + r * 128 + 16 * (cj ^ (r & 7)), src);
        }
#pragma unroll
        for (int q = 0; q < 4; q++) {
            int u  = q * 256 + tid;
            int r  = u >> 3, cj = u & 7;
            const __nv_bfloat16* src =
                (cj < 4 ? bh_ : bl_) + (size_t)r * K + c * 32 + (cj & 3) * 8;
            CP_ASYNC16(sb + 16384 + r * 128 + 16 * (cj ^ (r & 7)), src);
        }
    };

    float acc[4][4][4];
#pragma unroll
    for (int i = 0; i < 4; i++)
#pragma unroll
        for (int j = 0; j < 4; j++)
#pragma unroll
            for (int e = 0; e < 4; e++) acc[i][j][e] = 0.f;

    issue(0, 0); CP_COMMIT();
    issue(1, 1); CP_COMMIT();

    const int lrow = (lane & 7) + 8 * ((lane >> 3) & 1);
    const int lchk = lane >> 4;

    int stage = 0;
    for (int c = 0; c < kc; c++) {
        if (c + 1 < kc) CP_WAIT(1); else CP_WAIT(0);
        __syncthreads();
        if (c + 2 < kc) {
            int s2 = stage + 2; if (s2 >= 3) s2 -= 3;
            issue(s2, c + 2); CP_COMMIT();
        }

        const uint32_t sA = sbase + stage * GM_STAGE;
        const uint32_t sB = sA + 16384;

#pragma unroll
        for (int ks = 0; ks < 2; ks++) {
            uint32_t bh[4][2], bl[4][2];
#pragma unroll
            for (int g = 0; g < 2; g++) {
                int r  = wn * 32 + g * 16 + lrow;
                int ch = ks * 2 + lchk;
                uint32_t r0, r1, r2, r3;
                LDSM4(r0, r1, r2, r3, sB + r * 128 + 16 * ((ch)     ^ (r & 7)));
                bh[2*g][0] = r0; bh[2*g][1] = r2;
                bh[2*g+1][0] = r1; bh[2*g+1][1] = r3;
                LDSM4(r0, r1, r2, r3, sB + r * 128 + 16 * ((ch + 4) ^ (r & 7)));
                bl[2*g][0] = r0; bl[2*g][1] = r2;
                bl[2*g+1][0] = r1; bl[2*g+1][1] = r3;
            }
#pragma unroll
            for (int mf = 0; mf < 4; mf++) {
                int r  = wm * 64 + mf * 16 + lrow;
                int ch = ks * 2 + lchk;
                uint32_t ah_[4], al_[4];
                LDSM4(ah_[0], ah_[1], ah_[2], ah_[3],
                      sA + r * 128 + 16 * ((ch)     ^ (r & 7)));
                LDSM4(al_[0], al_[1], al_[2], al_[3],
                      sA + r * 128 + 16 * ((ch + 4) ^ (r & 7)));
#pragma unroll
                for (int nf = 0; nf < 4; nf++) {
                    MMA16816(acc[mf][nf], ah_, bh[nf]);
                    MMA16816(acc[mf][nf], ah_, bl[nf]);
                    MMA16816(acc[mf][nf], al_, bh[nf]);
                }
            }
        }
        stage++; if (stage == 3) stage = 0;
    }

    const int rbase = i0 + wm * 64 + (lane >> 2);
    const int cbase = j0 + wn * 32 + 2 * (lane & 3);
#pragma unroll
    for (int mf = 0; mf < 4; mf++) {
        int gi = rbase + mf * 16;
        float* row0 = C + (size_t)gi * N;
        float* row1 = row0 + 8 * N;
#pragma unroll
        for (int nf = 0; nf < 4; nf++) {
            int gj = cbase + nf * 8;
            float b0 = bias[gj], b1 = bias[gj + 1];
            *(float2*)(row0 + gj) = make_float2(acc[mf][nf][0] + b0,
                                                acc[mf][nf][1] + b1);
            *(float2*)(row1 + gj) = make_float2(acc[mf][nf][2] + b0,
                                                acc[mf][nf][3] + b1);
        }
    }
}

// ---------------------------------------------------------------------------
// batched projection GEMM (bf16 hi/lo out).  3-stage, single barrier.
// grid (4, 64, 3): z selects {q, k, v}.
// ---------------------------------------------------------------------------
__global__ __launch_bounds__(256, 2) void gemm_mma_split3(
    const float* __restrict__ bq, const float* __restrict__ bk,
    const float* __restrict__ bv)
{
    extern __shared__ char smem[];
    const uint32_t sbase = smem_u32(smem);
    const int K = D_;

    const int tid  = threadIdx.x;
    const int wid  = tid >> 5, lane = tid & 31;
    const int wm   = wid >> 2, wn = wid & 3;

    const int i0 = blockIdx.y * 128;
    const int j0 = blockIdx.x * 128;
    const int sel = blockIdx.z;

    const __nv_bfloat16 *Ah, *Al;
    const float* bias;
    __nv_bfloat16 *Ch, *Cl;
    size_t wslot;
    if (sel == 0) { Ah = g_inq_hi; Al = g_inq_lo; bias = bq; Ch = g_qs_hi; Cl = g_qs_lo; wslot = 0; }
    else if (sel == 1) { Ah = g_ink_hi; Al = g_ink_lo; bias = bk; Ch = g_ks_hi; Cl = g_ks_lo; wslot = (size_t)D_*D_; }
    else { Ah = g_inv_hi; Al = g_inv_lo; bias = bv; Ch = g_vs_hi; Cl = g_vs_lo; wslot = (size_t)2*D_*D_; }

    const __nv_bfloat16* ah = Ah + (size_t)i0 * K;
    const __nv_bfloat16* al = Al + (size_t)i0 * K;
    const __nv_bfloat16* bh_ = g_w_hi + wslot + (size_t)j0 * K;
    const __nv_bfloat16* bl_ = g_w_lo + wslot + (size_t)j0 * K;

    auto issue = [&](int s, int c) {
        const uint32_t sb = sbase + s * GM_STAGE;
#pragma unroll
        for (int q = 0; q < 4; q++) {
            int u  = q * 256 + tid;
            int r  = u >> 3, cj = u & 7;
            const __nv_bfloat16* src =
                (cj < 4 ? ah : al) + (size_t)r * K + c * 32 + (cj & 3) * 8;
            CP_ASYNC16(sb + r * 128 + 16 * (cj ^ (r & 7)), src);
        }
#pragma unroll
        for (int q = 0; q < 4; q++) {
            int u  = q * 256 + tid;
            int r  = u >> 3, cj = u & 7;
            const __nv_bfloat16* src =
                (cj < 4 ? bh_ : bl_) + (size_t)r * K + c * 32 + (cj & 3) * 8;
            CP_ASYNC16(sb + 16384 + r * 128 + 16 * (cj ^ (r & 7)), src);
        }
    };

    float acc[4][4][4];
#pragma unroll
    for (int i = 0; i < 4; i++)
#pragma unroll
        for (int j = 0; j < 4; j++)
#pragma unroll
            for (int e = 0; e < 4; e++) acc[i][j][e] = 0.f;

    issue(0, 0); CP_COMMIT();
    issue(1, 1); CP_COMMIT();

    const int lrow = (lane & 7) + 8 * ((lane >> 3) & 1);
    const int lchk = lane >> 4;

    int stage = 0;
    for (int c = 0; c < 16; c++) {
        if (c + 1 < 16) CP_WAIT(1); else CP_WAIT(0);
        __syncthreads();
        if (c + 2 < 16) {
            int s2 = stage + 2; if (s2 >= 3) s2 -= 3;
            issue(s2, c + 2); CP_COMMIT();
        }

        const uint32_t sA = sbase + stage * GM_STAGE;
        const uint32_t sB = sA + 16384;

#pragma unroll
        for (int ks = 0; ks < 2; ks++) {
            uint32_t bh[4][2], bl[4][2];
#pragma unroll
            for (int g = 0; g < 2; g++) {
                int r  = wn * 32 + g * 16 + lrow;
                int ch = ks * 2 + lchk;
                uint32_t r0, r1, r2, r3;
                LDSM4(r0, r1, r2, r3, sB + r * 128 + 16 * ((ch)     ^ (r & 7)));
                bh[2*g][0] = r0; bh[2*g][1] = r2;
                bh[2*g+1][0] = r1; bh[2*g+1][1] = r3;
                LDSM4(r0, r1, r2, r3, sB + r * 128 + 16 * ((ch + 4) ^ (r & 7)));
                bl[2*g][0] = r0; bl[2*g][1] = r2;
                bl[2*g+1][0] = r1; bl[2*g+1][1] = r3;
            }
#pragma unroll
            for (int mf = 0; mf < 4; mf++) {
                int r  = wm * 64 + mf * 16 + lrow;
                int ch = ks * 2 + lchk;
                uint32_t ah_[4], al_[4];
                LDSM4(ah_[0], ah_[1], ah_[2], ah_[3],
                      sA + r * 128 + 16 * ((ch)     ^ (r & 7)));
                LDSM4(al_[0], al_[1], al_[2], al_[3],
                      sA + r * 128 + 16 * ((ch + 4) ^ (r & 7)));
#pragma unroll
                for (int nf = 0; nf < 4; nf++) {
                    MMA16816(acc[mf][nf], ah_, bh[nf]);
                    MMA16816(acc[mf][nf], ah_, bl[nf]);
                    MMA16816(acc[mf][nf], al_, bh[nf]);
                }
            }
        }
        stage++; if (stage == 3) stage = 0;
    }

    const int rbase = i0 + wm * 64 + (lane >> 2);
    const int cbase = j0 + wn * 32 + 2 * (lane & 3);
#pragma unroll
    for (int mf = 0; mf < 4; mf++) {
        int gi = rbase + mf * 16;
        size_t ro0 = (size_t)gi * D_, ro1 = ro0 + 8 * D_;
#pragma unroll
        for (int nf = 0; nf < 4; nf++) {
            int gj = cbase + nf * 8;
            float b0 = bias[gj], b1 = bias[gj + 1];
            float v0 = acc[mf][nf][0] + b0, v1 = acc[mf][nf][1] + b1;
            float v2 = acc[mf][nf][2] + b0, v3 = acc[mf][nf][3] + b1;
            float h0 = bhi(v0), h1 = bhi(v1), h2 = bhi(v2), h3 = bhi(v3);
            *(unsigned*)(Ch + ro0 + gj) = pk2(h0, h1);
            *(unsigned*)(Cl + ro0 + gj) = pk2(v0 - h0, v1 - h1);
            *(unsigned*)(Ch + ro1 + gj) = pk2(h2, h3);
            *(unsigned*)(Cl + ro1 + gj) = pk2(v2 - h2, v3 - h3);
        }
    }
}

// ---------------------------------------------------------------------------
// qcat via mma (unchanged 2-chunk kernel)
// ---------------------------------------------------------------------------
__global__ __launch_bounds__(256, 2) void qcat_mma_kernel()
{
    __shared__ char smem[2 * GM_STAGE];
    const uint32_t sbase = smem_u32(smem);

    const int tid  = threadIdx.x;
    const int wid  = tid >> 5, lane = tid & 31;
    const int wm   = wid >> 2, wn = wid & 3;

    const int z  = blockIdx.z;
    const int b = z >> 3, h = z & 7;
    const int i0 = blockIdx.y * 128;
    const int n0 = blockIdx.x * 128;

    const __nv_bfloat16* ah = g_qs_hi + ((size_t)(b*L_ + i0)) * D_ + h*DK_;
    const __nv_bfloat16* al = g_qs_lo + ((size_t)(b*L_ + i0)) * D_ + h*DK_;
    const __nv_bfloat16* bh_ = g_wker_hi + ((size_t)h * WKN + n0) * DK_;
    const __nv_bfloat16* bl_ = g_wker_lo + ((size_t)h * WKN + n0) * DK_;

    auto issue = [&](int s, int c) {
        const uint32_t sb = sbase + s * GM_STAGE;
#pragma unroll
        for (int q = 0; q < 4; q++) {
            int u  = q * 256 + tid;
            int r  = u >> 3, cj = u & 7;
            const __nv_bfloat16* src =
                (cj < 4 ? ah : al) + (size_t)r * D_ + c * 32 + (cj & 3) * 8;
            CP_ASYNC16(sb + r * 128 + 16 * (cj ^ (r & 7)), src);
        }
#pragma unroll
        for (int q = 0; q < 4; q++) {
            int u  = q * 256 + tid;
            int r  = u >> 3, cj = u & 7;
            const __nv_bfloat16* src =
                (cj < 4 ? bh_ : bl_) + (size_t)r * DK_ + c * 32 + (cj & 3) * 8;
            CP_ASYNC16(sb + 16384 + r * 128 + 16 * (cj ^ (r & 7)), src);
        }
    };

    float acc[4][4][4];
#pragma unroll
    for (int i = 0; i < 4; i++)
#pragma unroll
        for (int j = 0; j < 4; j++)
#pragma unroll
            for (int e = 0; e < 4; e++) acc[i][j][e] = 0.f;

    issue(0, 0);
    CP_COMMIT();

    const int lrow = (lane & 7) + 8 * ((lane >> 3) & 1);
    const int lchk = lane >> 4;

    for (int c = 0; c < 2; c++) {
        const int s = c & 1;
        if (c == 0) { issue(1, 1); CP_COMMIT(); CP_WAIT(1); }
        else        { CP_WAIT(0); }
        __syncthreads();

        const uint32_t sA = sbase + s * GM_STAGE;
        const uint32_t sB = sA + 16384;

#pragma unroll
        for (int ks = 0; ks < 2; ks++) {
            uint32_t bh[4][2], bl[4][2];
#pragma unroll
            for (int g = 0; g < 2; g++) {
                int r  = wn * 32 + g * 16 + lrow;
                int ch = ks * 2 + lchk;
                uint32_t r0, r1, r2, r3;
                LDSM4(r0, r1, r2, r3, sB + r * 128 + 16 * ((ch)     ^ (r & 7)));
                bh[2*g][0] = r0; bh[2*g][1] = r2;
                bh[2*g+1][0] = r1; bh[2*g+1][1] = r3;
                LDSM4(r0, r1, r2, r3, sB + r * 128 + 16 * ((ch + 4) ^ (r & 7)));
                bl[2*g][0] = r0; bl[2*g][1] = r2;
                bl[2*g+1][0] = r1; bl[2*g+1][1] = r3;
            }
#pragma unroll
            for (int mf = 0; mf < 4; mf++) {
                int r  = wm * 64 + mf * 16 + lrow;
                int ch = ks * 2 + lchk;
                uint32_t ah_[4], al_[4];
                LDSM4(ah_[0], ah_[1], ah_[2], ah_[3],
                      sA + r * 128 + 16 * ((ch)     ^ (r & 7)));
                LDSM4(al_[0], al_[1], al_[2], al_[3],
                      sA + r * 128 + 16 * ((ch + 4) ^ (r & 7)));
#pragma unroll
                for (int nf = 0; nf < 4; nf++) {
                    MMA16816(acc[mf][nf], ah_, bh[nf]);
                    MMA16816(acc[mf][nf], ah_, bl[nf]);
                    MMA16816(acc[mf][nf], al_, bh[nf]);
                }
            }
        }
        __syncthreads();
    }

    __nv_bfloat16* Ch = g_qcat_hi + (size_t)z * L_ * NCAT;
    __nv_bfloat16* Cl = g_qcat_lo + (size_t)z * L_ * NCAT;
    const int rbase = i0 + wm * 64 + (lane >> 2);
    const int cbase = n0 + wn * 32 + 2 * (lane & 3);
#pragma unroll
    for (int mf = 0; mf < 4; mf++) {
        int gi = rbase + mf * 16;
        size_t ro0 = (size_t)gi * NCAT, ro1 = ro0 + 8 * NCAT;
#pragma unroll
        for (int nf = 0; nf < 4; nf++) {
            int gj = cbase + nf * 8;
            if (gj >= NCAT) continue;
            float b0 = g_bcat[h*WKN + gj], b1 = g_bcat[h*WKN + gj + 1];
            float v0 = acc[mf][nf][0] + b0, v1 = acc[mf][nf][1] + b1;
            float v2 = acc[mf][nf][2] + b0, v3 = acc[mf][nf][3] + b1;
            float h0 = bhi(v0), h1 = bhi(v1), h2 = bhi(v2), h3 = bhi(v3);
            *(unsigned*)(Ch + ro0 + gj) = pk2(h0, h1);
            *(unsigned*)(Cl + ro0 + gj) = pk2(v0 - h0, v1 - h1);
            *(unsigned*)(Ch + ro1 + gj) = pk2(h2, h3);
            *(unsigned*)(Cl + ro1 + gj) = pk2(v2 - h2, v3 - h3);
        }
    }
}

// ---------------------------------------------------------------------------
// vt transpose (bf16)
// ---------------------------------------------------------------------------
__global__ __launch_bounds__(256) void vt_kernel()
{
    __shared__ uint32_t t[128][65];
    const int z = blockIdx.y;
    const int b = z >> 3, h = z & 7;
    const int k0 = blockIdx.x * 128;
    const int tid = threadIdx.x;

#pragma unroll
    for (int q = 0; q < 4; q++) {
        int u = q * 256 + tid;
        int r = u >> 3, c8 = (u & 7) * 8;
        size_t so = ((size_t)(b*L_ + k0 + r)) * D_ + h*DK_ + c8;
        uint4 vh = *(const uint4*)(g_vs_hi + so);
        uint4 vl = *(const uint4*)(g_vs_lo + so);
        uint32_t hw[4] = {vh.x, vh.y, vh.z, vh.w};
        uint32_t lw[4] = {vl.x, vl.y, vl.z, vl.w};
#pragma unroll
        for (int e = 0; e < 4; e++) {
            t[r][c8 + 2*e]     = (hw[e] & 0xffffu) | (lw[e] << 16);
            t[r][c8 + 2*e + 1] = (hw[e] >> 16)     | (lw[e] & 0xffff0000u);
        }
    }
    __syncthreads();

#pragma unroll
    for (int q = 0; q < 4; q++) {
        int u = q * 256 + tid;
        int n = u >> 4, k8 = (u & 15) * 8;
        uint32_t hi4[4], lo4[4];
#pragma unroll
        for (int e = 0; e < 4; e++) {
            uint32_t a = t[k8 + 2*e][n];
            uint32_t c = t[k8 + 2*e + 1][n];
            hi4[e] = (a & 0xffffu) | ((c & 0xffffu) << 16);
            lo4[e] = (a >> 16)     | (c & 0xffff0000u);
        }
        size_t off = (size_t)z * DK_ * L_ + (size_t)n * L_ + k0 + k8;
        *(uint4*)(g_vt_hi + off) = make_uint4(hi4[0], hi4[1], hi4[2], hi4[3]);
        *(uint4*)(g_vt_lo + off) = make_uint4(lo4[0], lo4[1], lo4[2], lo4[3]);
    }
}

// ---------------------------------------------------------------------------
// Logits v3 + single-barrier loop: A 3-stage, B = shifted k_s smem panel.
// loop: CP_WAIT -> sync -> issueA(c+2) -> compute(c)
// ---------------------------------------------------------------------------
#define LOG_ASTAGE   16384
#define LOG_PANEL    17152
#define LOG_PANEL_HI (3*LOG_ASTAGE)
#define LOG_PANEL_LO (LOG_PANEL_HI + LOG_PANEL)
#define LOG_SMEM     (LOG_PANEL_LO + LOG_PANEL)

__global__ __launch_bounds__(256, 2) void logits_mma_kernel(float* __restrict__ attn)
{
    extern __shared__ char smem[];
    const uint32_t sbase = smem_u32(smem);
    const uint32_t pHI = sbase + LOG_PANEL_HI;
    const uint32_t pLO = sbase + LOG_PANEL_LO;

    const int tid  = threadIdx.x;
    const int wid  = tid >> 5, lane = tid & 31;
    const int wm   = wid >> 2, wn = wid & 3;

    const int z  = blockIdx.z;
    const int b = z >> 3, h = z & 7;
    const int i0 = blockIdx.y * 128;
    const int j0 = blockIdx.x * 128;

    const __nv_bfloat16* qh = g_qcat_hi + (size_t)z * L_ * NCAT + (size_t)i0 * NCAT;
    const __nv_bfloat16* ql = g_qcat_lo + (size_t)z * L_ * NCAT + (size_t)i0 * NCAT;
    const __nv_bfloat16* ksh = g_ks_hi + ((size_t)(b*L_)) * D_ + h*DK_;
    const __nv_bfloat16* ksl = g_ks_lo + ((size_t)(b*L_)) * D_ + h*DK_;

    auto issueA = [&](int s, int c) {
        const uint32_t sb = sbase + s * LOG_ASTAGE;
#pragma unroll
        for (int q = 0; q < 4; q++) {
            int u  = q * 256 + tid;
            int r  = u >> 3, cj = u & 7;
            const __nv_bfloat16* src =
                (cj < 4 ? qh : ql) + (size_t)r * NCAT + c * 32 + (cj & 3) * 8;
            CP_ASYNC16(sb + r * 128 + 16 * (cj ^ (r & 7)), src);
        }
    };

    // panel load: rows j0-3 .. j0+130
    for (int u = tid; u < 134 * 8; u += 256) {
        int r  = u >> 3, g8 = u & 7;
        int j  = j0 + r - PAD_;
        uint32_t dh = pHI + r * 128 + 16 * (g8 ^ (r & 7));
        uint32_t dl = pLO + r * 128 + 16 * (g8 ^ (r & 7));
        if (j >= 0 && j < L_) {
            CP_ASYNC16(dh, ksh + (size_t)j * D_ + g8 * 8);
            CP_ASYNC16(dl, ksl + (size_t)j * D_ + g8 * 8);
        } else {
            *(uint4*)(smem + (dh - sbase)) = make_uint4(0,0,0,0);
            *(uint4*)(smem + (dl - sbase)) = make_uint4(0,0,0,0);
        }
    }
    issueA(0, 0); CP_COMMIT();   // group: panel + A0
    issueA(1, 1); CP_COMMIT();   // group: A1

    float acc[4][4][4];
#pragma unroll
    for (int i = 0; i < 4; i++)
#pragma unroll
        for (int j = 0; j < 4; j++)
#pragma unroll
            for (int e = 0; e < 4; e++) acc[i][j][e] = 0.f;

    const int lrow = (lane & 7) + 8 * ((lane >> 3) & 1);
    const int lchk = lane >> 4;

    int stage = 0;
    for (int c = 0; c < 14; c++) {
        if (c + 1 < 14) CP_WAIT(1); else CP_WAIT(0);
        __syncthreads();
        if (c + 2 < 14) {
            int s2 = stage + 2; if (s2 >= 3) s2 -= 3;
            issueA(s2, c + 2); CP_COMMIT();
        }

        const uint32_t sA = sbase + stage * LOG_ASTAGE;
        const int t    = c >> 1;
        const int half = c & 1;

#pragma unroll
        for (int ks = 0; ks < 2; ks++) {
            uint32_t bh[4][2], bl[4][2];
#pragma unroll
            for (int g = 0; g < 2; g++) {
                int rr = wn * 32 + g * 16 + lrow + t;
                int g8 = half * 4 + ks * 2 + lchk;
                uint32_t r0, r1, r2, r3;
                LDSM4(r0, r1, r2, r3, pHI + rr * 128 + 16 * (g8 ^ (rr & 7)));
                bh[2*g][0] = r0; bh[2*g][1] = r2;
                bh[2*g+1][0] = r1; bh[2*g+1][1] = r3;
                LDSM4(r0, r1, r2, r3, pLO + rr * 128 + 16 * (g8 ^ (rr & 7)));
                bl[2*g][0] = r0; bl[2*g][1] = r2;
                bl[2*g+1][0] = r1; bl[2*g+1][1] = r3;
            }
#pragma unroll
            for (int mf = 0; mf < 4; mf++) {
                int r  = wm * 64 + mf * 16 + lrow;
                int ch = ks * 2 + lchk;
                uint32_t ah[4], al[4];
                LDSM4(ah[0], ah[1], ah[2], ah[3],
                      sA + r * 128 + 16 * ((ch)     ^ (r & 7)));
                LDSM4(al[0], al[1], al[2], al[3],
                      sA + r * 128 + 16 * ((ch + 4) ^ (r & 7)));
#pragma unroll
                for (int nf = 0; nf < 4; nf++) {
                    MMA16816(acc[mf][nf], ah, bh[nf]);
                    MMA16816(acc[mf][nf], ah, bl[nf]);
                    MMA16816(acc[mf][nf], al, bh[nf]);
                }
            }
        }
        stage++; if (stage == 3) stage = 0;
    }

    const int rbase = i0 + wm * 64 + (lane >> 2);
    const int cbase = j0 + wn * 32 + 2 * (lane & 3);
#pragma unroll
    for (int mf = 0; mf < 4; mf++) {
        int gi0 = rbase + mf * 16;
        float* row0 = attn + ((size_t)z * L_ + gi0) * L_;
        float* row1 = row0 + 8 * L_;
#pragma unroll
        for (int nf = 0; nf < 4; nf++) {
            int gj = cbase + nf * 8;
            *(float2*)(row0 + gj) = make_float2(acc[mf][nf][0]*0.125f,
                                                acc[mf][nf][1]*0.125f);
            *(float2*)(row1 + gj) = make_float2(acc[mf][nf][2]*0.125f,
                                                acc[mf][nf][3]*0.125f);
        }
    }
}

// ---------------------------------------------------------------------------
// Row softmax in-place on attn; mask; head-0 duplicate.
// ---------------------------------------------------------------------------
__global__ __launch_bounds__(256) void softmax_kernel(
    float* __restrict__ attn, const unsigned char* __restrict__ mask,
    float* __restrict__ one_head)
{
    const int r = blockIdx.x;
    const int i = r & (L_-1);
    const int bh = r >> 10;
    const int h = bh & (H_-1), b = bh >> 3;
    float* row = attn + (size_t)r * L_;
    const unsigned char* mrow = mask + ((size_t)(b*L_ + i)) * L_;
    const int t4 = threadIdx.x * 4;

    float4 v = *(const float4*)(row + t4);
    uchar4 m = *(const uchar4*)(mrow + t4);
    float x0 = m.x ? -INFINITY : v.x;
    float x1 = m.y ? -INFINITY : v.y;
    float x2 = m.z ? -INFINITY : v.z;
    float x3 = m.w ? -INFINITY : v.w;

    __shared__ float sm[8], ss[8];
    float mx = fmaxf(fmaxf(x0, x1), fmaxf(x2, x3));
#pragma unroll
    for (int o = 16; o; o >>= 1) mx = fmaxf(mx, __shfl_xor_sync(0xffffffffu, mx, o));
    if ((threadIdx.x & 31) == 0) sm[threadIdx.x >> 5] = mx;
    __syncthreads();
    if (threadIdx.x < 32) {
        float t = (threadIdx.x < 8) ? sm[threadIdx.x] : -INFINITY;
#pragma unroll
        for (int o = 4; o; o >>= 1) t = fmaxf(t, __shfl_xor_sync(0xffffffffu, t, o));
        if (threadIdx.x == 0) sm[0] = t;
    }
    __syncthreads();
    mx = sm[0];

    float e0 = __expf(x0 - mx), e1 = __expf(x1 - mx);
    float e2 = __expf(x2 - mx), e3 = __expf(x3 - mx);
    float s = (e0 + e1) + (e2 + e3);
#pragma unroll
    for (int o = 16; o; o >>= 1) s += __shfl_xor_sync(0xffffffffu, s, o);
    if ((threadIdx.x & 31) == 0) ss[threadIdx.x >> 5] = s;
    __syncthreads();
    if (threadIdx.x < 32) {
        float t = (threadIdx.x < 8) ? ss[threadIdx.x] : 0.f;
#pragma unroll
        for (int o = 4; o; o >>= 1) t += __shfl_xor_sync(0xffffffffu, t, o);
        if (threadIdx.x == 0) ss[0] = t;
    }
    __syncthreads();
    float inv = 1.0f / ss[0];

    float4 o = make_float4(e0*inv, e1*inv, e2*inv, e3*inv);
    *(float4*)(row + t4) = o;
    if (h == 0)
        *(float4*)(one_head + ((size_t)(b*L_ + i)) * L_ + t4) = o;
}

// ---------------------------------------------------------------------------
// ctx via mma (unchanged)
// ---------------------------------------------------------------------------
#define CTX_STAGE 24576

__global__ __launch_bounds__(256, 2) void ctx_mma_kernel(const float* __restrict__ attn)
{
    __shared__ char smem[2 * CTX_STAGE];
    const uint32_t sbase = smem_u32(smem);

    const int tid  = threadIdx.x;
    const int wid  = tid >> 5, lane = tid & 31;
    const int wm   = wid >> 2, wn = wid & 3;

    const int z  = blockIdx.y;
    const int b = z >> 3, h = z & 7;
    const int i0 = blockIdx.x * 128;

    const float* A = attn + ((size_t)z * L_ + i0) * L_;
    const __nv_bfloat16* vh = g_vt_hi + (size_t)z * DK_ * L_;
    const __nv_bfloat16* vl = g_vt_lo + (size_t)z * DK_ * L_;

    auto issueB = [&](int s, int c) {
        const uint32_t sb = sbase + s * CTX_STAGE + 16384;
#pragma unroll
        for (int q = 0; q < 2; q++) {
            int u  = q * 256 + tid;
            int r  = u >> 3, cj = u & 7;
            const __nv_bfloat16* src =
                (cj < 4 ? vh : vl) + (size_t)r * L_ + c * 32 + (cj & 3) * 8;
            CP_ASYNC16(sb + r * 128 + 16 * (cj ^ (r & 7)), src);
        }
    };
    float fa[2][8];
    auto ldgA = [&](int c) {
#pragma unroll
        for (int q = 0; q < 2; q++) {
            int u = q * 256 + tid;
            int r = u >> 2, seg = u & 3;
            const float4* p = (const float4*)(A + (size_t)r * L_ + c * 32 + seg * 8);
            float4 v0 = p[0], v1 = p[1];
            fa[q][0]=v0.x; fa[q][1]=v0.y; fa[q][2]=v0.z; fa[q][3]=v0.w;
            fa[q][4]=v1.x; fa[q][5]=v1.y; fa[q][6]=v1.z; fa[q][7]=v1.w;
        }
    };
    auto stsA = [&](int s) {
#pragma unroll
        for (int q = 0; q < 2; q++) {
            int u = q * 256 + tid;
            int r = u >> 2, seg = u & 3;
            float hh[8], ll[8];
#pragma unroll
            for (int e = 0; e < 8; e++) { hh[e] = bhi(fa[q][e]); ll[e] = fa[q][e] - hh[e]; }
            *(uint4*)(smem + s * CTX_STAGE + r * 128 + 16 * ((seg)     ^ (r & 7))) =
                make_uint4(pk2(hh[0],hh[1]), pk2(hh[2],hh[3]),
                           pk2(hh[4],hh[5]), pk2(hh[6],hh[7]));
            *(uint4*)(smem + s * CTX_STAGE + r * 128 + 16 * ((seg + 4) ^ (r & 7))) =
                make_uint4(pk2(ll[0],ll[1]), pk2(ll[2],ll[3]),
                           pk2(ll[4],ll[5]), pk2(ll[6],ll[7]));
        }
    };

    float acc[4][2][4];
#pragma unroll
    for (int i = 0; i < 4; i++)
#pragma unroll
        for (int j = 0; j < 2; j++)
#pragma unroll
            for (int e = 0; e < 4; e++) acc[i][j][e] = 0.f;

    ldgA(0);
    issueB(0, 0); CP_COMMIT();

    const int lrow = (lane & 7) + 8 * ((lane >> 3) & 1);
    const int lchk = lane >> 4;

    for (int c = 0; c < 32; c++) {
        const int s = c & 1;
        stsA(s);
        if (c + 1 < 32) {
            ldgA(c + 1);
            issueB(s ^ 1, c + 1); CP_COMMIT(); CP_WAIT(1);
        } else {
            CP_WAIT(0);
        }
        __syncthreads();

        const uint32_t sA = sbase + s * CTX_STAGE;
        const uint32_t sB = sA + 16384;

#pragma unroll
        for (int ks = 0; ks < 2; ks++) {
            uint32_t bh[2][2], bl[2][2];
            {
                int r  = wn * 16 + lrow;
                int ch = ks * 2 + lchk;
                uint32_t r0, r1, r2, r3;
                LDSM4(r0, r1, r2, r3, sB + r * 128 + 16 * ((ch)     ^ (r & 7)));
                bh[0][0] = r0; bh[0][1] = r2; bh[1][0] = r1; bh[1][1] = r3;
                LDSM4(r0, r1, r2, r3, sB + r * 128 + 16 * ((ch + 4) ^ (r & 7)));
                bl[0][0] = r0; bl[0][1] = r2; bl[1][0] = r1; bl[1][1] = r3;
            }
#pragma unroll
            for (int mf = 0; mf < 4; mf++) {
                int r  = wm * 64 + mf * 16 + lrow;
                int ch = ks * 2 + lchk;
                uint32_t ah[4], al[4];
                LDSM4(ah[0], ah[1], ah[2], ah[3],
                      sA + r * 128 + 16 * ((ch)     ^ (r & 7)));
                LDSM4(al[0], al[1], al[2], al[3],
                      sA + r * 128 + 16 * ((ch + 4) ^ (r & 7)));
#pragma unroll
                for (int nf = 0; nf < 2; nf++) {
                    MMA16816(acc[mf][nf], ah, bh[nf]);
                    MMA16816(acc[mf][nf], ah, bl[nf]);
                    MMA16816(acc[mf][nf], al, bh[nf]);
                }
            }
        }
        __syncthreads();
    }

    const int rbase = i0 + wm * 64 + (lane >> 2);
    const int cb = h * DK_ + wn * 16 + 2 * (lane & 3);
#pragma unroll
    for (int mf = 0; mf < 4; mf++) {
        int gi = rbase + mf * 16;
        size_t ro0 = ((size_t)(b * L_) + gi) * D_;
        size_t ro1 = ro0 + 8 * D_;
#pragma unroll
        for (int nf = 0; nf < 2; nf++) {
            int gj = cb + nf * 8;
            float v0 = acc[mf][nf][0], v1 = acc[mf][nf][1];
            float v2 = acc[mf][nf][2], v3 = acc[mf][nf][3];
            float h0 = bhi(v0), h1 = bhi(v1), h2 = bhi(v2), h3 = bhi(v3);
            *(unsigned*)(g_ctx_hi + ro0 + gj) = pk2(h0, h1);
            *(unsigned*)(g_ctx_lo + ro0 + gj) = pk2(v0 - h0, v1 - h1);
            *(unsigned*)(g_ctx_hi + ro1 + gj) = pk2(h2, h3);
            *(unsigned*)(g_ctx_lo + ro1 + gj) = pk2(v2 - h2, v3 - h3);
        }
    }
}

// ---------------------------------------------------------------------------
extern "C" void kernel_launch(void* const* d_in, const int* in_sizes, int n_in,
                              void* d_out, int out_size)
{
    const float* q      = (const float*)d_in[0];
    const float* k      = (const float*)d_in[1];
    const float* v      = (const float*)d_in[2];
    const unsigned char* mask = (const unsigned char*)d_in[3];
    const float* Wq     = (const float*)d_in[4];
    const float* bq     = (const float*)d_in[5];
    const float* Wk     = (const float*)d_in[6];
    const float* bk     = (const float*)d_in[7];
    const float* Wv     = (const float*)d_in[8];
    const float* bv     = (const float*)d_in[9];
    const float* Wker   = (const float*)d_in[10];
    const float* bker   = (const float*)d_in[11];
    const float* Wproj  = (const float*)d_in[15];
    const float* bproj  = (const float*)d_in[16];

    float* out      = (float*)d_out;
    float* attn     = out + (size_t)B_ * L_ * D_;
    float* one_head = attn + (size_t)B_ * H_ * L_ * L_;

    void* p;
    __nv_bfloat16 *wh, *wl, *ch, *cl;
    cudaGetSymbolAddress(&p, g_w_hi);   wh  = (__nv_bfloat16*)p;
    cudaGetSymbolAddress(&p, g_w_lo);   wl  = (__nv_bfloat16*)p;
    cudaGetSymbolAddress(&p, g_ctx_hi); ch  = (__nv_bfloat16*)p;
    cudaGetSymbolAddress(&p, g_ctx_lo); cl  = (__nv_bfloat16*)p;

    static bool attr_done = false;
    if (!attr_done) {
        cudaFuncSetAttribute(logits_mma_kernel,
            cudaFuncAttributeMaxDynamicSharedMemorySize, LOG_SMEM);
        cudaFuncSetAttribute(gemm_mma_nt,
            cudaFuncAttributeMaxDynamicSharedMemorySize, GM_SMEM3);
        cudaFuncSetAttribute(gemm_mma_split3,
            cudaFuncAttributeMaxDynamicSharedMemorySize, GM_SMEM3);
        attr_done = true;
    }

    const int M = B_ * L_;        // 8192
    const int NE = M * D_;
    const int NW = D_ * D_;
    dim3 blk(256);

    // 0) splits + weight prep
    conv_split3_kernel<<<dim3((NE/8 + 255)/256, 3), 256>>>(q, k, v, NE/8);
    conv_split4_kernel<<<dim3((NW/8 + 255)/256, 4), 256>>>(Wq, Wk, Wv, Wproj, NW/8);
    wker_prep_kernel<<<(H_*WKN*8 + H_*WKN + 255)/256, 256>>>(Wker, bker);

    // 1) q/k/v projections in ONE batched launch (768 CTAs, 3-stage 1-barrier)
    gemm_mma_split3<<<dim3(D_/128, M/128, 3), blk, GM_SMEM3>>>(bq, bk, bv);

    // 2) operand prep
    qcat_mma_kernel<<<dim3(WKN/128, L_/128, B_*H_), blk>>>();
    vt_kernel<<<dim3(L_/128, B_*H_), blk>>>();

    // 3) tensor-core logits (single-barrier loop) -> attn region
    logits_mma_kernel<<<dim3(L_/128, L_/128, B_*H_), 256, LOG_SMEM>>>(attn);

    // 4) softmax in place (+ one_head copy)
    softmax_kernel<<<B_*H_*L_, 256>>>(attn, mask, one_head);

    // 5) ctx = attn @ v_s -> g_ctx hi/lo
    ctx_mma_kernel<<<dim3(L_/128, B_*H_), blk>>>(attn);

    // 6) out = ctx @ Wproj^T + bproj (3-stage 1-barrier)
    gemm_mma_nt<<<dim3(D_/128, M/128), blk, GM_SMEM3>>>(ch, cl, wh + 3*NW, wl + 3*NW, bproj, out, D_, D_);
}

// round 17
// speedup vs baseline: 1.7461x; 1.6185x over previous
#include <cuda_runtime.h>
#include <cuda_bf16.h>
#include <cstdint>

#define B_   8
#define L_   1024
#define D_   512
#define H_   8
#define DK_  64
#define KW_  7
#define PAD_ 3
#define NCAT 448    /* KW*DK */

// ---------------- scratch (device globals; no runtime allocation) ----------
__device__ __align__(16) __nv_bfloat16 g_qs_hi[B_*L_*D_];
__device__ __align__(16) __nv_bfloat16 g_qs_lo[B_*L_*D_];
__device__ __align__(16) __nv_bfloat16 g_ks_hi[B_*L_*D_];
__device__ __align__(16) __nv_bfloat16 g_ks_lo[B_*L_*D_];
__device__ __align__(16) __nv_bfloat16 g_vs_hi[B_*L_*D_];
__device__ __align__(16) __nv_bfloat16 g_vs_lo[B_*L_*D_];
// Wker2pad: [h][n=0..127][k=0..447]; n<64: Wker[h, c(k), t(k), n]; n==64: bker
__device__ __align__(16) __nv_bfloat16 g_wker2_hi[H_*128*NCAT];
__device__ __align__(16) __nv_bfloat16 g_wker2_lo[H_*128*NCAT];
// Kconv: [z][j][d<64] bf16 hi/lo; bterm fp32 [z][j]
__device__ __align__(16) __nv_bfloat16 g_kconv_hi[(size_t)B_*H_*L_*DK_];
__device__ __align__(16) __nv_bfloat16 g_kconv_lo[(size_t)B_*H_*L_*DK_];
__device__ float g_bterm[B_*H_*L_];
// projection inputs (bf16 split)
__device__ __align__(16) __nv_bfloat16 g_inq_hi[B_*L_*D_];
__device__ __align__(16) __nv_bfloat16 g_inq_lo[B_*L_*D_];
__device__ __align__(16) __nv_bfloat16 g_ink_hi[B_*L_*D_];
__device__ __align__(16) __nv_bfloat16 g_ink_lo[B_*L_*D_];
__device__ __align__(16) __nv_bfloat16 g_inv_hi[B_*L_*D_];
__device__ __align__(16) __nv_bfloat16 g_inv_lo[B_*L_*D_];
// weights (bf16 split): slots 0=Wq 1=Wk 2=Wv 3=Wproj
__device__ __align__(16) __nv_bfloat16 g_w_hi[4*D_*D_];
__device__ __align__(16) __nv_bfloat16 g_w_lo[4*D_*D_];
// v transposed per head: [z][n=0..63][k=0..1023]
__device__ __align__(16) __nv_bfloat16 g_vt_hi[(size_t)B_*H_*DK_*L_];
__device__ __align__(16) __nv_bfloat16 g_vt_lo[(size_t)B_*H_*DK_*L_];
// ctx in bf16 split, layout [B*L, 512]
__device__ __align__(16) __nv_bfloat16 g_ctx_hi[B_*L_*D_];
__device__ __align__(16) __nv_bfloat16 g_ctx_lo[B_*L_*D_];

// ====================== baseline-PTX tensor helpers ========================
static __device__ __forceinline__ uint32_t smem_u32(const void* p){
    uint32_t a;
    asm("{ .reg .u64 t; cvta.to.shared.u64 t, %1; cvt.u32.u64 %0, t; }"
        : "=r"(a) : "l"(p));
    return a;
}
#define CP_ASYNC16(dst, src) \
    asm volatile("cp.async.cg.shared.global [%0], [%1], 16;" \
                 :: "r"(dst), "l"(src) : "memory")
#define CP_COMMIT() asm volatile("cp.async.commit_group;" ::: "memory")
#define CP_WAIT(n)  asm volatile("cp.async.wait_group %0;" :: "n"(n) : "memory")
#define LDSM4(r0, r1, r2, r3, addr) \
    asm volatile("ldmatrix.sync.aligned.m8n8.x4.shared.b16 {%0,%1,%2,%3}, [%4];" \
                 : "=r"(r0), "=r"(r1), "=r"(r2), "=r"(r3) : "r"(addr))
#define MMA16816(d, a, b) \
    asm volatile("mma.sync.aligned.m16n8k16.row.col.f32.bf16.bf16.f32 " \
                 "{%0,%1,%2,%3},{%4,%5,%6,%7},{%8,%9},{%0,%1,%2,%3};" \
                 : "+f"((d)[0]), "+f"((d)[1]), "+f"((d)[2]), "+f"((d)[3]) \
                 : "r"((a)[0]), "r"((a)[1]), "r"((a)[2]), "r"((a)[3]), \
                   "r"((b)[0]), "r"((b)[1]))

static __device__ __forceinline__ unsigned pk2(float a, float b){
    __nv_bfloat162 t = __floats2bfloat162_rn(a, b);
    return *reinterpret_cast<unsigned*>(&t);
}
static __device__ __forceinline__ float bhi(float x){
    return __bfloat162float(__float2bfloat16_rn(x));
}

// ---------------------------------------------------------------------------
// conv_split3: fp32 -> bf16 hi/lo for q,k,v inputs in one launch (y = slot)
// ---------------------------------------------------------------------------
__global__ __launch_bounds__(256) void conv_split3_kernel(
    const float* __restrict__ s0, const float* __restrict__ s1,
    const float* __restrict__ s2, int n8)
{
    int i = blockIdx.x * 256 + threadIdx.x;
    if (i >= n8) return;
    const float* src; __nv_bfloat16 *dh, *dl;
    if (blockIdx.y == 0)      { src = s0; dh = g_inq_hi; dl = g_inq_lo; }
    else if (blockIdx.y == 1) { src = s1; dh = g_ink_hi; dl = g_ink_lo; }
    else                      { src = s2; dh = g_inv_hi; dl = g_inv_lo; }
    const float4* s = (const float4*)(src + (size_t)i * 8);
    float4 v0 = s[0], v1 = s[1];
    float f[8] = {v0.x, v0.y, v0.z, v0.w, v1.x, v1.y, v1.z, v1.w};
    float hh[8], ll[8];
#pragma unroll
    for (int e = 0; e < 8; e++) { hh[e] = bhi(f[e]); ll[e] = f[e] - hh[e]; }
    *(uint4*)(dh + (size_t)i * 8) = make_uint4(pk2(hh[0],hh[1]), pk2(hh[2],hh[3]),
                                               pk2(hh[4],hh[5]), pk2(hh[6],hh[7]));
    *(uint4*)(dl + (size_t)i * 8) = make_uint4(pk2(ll[0],ll[1]), pk2(ll[2],ll[3]),
                                               pk2(ll[4],ll[5]), pk2(ll[6],ll[7]));
}

// conv_split4: the 4 weight matrices into g_w slots (y = slot)
__global__ __launch_bounds__(256) void conv_split4_kernel(
    const float* __restrict__ s0, const float* __restrict__ s1,
    const float* __restrict__ s2, const float* __restrict__ s3, int n8)
{
    int i = blockIdx.x * 256 + threadIdx.x;
    if (i >= n8) return;
    const float* srcs[4] = {s0, s1, s2, s3};
    const float* src = srcs[blockIdx.y];
    size_t slot = (size_t)blockIdx.y * D_ * D_;
    const float4* s = (const float4*)(src + (size_t)i * 8);
    float4 v0 = s[0], v1 = s[1];
    float f[8] = {v0.x, v0.y, v0.z, v0.w, v1.x, v1.y, v1.z, v1.w};
    float hh[8], ll[8];
#pragma unroll
    for (int e = 0; e < 8; e++) { hh[e] = bhi(f[e]); ll[e] = f[e] - hh[e]; }
    *(uint4*)(g_w_hi + slot + (size_t)i * 8) =
        make_uint4(pk2(hh[0],hh[1]), pk2(hh[2],hh[3]),
                   pk2(hh[4],hh[5]), pk2(hh[6],hh[7]));
    *(uint4*)(g_w_lo + slot + (size_t)i * 8) =
        make_uint4(pk2(ll[0],ll[1]), pk2(ll[2],ll[3]),
                   pk2(ll[4],ll[5]), pk2(ll[6],ll[7]));
}

// ---------------------------------------------------------------------------
// wker2_prep: g_wker2[h][n][k] for k = t*64+c:
//   n < 64 : Wker[h, c, t, n]
//   n == 64: bker[h, c, t]
//   else 0
// idx over H*128*448/8 units of 8 consecutive k.
// ---------------------------------------------------------------------------
__global__ __launch_bounds__(256) void wker2_prep_kernel(
    const float* __restrict__ Wker, const float* __restrict__ bker)
{
    int idx = blockIdx.x * 256 + threadIdx.x;
    if (idx >= H_ * 128 * (NCAT/8)) return;
    int k8 = (idx % (NCAT/8)) * 8;
    int n  = (idx / (NCAT/8)) & 127;
    int h  = idx / (128 * (NCAT/8));
    int t  = k8 >> 6;
    int c0 = k8 & 63;
    float f[8];
#pragma unroll
    for (int e = 0; e < 8; e++) {
        int c = c0 + e;
        if (n < 64)       f[e] = Wker[(((size_t)(h*DK_ + c)) * KW_ + t) * DK_ + n];
        else if (n == 64) f[e] = bker[((size_t)(h*DK_ + c)) * KW_ + t];
        else              f[e] = 0.f;
    }
    float hh[8], ll[8];
#pragma unroll
    for (int e = 0; e < 8; e++) { hh[e] = bhi(f[e]); ll[e] = f[e] - hh[e]; }
    size_t off = ((size_t)(h * 128 + n)) * NCAT + k8;
    *(uint4*)(g_wker2_hi + off) = make_uint4(pk2(hh[0],hh[1]), pk2(hh[2],hh[3]),
                                             pk2(hh[4],hh[5]), pk2(hh[6],hh[7]));
    *(uint4*)(g_wker2_lo + off) = make_uint4(pk2(ll[0],ll[1]), pk2(ll[2],ll[3]),
                                             pk2(ll[4],ll[5]), pk2(ll[6],ll[7]));
}

#define GM_STAGE 32768
#define GM_SMEM3 (3*GM_STAGE)

// ---------------------------------------------------------------------------
// out-projection GEMM: 3-stage, single barrier per chunk.  2 CTAs/SM.
// ---------------------------------------------------------------------------
__global__ __launch_bounds__(256, 2) void gemm_mma_nt(
    const __nv_bfloat16* __restrict__ Ah, const __nv_bfloat16* __restrict__ Al,
    const __nv_bfloat16* __restrict__ Bh, const __nv_bfloat16* __restrict__ Bl,
    const float* __restrict__ bias, float* __restrict__ C, int K, int N)
{
    extern __shared__ char smem[];
    const uint32_t sbase = smem_u32(smem);
    const int kc = K >> 5;

    const int tid  = threadIdx.x;
    const int wid  = tid >> 5, lane = tid & 31;
    const int wm   = wid >> 2, wn = wid & 3;

    const int i0 = blockIdx.y * 128;
    const int j0 = blockIdx.x * 128;

    const __nv_bfloat16* ah = Ah + (size_t)i0 * K;
    const __nv_bfloat16* al = Al + (size_t)i0 * K;
    const __nv_bfloat16* bh_ = Bh + (size_t)j0 * K;
    const __nv_bfloat16* bl_ = Bl + (size_t)j0 * K;

    auto issue = [&](int s, int c) {
        const uint32_t sb = sbase + s * GM_STAGE;
#pragma unroll
        for (int q = 0; q < 4; q++) {
            int u  = q * 256 + tid;
            int r  = u >> 3, cj = u & 7;
            const __nv_bfloat16* src =
                (cj < 4 ? ah : al) + (size_t)r * K + c * 32 + (cj & 3) * 8;
            CP_ASYNC16(sb + r * 128 + 16 * (cj ^ (r & 7)), src);
        }
#pragma unroll
        for (int q = 0; q < 4; q++) {
            int u  = q * 256 + tid;
            int r  = u >> 3, cj = u & 7;
            const __nv_bfloat16* src =
                (cj < 4 ? bh_ : bl_) + (size_t)r * K + c * 32 + (cj & 3) * 8;
            CP_ASYNC16(sb + 16384 + r * 128 + 16 * (cj ^ (r & 7)), src);
        }
    };

    float acc[4][4][4];
#pragma unroll
    for (int i = 0; i < 4; i++)
#pragma unroll
        for (int j = 0; j < 4; j++)
#pragma unroll
            for (int e = 0; e < 4; e++) acc[i][j][e] = 0.f;

    issue(0, 0); CP_COMMIT();
    issue(1, 1); CP_COMMIT();

    const int lrow = (lane & 7) + 8 * ((lane >> 3) & 1);
    const int lchk = lane >> 4;

    int stage = 0;
    for (int c = 0; c < kc; c++) {
        if (c + 1 < kc) CP_WAIT(1); else CP_WAIT(0);
        __syncthreads();
        if (c + 2 < kc) {
            int s2 = stage + 2; if (s2 >= 3) s2 -= 3;
            issue(s2, c + 2); CP_COMMIT();
        }

        const uint32_t sA = sbase + stage * GM_STAGE;
        const uint32_t sB = sA + 16384;

#pragma unroll
        for (int ks = 0; ks < 2; ks++) {
            uint32_t bh[4][2], bl[4][2];
#pragma unroll
            for (int g = 0; g < 2; g++) {
                int r  = wn * 32 + g * 16 + lrow;
                int ch = ks * 2 + lchk;
                uint32_t r0, r1, r2, r3;
                LDSM4(r0, r1, r2, r3, sB + r * 128 + 16 * ((ch)     ^ (r & 7)));
                bh[2*g][0] = r0; bh[2*g][1] = r2;
                bh[2*g+1][0] = r1; bh[2*g+1][1] = r3;
                LDSM4(r0, r1, r2, r3, sB + r * 128 + 16 * ((ch + 4) ^ (r & 7)));
                bl[2*g][0] = r0; bl[2*g][1] = r2;
                bl[2*g+1][0] = r1; bl[2*g+1][1] = r3;
            }
#pragma unroll
            for (int mf = 0; mf < 4; mf++) {
                int r  = wm * 64 + mf * 16 + lrow;
                int ch = ks * 2 + lchk;
                uint32_t ah_[4], al_[4];
                LDSM4(ah_[0], ah_[1], ah_[2], ah_[3],
                      sA + r * 128 + 16 * ((ch)     ^ (r & 7)));
                LDSM4(al_[0], al_[1], al_[2], al_[3],
                      sA + r * 128 + 16 * ((ch + 4) ^ (r & 7)));
#pragma unroll
                for (int nf = 0; nf < 4; nf++) {
                    MMA16816(acc[mf][nf], ah_, bh[nf]);
                    MMA16816(acc[mf][nf], ah_, bl[nf]);
                    MMA16816(acc[mf][nf], al_, bh[nf]);
                }
            }
        }
        stage++; if (stage == 3) stage = 0;
    }

    const int rbase = i0 + wm * 64 + (lane >> 2);
    const int cbase = j0 + wn * 32 + 2 * (lane & 3);
#pragma unroll
    for (int mf = 0; mf < 4; mf++) {
        int gi = rbase + mf * 16;
        float* row0 = C + (size_t)gi * N;
        float* row1 = row0 + 8 * N;
#pragma unroll
        for (int nf = 0; nf < 4; nf++) {
            int gj = cbase + nf * 8;
            float b0 = bias[gj], b1 = bias[gj + 1];
            *(float2*)(row0 + gj) = make_float2(acc[mf][nf][0] + b0,
                                                acc[mf][nf][1] + b1);
            *(float2*)(row1 + gj) = make_float2(acc[mf][nf][2] + b0,
                                                acc[mf][nf][3] + b1);
        }
    }
}

// ---------------------------------------------------------------------------
// batched projection GEMM (bf16 hi/lo out).  3-stage, single barrier.
// ---------------------------------------------------------------------------
__global__ __launch_bounds__(256, 2) void gemm_mma_split3(
    const float* __restrict__ bq, const float* __restrict__ bk,
    const float* __restrict__ bv)
{
    extern __shared__ char smem[];
    const uint32_t sbase = smem_u32(smem);
    const int K = D_;

    const int tid  = threadIdx.x;
    const int wid  = tid >> 5, lane = tid & 31;
    const int wm   = wid >> 2, wn = wid & 3;

    const int i0 = blockIdx.y * 128;
    const int j0 = blockIdx.x * 128;
    const int sel = blockIdx.z;

    const __nv_bfloat16 *Ah, *Al;
    const float* bias;
    __nv_bfloat16 *Ch, *Cl;
    size_t wslot;
    if (sel == 0) { Ah = g_inq_hi; Al = g_inq_lo; bias = bq; Ch = g_qs_hi; Cl = g_qs_lo; wslot = 0; }
    else if (sel == 1) { Ah = g_ink_hi; Al = g_ink_lo; bias = bk; Ch = g_ks_hi; Cl = g_ks_lo; wslot = (size_t)D_*D_; }
    else { Ah = g_inv_hi; Al = g_inv_lo; bias = bv; Ch = g_vs_hi; Cl = g_vs_lo; wslot = (size_t)2*D_*D_; }

    const __nv_bfloat16* ah = Ah + (size_t)i0 * K;
    const __nv_bfloat16* al = Al + (size_t)i0 * K;
    const __nv_bfloat16* bh_ = g_w_hi + wslot + (size_t)j0 * K;
    const __nv_bfloat16* bl_ = g_w_lo + wslot + (size_t)j0 * K;

    auto issue = [&](int s, int c) {
        const uint32_t sb = sbase + s * GM_STAGE;
#pragma unroll
        for (int q = 0; q < 4; q++) {
            int u  = q * 256 + tid;
            int r  = u >> 3, cj = u & 7;
            const __nv_bfloat16* src =
                (cj < 4 ? ah : al) + (size_t)r * K + c * 32 + (cj & 3) * 8;
            CP_ASYNC16(sb + r * 128 + 16 * (cj ^ (r & 7)), src);
        }
#pragma unroll
        for (int q = 0; q < 4; q++) {
            int u  = q * 256 + tid;
            int r  = u >> 3, cj = u & 7;
            const __nv_bfloat16* src =
                (cj < 4 ? bh_ : bl_) + (size_t)r * K + c * 32 + (cj & 3) * 8;
            CP_ASYNC16(sb + 16384 + r * 128 + 16 * (cj ^ (r & 7)), src);
        }
    };

    float acc[4][4][4];
#pragma unroll
    for (int i = 0; i < 4; i++)
#pragma unroll
        for (int j = 0; j < 4; j++)
#pragma unroll
            for (int e = 0; e < 4; e++) acc[i][j][e] = 0.f;

    issue(0, 0); CP_COMMIT();
    issue(1, 1); CP_COMMIT();

    const int lrow = (lane & 7) + 8 * ((lane >> 3) & 1);
    const int lchk = lane >> 4;

    int stage = 0;
    for (int c = 0; c < 16; c++) {
        if (c + 1 < 16) CP_WAIT(1); else CP_WAIT(0);
        __syncthreads();
        if (c + 2 < 16) {
            int s2 = stage + 2; if (s2 >= 3) s2 -= 3;
            issue(s2, c + 2); CP_COMMIT();
        }

        const uint32_t sA = sbase + stage * GM_STAGE;
        const uint32_t sB = sA + 16384;

#pragma unroll
        for (int ks = 0; ks < 2; ks++) {
            uint32_t bh[4][2], bl[4][2];
#pragma unroll
            for (int g = 0; g < 2; g++) {
                int r  = wn * 32 + g * 16 + lrow;
                int ch = ks * 2 + lchk;
                uint32_t r0, r1, r2, r3;
                LDSM4(r0, r1, r2, r3, sB + r * 128 + 16 * ((ch)     ^ (r & 7)));
                bh[2*g][0] = r0; bh[2*g][1] = r2;
                bh[2*g+1][0] = r1; bh[2*g+1][1] = r3;
                LDSM4(r0, r1, r2, r3, sB + r * 128 + 16 * ((ch + 4) ^ (r & 7)));
                bl[2*g][0] = r0; bl[2*g][1] = r2;
                bl[2*g+1][0] = r1; bl[2*g+1][1] = r3;
            }
#pragma unroll
            for (int mf = 0; mf < 4; mf++) {
                int r  = wm * 64 + mf * 16 + lrow;
                int ch = ks * 2 + lchk;
                uint32_t ah_[4], al_[4];
                LDSM4(ah_[0], ah_[1], ah_[2], ah_[3],
                      sA + r * 128 + 16 * ((ch)     ^ (r & 7)));
                LDSM4(al_[0], al_[1], al_[2], al_[3],
                      sA + r * 128 + 16 * ((ch + 4) ^ (r & 7)));
#pragma unroll
                for (int nf = 0; nf < 4; nf++) {
                    MMA16816(acc[mf][nf], ah_, bh[nf]);
                    MMA16816(acc[mf][nf], ah_, bl[nf]);
                    MMA16816(acc[mf][nf], al_, bh[nf]);
                }
            }
        }
        stage++; if (stage == 3) stage = 0;
    }

    const int rbase = i0 + wm * 64 + (lane >> 2);
    const int cbase = j0 + wn * 32 + 2 * (lane & 3);
#pragma unroll
    for (int mf = 0; mf < 4; mf++) {
        int gi = rbase + mf * 16;
        size_t ro0 = (size_t)gi * D_, ro1 = ro0 + 8 * D_;
#pragma unroll
        for (int nf = 0; nf < 4; nf++) {
            int gj = cbase + nf * 8;
            float b0 = bias[gj], b1 = bias[gj + 1];
            float v0 = acc[mf][nf][0] + b0, v1 = acc[mf][nf][1] + b1;
            float v2 = acc[mf][nf][2] + b0, v3 = acc[mf][nf][3] + b1;
            float h0 = bhi(v0), h1 = bhi(v1), h2 = bhi(v2), h3 = bhi(v3);
            *(unsigned*)(Ch + ro0 + gj) = pk2(h0, h1);
            *(unsigned*)(Cl + ro0 + gj) = pk2(v0 - h0, v1 - h1);
            *(unsigned*)(Ch + ro1 + gj) = pk2(h2, h3);
            *(unsigned*)(Cl + ro1 + gj) = pk2(v2 - h2, v3 - h3);
        }
    }
}

// ---------------------------------------------------------------------------
// kconv: per (j-tile, z): out[128 j, 128 n] = Kcat_panel[128 j, 448] @
//   Wker2pad[128 n, 448]^T,  A (m=j) from the shifted k_s smem panel,
//   B (n) streamed from g_wker2.  cols<64 -> Kconv hi/lo; col 64 -> bterm.
// grid (8 [j/128], 64 z).  3-stage B stream + panel; single barrier.
// ---------------------------------------------------------------------------
#define KCV_BSTAGE   16384
#define KCV_PANEL    17152
#define KCV_PANEL_HI (3*KCV_BSTAGE)
#define KCV_PANEL_LO (KCV_PANEL_HI + KCV_PANEL)
#define KCV_SMEM     (KCV_PANEL_LO + KCV_PANEL)

__global__ __launch_bounds__(256, 2) void kconv_mma_kernel()
{
    extern __shared__ char smem[];
    const uint32_t sbase = smem_u32(smem);
    const uint32_t pHI = sbase + KCV_PANEL_HI;
    const uint32_t pLO = sbase + KCV_PANEL_LO;

    const int tid  = threadIdx.x;
    const int wid  = tid >> 5, lane = tid & 31;
    const int wm   = wid >> 2, wn = wid & 3;

    const int z  = blockIdx.y;
    const int b = z >> 3, h = z & 7;
    const int j0 = blockIdx.x * 128;

    const __nv_bfloat16* ksh = g_ks_hi + ((size_t)(b*L_)) * D_ + h*DK_;
    const __nv_bfloat16* ksl = g_ks_lo + ((size_t)(b*L_)) * D_ + h*DK_;
    const __nv_bfloat16* wk2h = g_wker2_hi + (size_t)h * 128 * NCAT;
    const __nv_bfloat16* wk2l = g_wker2_lo + (size_t)h * 128 * NCAT;

    auto issueB = [&](int s, int c) {
        const uint32_t sb = sbase + s * KCV_BSTAGE;
#pragma unroll
        for (int q = 0; q < 4; q++) {
            int u  = q * 256 + tid;
            int r  = u >> 3, cj = u & 7;
            const __nv_bfloat16* src =
                (cj < 4 ? wk2h : wk2l) + (size_t)r * NCAT + c * 32 + (cj & 3) * 8;
            CP_ASYNC16(sb + r * 128 + 16 * (cj ^ (r & 7)), src);
        }
    };

    // panel load: rows j0-3 .. j0+130
    for (int u = tid; u < 134 * 8; u += 256) {
        int r  = u >> 3, g8 = u & 7;
        int j  = j0 + r - PAD_;
        uint32_t dh = pHI + r * 128 + 16 * (g8 ^ (r & 7));
        uint32_t dl = pLO + r * 128 + 16 * (g8 ^ (r & 7));
        if (j >= 0 && j < L_) {
            CP_ASYNC16(dh, ksh + (size_t)j * D_ + g8 * 8);
            CP_ASYNC16(dl, ksl + (size_t)j * D_ + g8 * 8);
        } else {
            *(uint4*)(smem + (dh - sbase)) = make_uint4(0,0,0,0);
            *(uint4*)(smem + (dl - sbase)) = make_uint4(0,0,0,0);
        }
    }
    issueB(0, 0); CP_COMMIT();   // group: panel + B0
    issueB(1, 1); CP_COMMIT();   // group: B1

    float acc[4][4][4];
#pragma unroll
    for (int i = 0; i < 4; i++)
#pragma unroll
        for (int j = 0; j < 4; j++)
#pragma unroll
            for (int e = 0; e < 4; e++) acc[i][j][e] = 0.f;

    const int lrow = (lane & 7) + 8 * ((lane >> 3) & 1);
    const int lchk = lane >> 4;

    int stage = 0;
    for (int c = 0; c < 14; c++) {
        if (c + 1 < 14) CP_WAIT(1); else CP_WAIT(0);
        __syncthreads();
        if (c + 2 < 14) {
            int s2 = stage + 2; if (s2 >= 3) s2 -= 3;
            issueB(s2, c + 2); CP_COMMIT();
        }

        const uint32_t sB = sbase + stage * KCV_BSTAGE;
        const int t    = c >> 1;
        const int half = c & 1;

#pragma unroll
        for (int ks = 0; ks < 2; ks++) {
            // n-fragments from streamed Wker2 buffer
            uint32_t bh[4][2], bl[4][2];
#pragma unroll
            for (int g = 0; g < 2; g++) {
                int r  = wn * 32 + g * 16 + lrow;
                int ch = ks * 2 + lchk;
                uint32_t r0, r1, r2, r3;
                LDSM4(r0, r1, r2, r3, sB + r * 128 + 16 * ((ch)     ^ (r & 7)));
                bh[2*g][0] = r0; bh[2*g][1] = r2;
                bh[2*g+1][0] = r1; bh[2*g+1][1] = r3;
                LDSM4(r0, r1, r2, r3, sB + r * 128 + 16 * ((ch + 4) ^ (r & 7)));
                bl[2*g][0] = r0; bl[2*g][1] = r2;
                bl[2*g+1][0] = r1; bl[2*g+1][1] = r3;
            }
            // m-fragments from the shifted panel
#pragma unroll
            for (int mf = 0; mf < 4; mf++) {
                int rr = wm * 64 + mf * 16 + lrow + t;
                int g8 = half * 4 + ks * 2 + lchk;
                uint32_t ah[4], al[4];
                LDSM4(ah[0], ah[1], ah[2], ah[3],
                      pHI + rr * 128 + 16 * (g8 ^ (rr & 7)));
                LDSM4(al[0], al[1], al[2], al[3],
                      pLO + rr * 128 + 16 * (g8 ^ (rr & 7)));
#pragma unroll
                for (int nf = 0; nf < 4; nf++) {
                    MMA16816(acc[mf][nf], ah, bh[nf]);
                    MMA16816(acc[mf][nf], ah, bl[nf]);
                    MMA16816(acc[mf][nf], al, bh[nf]);
                }
            }
        }
        stage++; if (stage == 3) stage = 0;
    }

    // epilogue: cols<64 -> Kconv hi/lo (stride 64); col 64 -> bterm fp32
    __nv_bfloat16* Ch = g_kconv_hi + (size_t)z * L_ * DK_;
    __nv_bfloat16* Cl = g_kconv_lo + (size_t)z * L_ * DK_;
    float* bt = g_bterm + (size_t)z * L_;
    const int rbase = j0 + wm * 64 + (lane >> 2);
    const int cbase = wn * 32 + 2 * (lane & 3);
#pragma unroll
    for (int mf = 0; mf < 4; mf++) {
        int gi = rbase + mf * 16;
        size_t ro0 = (size_t)gi * DK_, ro1 = ro0 + 8 * DK_;
#pragma unroll
        for (int nf = 0; nf < 4; nf++) {
            int gj = cbase + nf * 8;
            float v0 = acc[mf][nf][0], v1 = acc[mf][nf][1];
            float v2 = acc[mf][nf][2], v3 = acc[mf][nf][3];
            if (gj < 64) {
                float h0 = bhi(v0), h1 = bhi(v1), h2 = bhi(v2), h3 = bhi(v3);
                *(unsigned*)(Ch + ro0 + gj) = pk2(h0, h1);
                *(unsigned*)(Cl + ro0 + gj) = pk2(v0 - h0, v1 - h1);
                *(unsigned*)(Ch + ro1 + gj) = pk2(h2, h3);
                *(unsigned*)(Cl + ro1 + gj) = pk2(v2 - h2, v3 - h3);
            } else if (gj == 64) {
                bt[gi]     = v0;
                bt[gi + 8] = v2;
            }
        }
    }
}

// ---------------------------------------------------------------------------
// Logits v4: per (j-tile, i-tile, z): S[i,j] = 0.125*(q_s[i,:64]·Kconv[j,:64]
//   + bterm[j]).  K=64 -> 2 chunks (qcat-style).  grid (8, 8, 64).
// ---------------------------------------------------------------------------
__global__ __launch_bounds__(256, 2) void logits_mma_kernel(float* __restrict__ attn)
{
    __shared__ char smem[2 * GM_STAGE];
    const uint32_t sbase = smem_u32(smem);

    const int tid  = threadIdx.x;
    const int wid  = tid >> 5, lane = tid & 31;
    const int wm   = wid >> 2, wn = wid & 3;

    const int z  = blockIdx.z;
    const int b = z >> 3, h = z & 7;
    const int i0 = blockIdx.y * 128;
    const int j0 = blockIdx.x * 128;

    const __nv_bfloat16* ah = g_qs_hi + ((size_t)(b*L_ + i0)) * D_ + h*DK_;
    const __nv_bfloat16* al = g_qs_lo + ((size_t)(b*L_ + i0)) * D_ + h*DK_;
    const __nv_bfloat16* bh_ = g_kconv_hi + (size_t)z * L_ * DK_ + (size_t)j0 * DK_;
    const __nv_bfloat16* bl_ = g_kconv_lo + (size_t)z * L_ * DK_ + (size_t)j0 * DK_;

    auto issue = [&](int s, int c) {
        const uint32_t sb = sbase + s * GM_STAGE;
#pragma unroll
        for (int q = 0; q < 4; q++) {
            int u  = q * 256 + tid;
            int r  = u >> 3, cj = u & 7;
            const __nv_bfloat16* src =
                (cj < 4 ? ah : al) + (size_t)r * D_ + c * 32 + (cj & 3) * 8;
            CP_ASYNC16(sb + r * 128 + 16 * (cj ^ (r & 7)), src);
        }
#pragma unroll
        for (int q = 0; q < 4; q++) {
            int u  = q * 256 + tid;
            int r  = u >> 3, cj = u & 7;
            const __nv_bfloat16* src =
                (cj < 4 ? bh_ : bl_) + (size_t)r * DK_ + c * 32 + (cj & 3) * 8;
            CP_ASYNC16(sb + 16384 + r * 128 + 16 * (cj ^ (r & 7)), src);
        }
    };

    float acc[4][4][4];
#pragma unroll
    for (int i = 0; i < 4; i++)
#pragma unroll
        for (int j = 0; j < 4; j++)
#pragma unroll
            for (int e = 0; e < 4; e++) acc[i][j][e] = 0.f;

    issue(0, 0);
    CP_COMMIT();

    const int lrow = (lane & 7) + 8 * ((lane >> 3) & 1);
    const int lchk = lane >> 4;

    for (int c = 0; c < 2; c++) {
        const int s = c & 1;
        if (c == 0) { issue(1, 1); CP_COMMIT(); CP_WAIT(1); }
        else        { CP_WAIT(0); }
        __syncthreads();

        const uint32_t sA = sbase + s * GM_STAGE;
        const uint32_t sB = sA + 16384;

#pragma unroll
        for (int ks = 0; ks < 2; ks++) {
            uint32_t bh[4][2], bl[4][2];
#pragma unroll
            for (int g = 0; g < 2; g++) {
                int r  = wn * 32 + g * 16 + lrow;
                int ch = ks * 2 + lchk;
                uint32_t r0, r1, r2, r3;
                LDSM4(r0, r1, r2, r3, sB + r * 128 + 16 * ((ch)     ^ (r & 7)));
                bh[2*g][0] = r0; bh[2*g][1] = r2;
                bh[2*g+1][0] = r1; bh[2*g+1][1] = r3;
                LDSM4(r0, r1, r2, r3, sB + r * 128 + 16 * ((ch + 4) ^ (r & 7)));
                bl[2*g][0] = r0; bl[2*g][1] = r2;
                bl[2*g+1][0] = r1; bl[2*g+1][1] = r3;
            }
#pragma unroll
            for (int mf = 0; mf < 4; mf++) {
                int r  = wm * 64 + mf * 16 + lrow;
                int ch = ks * 2 + lchk;
                uint32_t ah_[4], al_[4];
                LDSM4(ah_[0], ah_[1], ah_[2], ah_[3],
                      sA + r * 128 + 16 * ((ch)     ^ (r & 7)));
                LDSM4(al_[0], al_[1], al_[2], al_[3],
                      sA + r * 128 + 16 * ((ch + 4) ^ (r & 7)));
#pragma unroll
                for (int nf = 0; nf < 4; nf++) {
                    MMA16816(acc[mf][nf], ah_, bh[nf]);
                    MMA16816(acc[mf][nf], ah_, bl[nf]);
                    MMA16816(acc[mf][nf], al_, bh[nf]);
                }
            }
        }
        __syncthreads();
    }

    const float* bt = g_bterm + (size_t)z * L_;
    const int rbase = i0 + wm * 64 + (lane >> 2);
    const int cbase = j0 + wn * 32 + 2 * (lane & 3);
#pragma unroll
    for (int mf = 0; mf < 4; mf++) {
        int gi = rbase + mf * 16;
        float* row0 = attn + ((size_t)z * L_ + gi) * L_;
        float* row1 = row0 + 8 * L_;
#pragma unroll
        for (int nf = 0; nf < 4; nf++) {
            int gj = cbase + nf * 8;
            float bt0 = bt[gj], bt1 = bt[gj + 1];
            *(float2*)(row0 + gj) = make_float2((acc[mf][nf][0] + bt0) * 0.125f,
                                                (acc[mf][nf][1] + bt1) * 0.125f);
            *(float2*)(row1 + gj) = make_float2((acc[mf][nf][2] + bt0) * 0.125f,
                                                (acc[mf][nf][3] + bt1) * 0.125f);
        }
    }
}

// ---------------------------------------------------------------------------
// vt transpose (bf16)
// ---------------------------------------------------------------------------
__global__ __launch_bounds__(256) void vt_kernel()
{
    __shared__ uint32_t t[128][65];
    const int z = blockIdx.y;
    const int b = z >> 3, h = z & 7;
    const int k0 = blockIdx.x * 128;
    const int tid = threadIdx.x;

#pragma unroll
    for (int q = 0; q < 4; q++) {
        int u = q * 256 + tid;
        int r = u >> 3, c8 = (u & 7) * 8;
        size_t so = ((size_t)(b*L_ + k0 + r)) * D_ + h*DK_ + c8;
        uint4 vh = *(const uint4*)(g_vs_hi + so);
        uint4 vl = *(const uint4*)(g_vs_lo + so);
        uint32_t hw[4] = {vh.x, vh.y, vh.z, vh.w};
        uint32_t lw[4] = {vl.x, vl.y, vl.z, vl.w};
#pragma unroll
        for (int e = 0; e < 4; e++) {
            t[r][c8 + 2*e]     = (hw[e] & 0xffffu) | (lw[e] << 16);
            t[r][c8 + 2*e + 1] = (hw[e] >> 16)     | (lw[e] & 0xffff0000u);
        }
    }
    __syncthreads();

#pragma unroll
    for (int q = 0; q < 4; q++) {
        int u = q * 256 + tid;
        int n = u >> 4, k8 = (u & 15) * 8;
        uint32_t hi4[4], lo4[4];
#pragma unroll
        for (int e = 0; e < 4; e++) {
            uint32_t a = t[k8 + 2*e][n];
            uint32_t c = t[k8 + 2*e + 1][n];
            hi4[e] = (a & 0xffffu) | ((c & 0xffffu) << 16);
            lo4[e] = (a >> 16)     | (c & 0xffff0000u);
        }
        size_t off = (size_t)z * DK_ * L_ + (size_t)n * L_ + k0 + k8;
        *(uint4*)(g_vt_hi + off) = make_uint4(hi4[0], hi4[1], hi4[2], hi4[3]);
        *(uint4*)(g_vt_lo + off) = make_uint4(lo4[0], lo4[1], lo4[2], lo4[3]);
    }
}

// ---------------------------------------------------------------------------
// Row softmax in-place on attn; mask; head-0 duplicate.
// ---------------------------------------------------------------------------
__global__ __launch_bounds__(256) void softmax_kernel(
    float* __restrict__ attn, const unsigned char* __restrict__ mask,
    float* __restrict__ one_head)
{
    const int r = blockIdx.x;
    const int i = r & (L_-1);
    const int bh = r >> 10;
    const int h = bh & (H_-1), b = bh >> 3;
    float* row = attn + (size_t)r * L_;
    const unsigned char* mrow = mask + ((size_t)(b*L_ + i)) * L_;
    const int t4 = threadIdx.x * 4;

    float4 v = *(const float4*)(row + t4);
    uchar4 m = *(const uchar4*)(mrow + t4);
    float x0 = m.x ? -INFINITY : v.x;
    float x1 = m.y ? -INFINITY : v.y;
    float x2 = m.z ? -INFINITY : v.z;
    float x3 = m.w ? -INFINITY : v.w;

    __shared__ float sm[8], ss[8];
    float mx = fmaxf(fmaxf(x0, x1), fmaxf(x2, x3));
#pragma unroll
    for (int o = 16; o; o >>= 1) mx = fmaxf(mx, __shfl_xor_sync(0xffffffffu, mx, o));
    if ((threadIdx.x & 31) == 0) sm[threadIdx.x >> 5] = mx;
    __syncthreads();
    if (threadIdx.x < 32) {
        float t = (threadIdx.x < 8) ? sm[threadIdx.x] : -INFINITY;
#pragma unroll
        for (int o = 4; o; o >>= 1) t = fmaxf(t, __shfl_xor_sync(0xffffffffu, t, o));
        if (threadIdx.x == 0) sm[0] = t;
    }
    __syncthreads();
    mx = sm[0];

    float e0 = __expf(x0 - mx), e1 = __expf(x1 - mx);
    float e2 = __expf(x2 - mx), e3 = __expf(x3 - mx);
    float s = (e0 + e1) + (e2 + e3);
#pragma unroll
    for (int o = 16; o; o >>= 1) s += __shfl_xor_sync(0xffffffffu, s, o);
    if ((threadIdx.x & 31) == 0) ss[threadIdx.x >> 5] = s;
    __syncthreads();
    if (threadIdx.x < 32) {
        float t = (threadIdx.x < 8) ? ss[threadIdx.x] : 0.f;
#pragma unroll
        for (int o = 4; o; o >>= 1) t += __shfl_xor_sync(0xffffffffu, t, o);
        if (threadIdx.x == 0) ss[0] = t;
    }
    __syncthreads();
    float inv = 1.0f / ss[0];

    float4 o = make_float4(e0*inv, e1*inv, e2*inv, e3*inv);
    *(float4*)(row + t4) = o;
    if (h == 0)
        *(float4*)(one_head + ((size_t)(b*L_ + i)) * L_ + t4) = o;
}

// ---------------------------------------------------------------------------
// ctx via mma (unchanged)
// ---------------------------------------------------------------------------
#define CTX_STAGE 24576

__global__ __launch_bounds__(256, 2) void ctx_mma_kernel(const float* __restrict__ attn)
{
    __shared__ char smem[2 * CTX_STAGE];
    const uint32_t sbase = smem_u32(smem);

    const int tid  = threadIdx.x;
    const int wid  = tid >> 5, lane = tid & 31;
    const int wm   = wid >> 2, wn = wid & 3;

    const int z  = blockIdx.y;
    const int b = z >> 3, h = z & 7;
    const int i0 = blockIdx.x * 128;

    const float* A = attn + ((size_t)z * L_ + i0) * L_;
    const __nv_bfloat16* vh = g_vt_hi + (size_t)z * DK_ * L_;
    const __nv_bfloat16* vl = g_vt_lo + (size_t)z * DK_ * L_;

    auto issueB = [&](int s, int c) {
        const uint32_t sb = sbase + s * CTX_STAGE + 16384;
#pragma unroll
        for (int q = 0; q < 2; q++) {
            int u  = q * 256 + tid;
            int r  = u >> 3, cj = u & 7;
            const __nv_bfloat16* src =
                (cj < 4 ? vh : vl) + (size_t)r * L_ + c * 32 + (cj & 3) * 8;
            CP_ASYNC16(sb + r * 128 + 16 * (cj ^ (r & 7)), src);
        }
    };
    float fa[2][8];
    auto ldgA = [&](int c) {
#pragma unroll
        for (int q = 0; q < 2; q++) {
            int u = q * 256 + tid;
            int r = u >> 2, seg = u & 3;
            const float4* p = (const float4*)(A + (size_t)r * L_ + c * 32 + seg * 8);
            float4 v0 = p[0], v1 = p[1];
            fa[q][0]=v0.x; fa[q][1]=v0.y; fa[q][2]=v0.z; fa[q][3]=v0.w;
            fa[q][4]=v1.x; fa[q][5]=v1.y; fa[q][6]=v1.z; fa[q][7]=v1.w;
        }
    };
    auto stsA = [&](int s) {
#pragma unroll
        for (int q = 0; q < 2; q++) {
            int u = q * 256 + tid;
            int r = u >> 2, seg = u & 3;
            float hh[8], ll[8];
#pragma unroll
            for (int e = 0; e < 8; e++) { hh[e] = bhi(fa[q][e]); ll[e] = fa[q][e] - hh[e]; }
            *(uint4*)(smem + s * CTX_STAGE + r * 128 + 16 * ((seg)     ^ (r & 7))) =
                make_uint4(pk2(hh[0],hh[1]), pk2(hh[2],hh[3]),
                           pk2(hh[4],hh[5]), pk2(hh[6],hh[7]));
            *(uint4*)(smem + s * CTX_STAGE + r * 128 + 16 * ((seg + 4) ^ (r & 7))) =
                make_uint4(pk2(ll[0],ll[1]), pk2(ll[2],ll[3]),
                           pk2(ll[4],ll[5]), pk2(ll[6],ll[7]));
        }
    };

    float acc[4][2][4];
#pragma unroll
    for (int i = 0; i < 4; i++)
#pragma unroll
        for (int j = 0; j < 2; j++)
#pragma unroll
            for (int e = 0; e < 4; e++) acc[i][j][e] = 0.f;

    ldgA(0);
    issueB(0, 0); CP_COMMIT();

    const int lrow = (lane & 7) + 8 * ((lane >> 3) & 1);
    const int lchk = lane >> 4;

    for (int c = 0; c < 32; c++) {
        const int s = c & 1;
        stsA(s);
        if (c + 1 < 32) {
            ldgA(c + 1);
            issueB(s ^ 1, c + 1); CP_COMMIT(); CP_WAIT(1);
        } else {
            CP_WAIT(0);
        }
        __syncthreads();

        const uint32_t sA = sbase + s * CTX_STAGE;
        const uint32_t sB = sA + 16384;

#pragma unroll
        for (int ks = 0; ks < 2; ks++) {
            uint32_t bh[2][2], bl[2][2];
            {
                int r  = wn * 16 + lrow;
                int ch = ks * 2 + lchk;
                uint32_t r0, r1, r2, r3;
                LDSM4(r0, r1, r2, r3, sB + r * 128 + 16 * ((ch)     ^ (r & 7)));
                bh[0][0] = r0; bh[0][1] = r2; bh[1][0] = r1; bh[1][1] = r3;
                LDSM4(r0, r1, r2, r3, sB + r * 128 + 16 * ((ch + 4) ^ (r & 7)));
                bl[0][0] = r0; bl[0][1] = r2; bl[1][0] = r1; bl[1][1] = r3;
            }
#pragma unroll
            for (int mf = 0; mf < 4; mf++) {
                int r  = wm * 64 + mf * 16 + lrow;
                int ch = ks * 2 + lchk;
                uint32_t ah[4], al[4];
                LDSM4(ah[0], ah[1], ah[2], ah[3],
                      sA + r * 128 + 16 * ((ch)     ^ (r & 7)));
                LDSM4(al[0], al[1], al[2], al[3],
                      sA + r * 128 + 16 * ((ch + 4) ^ (r & 7)));
#pragma unroll
                for (int nf = 0; nf < 2; nf++) {
                    MMA16816(acc[mf][nf], ah, bh[nf]);
                    MMA16816(acc[mf][nf], ah, bl[nf]);
                    MMA16816(acc[mf][nf], al, bh[nf]);
                }
            }
        }
        __syncthreads();
    }

    const int rbase = i0 + wm * 64 + (lane >> 2);
    const int cb = h * DK_ + wn * 16 + 2 * (lane & 3);
#pragma unroll
    for (int mf = 0; mf < 4; mf++) {
        int gi = rbase + mf * 16;
        size_t ro0 = ((size_t)(b * L_) + gi) * D_;
        size_t ro1 = ro0 + 8 * D_;
#pragma unroll
        for (int nf = 0; nf < 2; nf++) {
            int gj = cb + nf * 8;
            float v0 = acc[mf][nf][0], v1 = acc[mf][nf][1];
            float v2 = acc[mf][nf][2], v3 = acc[mf][nf][3];
            float h0 = bhi(v0), h1 = bhi(v1), h2 = bhi(v2), h3 = bhi(v3);
            *(unsigned*)(g_ctx_hi + ro0 + gj) = pk2(h0, h1);
            *(unsigned*)(g_ctx_lo + ro0 + gj) = pk2(v0 - h0, v1 - h1);
            *(unsigned*)(g_ctx_hi + ro1 + gj) = pk2(h2, h3);
            *(unsigned*)(g_ctx_lo + ro1 + gj) = pk2(v2 - h2, v3 - h3);
        }
    }
}

// ---------------------------------------------------------------------------
extern "C" void kernel_launch(void* const* d_in, const int* in_sizes, int n_in,
                              void* d_out, int out_size)
{
    const float* q      = (const float*)d_in[0];
    const float* k      = (const float*)d_in[1];
    const float* v      = (const float*)d_in[2];
    const unsigned char* mask = (const unsigned char*)d_in[3];
    const float* Wq     = (const float*)d_in[4];
    const float* bq     = (const float*)d_in[5];
    const float* Wk     = (const float*)d_in[6];
    const float* bk     = (const float*)d_in[7];
    const float* Wv     = (const float*)d_in[8];
    const float* bv     = (const float*)d_in[9];
    const float* Wker   = (const float*)d_in[10];
    const float* bker   = (const float*)d_in[11];
    const float* Wproj  = (const float*)d_in[15];
    const float* bproj  = (const float*)d_in[16];

    float* out      = (float*)d_out;
    float* attn     = out + (size_t)B_ * L_ * D_;
    float* one_head = attn + (size_t)B_ * H_ * L_ * L_;

    void* p;
    __nv_bfloat16 *wh, *wl, *ch, *cl;
    cudaGetSymbolAddress(&p, g_w_hi);   wh  = (__nv_bfloat16*)p;
    cudaGetSymbolAddress(&p, g_w_lo);   wl  = (__nv_bfloat16*)p;
    cudaGetSymbolAddress(&p, g_ctx_hi); ch  = (__nv_bfloat16*)p;
    cudaGetSymbolAddress(&p, g_ctx_lo); cl  = (__nv_bfloat16*)p;

    static bool attr_done = false;
    if (!attr_done) {
        cudaFuncSetAttribute(kconv_mma_kernel,
            cudaFuncAttributeMaxDynamicSharedMemorySize, KCV_SMEM);
        cudaFuncSetAttribute(gemm_mma_nt,
            cudaFuncAttributeMaxDynamicSharedMemorySize, GM_SMEM3);
        cudaFuncSetAttribute(gemm_mma_split3,
            cudaFuncAttributeMaxDynamicSharedMemorySize, GM_SMEM3);
        attr_done = true;
    }

    const int M = B_ * L_;        // 8192
    const int NE = M * D_;
    const int NW = D_ * D_;
    dim3 blk(256);

    // 0) splits + weight prep
    conv_split3_kernel<<<dim3((NE/8 + 255)/256, 3), 256>>>(q, k, v, NE/8);
    conv_split4_kernel<<<dim3((NW/8 + 255)/256, 4), 256>>>(Wq, Wk, Wv, Wproj, NW/8);
    wker2_prep_kernel<<<(H_*128*(NCAT/8) + 255)/256, 256>>>(Wker, bker);

    // 1) q/k/v projections in one batched launch
    gemm_mma_split3<<<dim3(D_/128, M/128, 3), blk, GM_SMEM3>>>(bq, bk, bv);

    // 2) Kconv (+bterm) from k_s panel; v transpose
    kconv_mma_kernel<<<dim3(L_/128, B_*H_), blk, KCV_SMEM>>>();
    vt_kernel<<<dim3(L_/128, B_*H_), blk>>>();

    // 3) logits v4: q_s @ Kconv^T (+bterm), scaled -> attn region
    logits_mma_kernel<<<dim3(L_/128, L_/128, B_*H_), blk>>>(attn);

    // 4) softmax in place (+ one_head copy)
    softmax_kernel<<<B_*H_*L_, 256>>>(attn, mask, one_head);

    // 5) ctx = attn @ v_s -> g_ctx hi/lo
    ctx_mma_kernel<<<dim3(L_/128, B_*H_), blk>>>(attn);

    // 6) out = ctx @ Wproj^T + bproj
    gemm_mma_nt<<<dim3(D_/128, M/128), blk, GM_SMEM3>>>(ch, cl, wh + 3*NW, wl + 3*NW, bproj, out, D_, D_);
}